// round 3
// baseline (speedup 1.0000x reference)
#include <cuda_runtime.h>

#define Bsz 8
#define Lsz 1024
#define Dsz 512
#define HDsz 64
#define NCsz 128
#define Msz (Bsz*Lsz)
#define OUTHALF ((size_t)Msz*Dsz)
#define NEG_INF (-__int_as_float(0x7f800000))

__device__ float g_zr[Msz*Dsz];
__device__ float g_qr[Msz*Dsz], g_qi[Msz*Dsz];
__device__ float g_kr[Msz*Dsz], g_ki[Msz*Dsz];
__device__ float g_vr[Msz*Dsz], g_vi[Msz*Dsz];
__device__ float g_ar[Msz*Dsz], g_ai[Msz*Dsz];
__device__ float g_pr[Msz*Dsz], g_pi[Msz*Dsz];
__device__ int   g_idx[Msz];
__device__ float g_stk[Msz*Dsz];
__device__ float g_cn2[NCsz], g_gp[NCsz], g_go[NCsz];
__device__ double g_loss;

// ---------- prep ----------
__global__ void prep_kernel(const float* __restrict__ cb,
                            const float* __restrict__ gw,
                            const float* __restrict__ gb) {
    int j = threadIdx.x;
    if (j == 0) g_loss = 0.0;
    if (j < NCsz) {
        float s2 = 0.f, d0 = 0.f, d1 = 0.f;
        for (int d = 0; d < Dsz; d++) {
            float c = cb[j*Dsz + d];
            s2 += c*c; d0 += c*gw[d*2+0]; d1 += c*gw[d*2+1];
        }
        g_cn2[j] = s2;
        g_gp[j] = 1.f/(1.f+expf(-(d0+gb[0])));
        g_go[j] = 1.f/(1.f+expf(-(d1+gb[1])));
    }
}

// ---------- embedding gather ----------
__global__ void gather_kernel(const int* __restrict__ tokens,
                              const float* __restrict__ embed) {
    int m = blockIdx.x;
    const float4* src = (const float4*)(embed + (size_t)tokens[m]*Dsz);
    ((float4*)(g_zr + (size_t)m*Dsz))[threadIdx.x] = src[threadIdx.x];
}

// ---------- 6-way projection GEMM (K-step 16, prefetch) ----------
__global__ __launch_bounds__(256) void proj_kernel(
        const float* __restrict__ qw, const float* __restrict__ qb,
        const float* __restrict__ kw, const float* __restrict__ kb,
        const float* __restrict__ vw, const float* __restrict__ vb) {
    __shared__ float As[16][128], Bs[16][128];
    const int z = blockIdx.z, pair = z>>1, im = z&1;
    const float* W; const float* bias; float* C;
    if (pair==0){W=qw;bias=qb;C=im?g_qi:g_qr;}
    else if (pair==1){W=kw;bias=kb;C=im?g_ki:g_kr;}
    else {W=vw;bias=vb;C=im?g_vi:g_vr;}
    W += (size_t)im*Dsz*Dsz;
    const float sgn = im?1.f:-1.f;
    const int m0=blockIdx.y*128, n0=blockIdx.x*128;
    const int tid=threadIdx.x, ty=tid>>4, tx=tid&15;
    const int arow=tid>>1, ak=(tid&1)*8;
    const int brow=tid>>4, bcol=(tid&15)*8;
    float acc[8][8];
#pragma unroll
    for(int i=0;i<8;i++)
#pragma unroll
        for(int j=0;j<8;j++) acc[i][j]=0.f;
    float4 aa0=*(const float4*)(g_zr+(size_t)(m0+arow)*Dsz+ak);
    float4 aa1=*(const float4*)(g_zr+(size_t)(m0+arow)*Dsz+ak+4);
    float4 bb0=*(const float4*)(W+(size_t)brow*Dsz+n0+bcol);
    float4 bb1=*(const float4*)(W+(size_t)brow*Dsz+n0+bcol+4);
    for(int k0=0;k0<Dsz;k0+=16){
        __syncthreads();
        As[ak+0][arow]=aa0.x;As[ak+1][arow]=aa0.y;As[ak+2][arow]=aa0.z;As[ak+3][arow]=aa0.w;
        As[ak+4][arow]=aa1.x;As[ak+5][arow]=aa1.y;As[ak+6][arow]=aa1.z;As[ak+7][arow]=aa1.w;
        *(float4*)&Bs[brow][bcol]=bb0; *(float4*)&Bs[brow][bcol+4]=bb1;
        __syncthreads();
        if(k0+16<Dsz){
            aa0=*(const float4*)(g_zr+(size_t)(m0+arow)*Dsz+k0+16+ak);
            aa1=*(const float4*)(g_zr+(size_t)(m0+arow)*Dsz+k0+16+ak+4);
            bb0=*(const float4*)(W+(size_t)(k0+16+brow)*Dsz+n0+bcol);
            bb1=*(const float4*)(W+(size_t)(k0+16+brow)*Dsz+n0+bcol+4);
        }
#pragma unroll
        for(int kk=0;kk<16;kk++){
            float4 a0=*(float4*)&As[kk][ty*8],a1=*(float4*)&As[kk][ty*8+4];
            float4 b0=*(float4*)&Bs[kk][tx*8],b1=*(float4*)&Bs[kk][tx*8+4];
            float a[8]={a0.x,a0.y,a0.z,a0.w,a1.x,a1.y,a1.z,a1.w};
            float b[8]={b0.x,b0.y,b0.z,b0.w,b1.x,b1.y,b1.z,b1.w};
#pragma unroll
            for(int i=0;i<8;i++)
#pragma unroll
                for(int j=0;j<8;j++) acc[i][j]+=a[i]*b[j];
        }
    }
    float bv_[8];
#pragma unroll
    for(int j=0;j<8;j++){int n=n0+tx*8+j; bv_[j]=bias[n]+sgn*bias[Dsz+n];}
#pragma unroll
    for(int i=0;i<8;i++){
        float* cr=C+(size_t)(m0+ty*8+i)*Dsz+n0+tx*8;
        *(float4*)(cr)  =make_float4(acc[i][0]+bv_[0],acc[i][1]+bv_[1],acc[i][2]+bv_[2],acc[i][3]+bv_[3]);
        *(float4*)(cr+4)=make_float4(acc[i][4]+bv_[4],acc[i][5]+bv_[5],acc[i][6]+bv_[6],acc[i][7]+bv_[7]);
    }
}

// ---------- flash attention v2: 512 threads, 2x4 micro-tile ----------
#define AP 68
__global__ __launch_bounds__(512) void attn_kernel() {
    extern __shared__ float sm[];
    float* sQr=sm;            float* sQi=sQr+64*AP;
    float* sKr=sQi+64*AP;     float* sKi=sKr+64*AP;
    float* sVr=sKi+64*AP;     float* sVi=sVr+64*AP;
    float* sP =sVi+64*AP;
    const int bh=blockIdx.y, b=bh>>3, h=bh&7;
    const int i0=blockIdx.x*64;
    const int tid=threadIdx.x, ty=tid>>4, tx=tid&15;
    const size_t base=(size_t)b*Lsz*Dsz + h*HDsz;
#pragma unroll
    for(int u=0;u<2;u++){
        int li=tid+u*512, r=li>>4, c4=(li&15)*4;
        size_t g=base+(size_t)(i0+r)*Dsz+c4;
        *(float4*)&sQr[r*AP+c4]=*(const float4*)(g_qr+g);
        *(float4*)&sQi[r*AP+c4]=*(const float4*)(g_qi+g);
    }
    float m_run[2],l_run[2],accr[2][4],acci[2][4];
#pragma unroll
    for(int i=0;i<2;i++){m_run[i]=NEG_INF;l_run[i]=0.f;
#pragma unroll
        for(int j=0;j<4;j++){accr[i][j]=0.f;acci[i][j]=0.f;}}
    for(int jt=0;jt<=blockIdx.x;jt++){
        const int s0=jt*64;
        __syncthreads();
#pragma unroll
        for(int u=0;u<2;u++){
            int li=tid+u*512, r=li>>4, c4=(li&15)*4;
            size_t g=base+(size_t)(s0+r)*Dsz+c4;
            float4 a=*(const float4*)(g_kr+g);
            float4 c=*(const float4*)(g_ki+g);
            sKr[(c4+0)*AP+r]=a.x;sKr[(c4+1)*AP+r]=a.y;sKr[(c4+2)*AP+r]=a.z;sKr[(c4+3)*AP+r]=a.w;
            sKi[(c4+0)*AP+r]=c.x;sKi[(c4+1)*AP+r]=c.y;sKi[(c4+2)*AP+r]=c.z;sKi[(c4+3)*AP+r]=c.w;
            *(float4*)&sVr[r*AP+c4]=*(const float4*)(g_vr+g);
            *(float4*)&sVi[r*AP+c4]=*(const float4*)(g_vi+g);
        }
        __syncthreads();
        float s_[2][4];
#pragma unroll
        for(int i=0;i<2;i++)
#pragma unroll
            for(int j=0;j<4;j++) s_[i][j]=0.f;
#pragma unroll
        for(int k4=0;k4<16;k4++){
            float qrv[2][4],qiv[2][4];
#pragma unroll
            for(int i=0;i<2;i++){
                float4 t=*(float4*)&sQr[(2*ty+i)*AP+4*k4];
                qrv[i][0]=t.x;qrv[i][1]=t.y;qrv[i][2]=t.z;qrv[i][3]=t.w;
                float4 u=*(float4*)&sQi[(2*ty+i)*AP+4*k4];
                qiv[i][0]=u.x;qiv[i][1]=u.y;qiv[i][2]=u.z;qiv[i][3]=u.w;
            }
#pragma unroll
            for(int kk=0;kk<4;kk++){
                float4 kr4=*(float4*)&sKr[(4*k4+kk)*AP+4*tx];
                float4 ki4=*(float4*)&sKi[(4*k4+kk)*AP+4*tx];
#pragma unroll
                for(int i=0;i<2;i++){
                    s_[i][0]+=qrv[i][kk]*kr4.x+qiv[i][kk]*ki4.x;
                    s_[i][1]+=qrv[i][kk]*kr4.y+qiv[i][kk]*ki4.y;
                    s_[i][2]+=qrv[i][kk]*kr4.z+qiv[i][kk]*ki4.z;
                    s_[i][3]+=qrv[i][kk]*kr4.w+qiv[i][kk]*ki4.w;
                }
            }
        }
        const bool diag=(jt==blockIdx.x);
#pragma unroll
        for(int i=0;i<2;i++)
#pragma unroll
            for(int j=0;j<4;j++){
                s_[i][j]*=0.125f;
                if(diag && (4*tx+j>2*ty+i)) s_[i][j]=NEG_INF;
            }
        float p_[2][4];
#pragma unroll
        for(int i=0;i<2;i++){
            float mx=fmaxf(fmaxf(s_[i][0],s_[i][1]),fmaxf(s_[i][2],s_[i][3]));
#pragma unroll
            for(int off=8;off;off>>=1) mx=fmaxf(mx,__shfl_xor_sync(0xffffffffu,mx,off));
            float mnew=fmaxf(m_run[i],mx);
            float alpha=__expf(m_run[i]-mnew);
            m_run[i]=mnew;
            float rs=0.f;
#pragma unroll
            for(int j=0;j<4;j++){p_[i][j]=__expf(s_[i][j]-mnew);rs+=p_[i][j];}
#pragma unroll
            for(int off=8;off;off>>=1) rs+=__shfl_xor_sync(0xffffffffu,rs,off);
            l_run[i]=l_run[i]*alpha+rs;
#pragma unroll
            for(int j=0;j<4;j++){accr[i][j]*=alpha;acci[i][j]*=alpha;}
        }
#pragma unroll
        for(int i=0;i<2;i++)
            *(float4*)&sP[(2*ty+i)*AP+4*tx]=make_float4(p_[i][0],p_[i][1],p_[i][2],p_[i][3]);
        __syncthreads();
#pragma unroll
        for(int c4=0;c4<16;c4++){
            float pp[2][4];
#pragma unroll
            for(int i=0;i<2;i++){
                float4 t=*(float4*)&sP[(2*ty+i)*AP+4*c4];
                pp[i][0]=t.x;pp[i][1]=t.y;pp[i][2]=t.z;pp[i][3]=t.w;
            }
#pragma unroll
            for(int cc=0;cc<4;cc++){
                float4 vr4=*(float4*)&sVr[(4*c4+cc)*AP+4*tx];
                float4 vi4=*(float4*)&sVi[(4*c4+cc)*AP+4*tx];
#pragma unroll
                for(int i=0;i<2;i++){
                    accr[i][0]+=pp[i][cc]*vr4.x;accr[i][1]+=pp[i][cc]*vr4.y;
                    accr[i][2]+=pp[i][cc]*vr4.z;accr[i][3]+=pp[i][cc]*vr4.w;
                    acci[i][0]+=pp[i][cc]*vi4.x;acci[i][1]+=pp[i][cc]*vi4.y;
                    acci[i][2]+=pp[i][cc]*vi4.z;acci[i][3]+=pp[i][cc]*vi4.w;
                }
            }
        }
    }
#pragma unroll
    for(int i=0;i<2;i++){
        float inv=1.f/l_run[i];
        size_t g=base+(size_t)(i0+2*ty+i)*Dsz+4*tx;
        *(float4*)(g_ar+g)=make_float4(accr[i][0]*inv,accr[i][1]*inv,accr[i][2]*inv,accr[i][3]*inv);
        *(float4*)(g_ai+g)=make_float4(acci[i][0]*inv,acci[i][1]*inv,acci[i][2]*inv,acci[i][3]*inv);
    }
}

// ---------- complex O-projection (K-step 16, prefetch) ----------
__global__ __launch_bounds__(256) void oproj_kernel(const float* __restrict__ ow,
                                                    const float* __restrict__ ob) {
    __shared__ float Ars[16][128],Ais[16][128],B0s[16][64],B1s[16][64];
    const int m0=blockIdx.y*128, n0=blockIdx.x*64;
    const int tid=threadIdx.x, ty=tid>>4, tx=tid&15;
    const int arow=tid>>1, ak=(tid&1)*8;
    const int bkr=(tid&127)>>3, bn=((tid&127)&7)*8;
    const bool isB1=tid>=128;
    const float* w0=ow; const float* w1=ow+(size_t)Dsz*Dsz;
    const float* ws=isB1?w1:w0;
    float accR[8][4],accI[8][4];
#pragma unroll
    for(int i=0;i<8;i++)
#pragma unroll
        for(int j=0;j<4;j++){accR[i][j]=0.f;accI[i][j]=0.f;}
    float4 ar0=*(const float4*)(g_ar+(size_t)(m0+arow)*Dsz+ak);
    float4 ar1=*(const float4*)(g_ar+(size_t)(m0+arow)*Dsz+ak+4);
    float4 ai0=*(const float4*)(g_ai+(size_t)(m0+arow)*Dsz+ak);
    float4 ai1=*(const float4*)(g_ai+(size_t)(m0+arow)*Dsz+ak+4);
    float4 bb0=*(const float4*)(ws+(size_t)bkr*Dsz+n0+bn);
    float4 bb1=*(const float4*)(ws+(size_t)bkr*Dsz+n0+bn+4);
    for(int k0=0;k0<Dsz;k0+=16){
        __syncthreads();
        Ars[ak+0][arow]=ar0.x;Ars[ak+1][arow]=ar0.y;Ars[ak+2][arow]=ar0.z;Ars[ak+3][arow]=ar0.w;
        Ars[ak+4][arow]=ar1.x;Ars[ak+5][arow]=ar1.y;Ars[ak+6][arow]=ar1.z;Ars[ak+7][arow]=ar1.w;
        Ais[ak+0][arow]=ai0.x;Ais[ak+1][arow]=ai0.y;Ais[ak+2][arow]=ai0.z;Ais[ak+3][arow]=ai0.w;
        Ais[ak+4][arow]=ai1.x;Ais[ak+5][arow]=ai1.y;Ais[ak+6][arow]=ai1.z;Ais[ak+7][arow]=ai1.w;
        if(isB1){*(float4*)&B1s[bkr][bn]=bb0;*(float4*)&B1s[bkr][bn+4]=bb1;}
        else    {*(float4*)&B0s[bkr][bn]=bb0;*(float4*)&B0s[bkr][bn+4]=bb1;}
        __syncthreads();
        if(k0+16<Dsz){
            ar0=*(const float4*)(g_ar+(size_t)(m0+arow)*Dsz+k0+16+ak);
            ar1=*(const float4*)(g_ar+(size_t)(m0+arow)*Dsz+k0+16+ak+4);
            ai0=*(const float4*)(g_ai+(size_t)(m0+arow)*Dsz+k0+16+ak);
            ai1=*(const float4*)(g_ai+(size_t)(m0+arow)*Dsz+k0+16+ak+4);
            bb0=*(const float4*)(ws+(size_t)(k0+16+bkr)*Dsz+n0+bn);
            bb1=*(const float4*)(ws+(size_t)(k0+16+bkr)*Dsz+n0+bn+4);
        }
#pragma unroll
        for(int kk=0;kk<16;kk++){
            float4 a0=*(float4*)&Ars[kk][ty*8],a1=*(float4*)&Ars[kk][ty*8+4];
            float4 c0=*(float4*)&Ais[kk][ty*8],c1=*(float4*)&Ais[kk][ty*8+4];
            float4 b0=*(float4*)&B0s[kk][tx*4],b1=*(float4*)&B1s[kk][tx*4];
            float ar8[8]={a0.x,a0.y,a0.z,a0.w,a1.x,a1.y,a1.z,a1.w};
            float ai8[8]={c0.x,c0.y,c0.z,c0.w,c1.x,c1.y,c1.z,c1.w};
            float bw0[4]={b0.x,b0.y,b0.z,b0.w};
            float bw1[4]={b1.x,b1.y,b1.z,b1.w};
#pragma unroll
            for(int i=0;i<8;i++)
#pragma unroll
                for(int j=0;j<4;j++){
                    accR[i][j]+=ar8[i]*bw0[j]-ai8[i]*bw1[j];
                    accI[i][j]+=ai8[i]*bw0[j]+ar8[i]*bw1[j];
                }
        }
    }
    float bR[4],bI[4];
#pragma unroll
    for(int j=0;j<4;j++){int n=n0+tx*4+j;bR[j]=ob[n]-ob[Dsz+n];bI[j]=ob[n]+ob[Dsz+n];}
#pragma unroll
    for(int i=0;i<8;i++){
        size_t g=(size_t)(m0+ty*8+i)*Dsz+n0+tx*4;
        *(float4*)(g_pr+g)=make_float4(accR[i][0]+bR[0],accR[i][1]+bR[1],accR[i][2]+bR[2],accR[i][3]+bR[3]);
        *(float4*)(g_pi+g)=make_float4(accI[i][0]+bI[0],accI[i][1]+bI[1],accI[i][2]+bI[2],accI[i][3]+bI[3]);
    }
}

// ---------- VQ distance GEMM + first-argmin (K-step 16, prefetch) ----------
__global__ __launch_bounds__(256) void dist_kernel(const float* __restrict__ cb) {
    __shared__ float As[16][128], Bs[16][128];
    __shared__ float2 sRed[128][16];
    const int m0=blockIdx.x*128;
    const int tid=threadIdx.x, ty=tid>>4, tx=tid&15;
    const int arow=tid>>1, ak=(tid&1)*8;
    float acc[8][8];
#pragma unroll
    for(int i=0;i<8;i++)
#pragma unroll
        for(int j=0;j<8;j++) acc[i][j]=0.f;
    float4 aa0=*(const float4*)(g_pr+(size_t)(m0+arow)*Dsz+ak);
    float4 aa1=*(const float4*)(g_pr+(size_t)(m0+arow)*Dsz+ak+4);
    float4 cc0=*(const float4*)(cb+(size_t)arow*Dsz+ak);
    float4 cc1=*(const float4*)(cb+(size_t)arow*Dsz+ak+4);
    for(int k0=0;k0<Dsz;k0+=16){
        __syncthreads();
        As[ak+0][arow]=aa0.x;As[ak+1][arow]=aa0.y;As[ak+2][arow]=aa0.z;As[ak+3][arow]=aa0.w;
        As[ak+4][arow]=aa1.x;As[ak+5][arow]=aa1.y;As[ak+6][arow]=aa1.z;As[ak+7][arow]=aa1.w;
        Bs[ak+0][arow]=cc0.x;Bs[ak+1][arow]=cc0.y;Bs[ak+2][arow]=cc0.z;Bs[ak+3][arow]=cc0.w;
        Bs[ak+4][arow]=cc1.x;Bs[ak+5][arow]=cc1.y;Bs[ak+6][arow]=cc1.z;Bs[ak+7][arow]=cc1.w;
        __syncthreads();
        if(k0+16<Dsz){
            aa0=*(const float4*)(g_pr+(size_t)(m0+arow)*Dsz+k0+16+ak);
            aa1=*(const float4*)(g_pr+(size_t)(m0+arow)*Dsz+k0+16+ak+4);
            cc0=*(const float4*)(cb+(size_t)arow*Dsz+k0+16+ak);
            cc1=*(const float4*)(cb+(size_t)arow*Dsz+k0+16+ak+4);
        }
#pragma unroll
        for(int kk=0;kk<16;kk++){
            float4 a0=*(float4*)&As[kk][ty*8],a1=*(float4*)&As[kk][ty*8+4];
            float4 b0=*(float4*)&Bs[kk][tx*8],b1=*(float4*)&Bs[kk][tx*8+4];
            float a[8]={a0.x,a0.y,a0.z,a0.w,a1.x,a1.y,a1.z,a1.w};
            float b[8]={b0.x,b0.y,b0.z,b0.w,b1.x,b1.y,b1.z,b1.w};
#pragma unroll
            for(int i=0;i<8;i++)
#pragma unroll
                for(int j=0;j<8;j++) acc[i][j]+=a[i]*b[j];
        }
    }
#pragma unroll
    for(int i=0;i<8;i++){
        float bd=1e30f; int bi=0;
#pragma unroll
        for(int j=0;j<8;j++){
            int n=tx*8+j;
            float d=g_cn2[n]-2.f*acc[i][j];
            if(d<bd){bd=d;bi=n;}
        }
        sRed[ty*8+i][tx]=make_float2(bd,__int_as_float(bi));
    }
    __syncthreads();
    if(tid<128){
        float bd=1e30f; int bi=0;
#pragma unroll
        for(int t=0;t<16;t++){
            float2 e=sRed[tid][t];
            if(e.x<bd){bd=e.x;bi=__float_as_int(e.y);}
        }
        g_idx[m0+tid]=bi;
    }
}

// ---------- VQ loss ----------
__global__ void loss_kernel(const float* __restrict__ cb) {
    __shared__ float sw[4];
    int m=blockIdx.x, tid=threadIdx.x;
    const float4 f=((const float4*)(g_pr+(size_t)m*Dsz))[tid];
    const float4 c=((const float4*)(cb+(size_t)g_idx[m]*Dsz))[tid];
    float dx=c.x-f.x,dy=c.y-f.y,dz=c.z-f.z,dw=c.w-f.w;
    float v=dx*dx+dy*dy+dz*dz+dw*dw;
#pragma unroll
    for(int o=16;o;o>>=1) v+=__shfl_xor_sync(0xffffffffu,v,o);
    if((tid&31)==0) sw[tid>>5]=v;
    __syncthreads();
    if(tid==0) atomicAdd(&g_loss,(double)(sw[0]+sw[1]+sw[2]+sw[3]));
}

// ---------- gated stack scan ----------
__global__ __launch_bounds__(256) void scan_kernel(const float* __restrict__ cb) {
    __shared__ int sIdx[256]; __shared__ float sP[256],sO[256];
    const int b=blockIdx.x>>6, dg=blockIdx.x&63;
    const int warp=threadIdx.x>>5, lane=threadIdx.x&31;
    const int d=dg*8+warp;
    float st=0.f;
    for(int t0=0;t0<Lsz;t0+=256){
        __syncthreads();
        int ix=g_idx[b*Lsz+t0+threadIdx.x];
        sIdx[threadIdx.x]=ix; sP[threadIdx.x]=g_gp[ix]; sO[threadIdx.x]=g_go[ix];
        __syncthreads();
        for(int tt=0;tt<256;tt++){
            float val=cb[(size_t)sIdx[tt]*Dsz+d];
            float p=sP[tt],o=sO[tt];
            float sh=__shfl_down_sync(0xffffffffu,st,1);
            if(lane==31) sh=val;
            st=((1.f-p)*st+p*sh)*(1.f-o);
            if(lane==31) g_stk[((size_t)b*Lsz+t0+tt)*Dsz+d]=st;
        }
    }
}

// ---------- final ----------
__device__ __forceinline__ float blkRed(float v, float* s) {
#pragma unroll
    for(int o=16;o;o>>=1) v+=__shfl_xor_sync(0xffffffffu,v,o);
    if((threadIdx.x&31)==0) s[threadIdx.x>>5]=v;
    __syncthreads();
    v=s[0]+s[1]+s[2]+s[3];
    __syncthreads();
    return v;
}

__global__ void final_kernel(const float* __restrict__ cb,
                             const float* __restrict__ lng,
                             const float* __restrict__ lnb,
                             const float* __restrict__ mb,
                             float* __restrict__ out, long out_size) {
    __shared__ float sw[4];
    const int m=blockIdx.x, tid=threadIdx.x;
    const float* pr=g_pr+(size_t)m*Dsz;
    const float4 c4=((const float4*)(cb+(size_t)g_idx[m]*Dsz))[tid];
    const float4 f4=((const float4*)pr)[tid];
    const float4 s4=((const float4*)(g_stk+(size_t)m*Dsz))[tid];
    const float4 i4=((const float4*)(g_pi+(size_t)m*Dsz))[tid];
    float cr[4],ci[4];
    cr[0]=(f4.x+(c4.x-f4.x))+s4.x; cr[1]=(f4.y+(c4.y-f4.y))+s4.y;
    cr[2]=(f4.z+(c4.z-f4.z))+s4.z; cr[3]=(f4.w+(c4.w-f4.w))+s4.w;
    ci[0]=i4.x;ci[1]=i4.y;ci[2]=i4.z;ci[3]=i4.w;
    float sr=cr[0]+cr[1]+cr[2]+cr[3], si=ci[0]+ci[1]+ci[2]+ci[3];
    float mur=blkRed(sr,sw)*(1.f/Dsz);
    float mui=blkRed(si,sw)*(1.f/Dsz);
    float vr=0.f,vi=0.f;
#pragma unroll
    for(int k=0;k<4;k++){float a=cr[k]-mur,b=ci[k]-mui;vr+=a*a;vi+=b*b;}
    float varr=blkRed(vr,sw)*(1.f/Dsz);
    float vari=blkRed(vi,sw)*(1.f/Dsz);
    float rr=rsqrtf(varr+1e-5f), ri=rsqrtf(vari+1e-5f);
#pragma unroll
    for(int k=0;k<4;k++){
        int d=tid*4+k;
        float nr=(cr[k]-mur)*rr*lng[d]+lnb[d];
        float ni=(ci[k]-mui)*ri*lng[Dsz+d]+lnb[Dsz+d];
        float mag=sqrtf(nr*nr+ni*ni);
        float sc=fmaxf(mag+mb[d],0.f)/(mag+1e-6f);
        out[(size_t)m*Dsz+d]=nr*sc;
        out[OUTHALF+(size_t)m*Dsz+d]=ni*sc;
    }
    if(m==0&&tid==0)
        out[out_size-1]=(float)(1.25*g_loss/(double)((size_t)Msz*Dsz));
}

extern "C" void kernel_launch(void* const* d_in, const int* in_sizes, int n_in,
                              void* d_out, int out_size) {
    const int*   tokens=(const int*)  d_in[0];
    const float* embed =(const float*)d_in[2];
    const float* q_w=(const float*)d_in[3],  *q_b=(const float*)d_in[4];
    const float* k_w=(const float*)d_in[5],  *k_b=(const float*)d_in[6];
    const float* v_w=(const float*)d_in[7],  *v_b=(const float*)d_in[8];
    const float* o_w=(const float*)d_in[9],  *o_b=(const float*)d_in[10];
    const float* cb =(const float*)d_in[11];
    const float* gw =(const float*)d_in[12], *gb=(const float*)d_in[13];
    const float* lng=(const float*)d_in[14], *lnb=(const float*)d_in[15];
    const float* mb =(const float*)d_in[16];
    float* out=(float*)d_out;

    static bool attr_set=false;
    if(!attr_set){
        cudaFuncSetAttribute(attn_kernel,cudaFuncAttributeMaxDynamicSharedMemorySize,7*64*AP*4);
        attr_set=true;
    }
    prep_kernel<<<1,128>>>(cb,gw,gb);
    gather_kernel<<<Msz,128>>>(tokens,embed);
    proj_kernel<<<dim3(4,64,6),256>>>(q_w,q_b,k_w,k_b,v_w,v_b);
    attn_kernel<<<dim3(16,64),512,7*64*AP*4>>>();
    oproj_kernel<<<dim3(8,64),256>>>(o_w,o_b);
    dist_kernel<<<64,256>>>(cb);
    loss_kernel<<<Msz,128>>>(cb);
    scan_kernel<<<512,256>>>(cb);
    final_kernel<<<Msz,128>>>(cb,lng,lnb,mb,out,(long)out_size);
}

// round 4
// speedup vs baseline: 1.0683x; 1.0683x over previous
#include <cuda_runtime.h>

#define Bsz 8
#define Lsz 1024
#define Dsz 512
#define HDsz 64
#define NCsz 128
#define Msz (Bsz*Lsz)
#define OUTHALF ((size_t)Msz*Dsz)
#define NEG_INF (-__int_as_float(0x7f800000))

__device__ float g_zr[Msz*Dsz];
__device__ float g_qr[Msz*Dsz], g_qi[Msz*Dsz];
__device__ float g_kr[Msz*Dsz], g_ki[Msz*Dsz];
__device__ float g_vr[Msz*Dsz], g_vi[Msz*Dsz];
__device__ float g_ar[Msz*Dsz], g_ai[Msz*Dsz];
__device__ float g_pr[Msz*Dsz], g_pi[Msz*Dsz];
__device__ int   g_idx[Msz];
__device__ float g_stk[Msz*Dsz];
__device__ float g_cn2[NCsz], g_gp[NCsz], g_go[NCsz];
__device__ double g_loss;

// ---------- prep ----------
__global__ void prep_kernel(const float* __restrict__ cb,
                            const float* __restrict__ gw,
                            const float* __restrict__ gb) {
    int j = threadIdx.x;
    if (j == 0) g_loss = 0.0;
    if (j < NCsz) {
        float s2 = 0.f, d0 = 0.f, d1 = 0.f;
        for (int d = 0; d < Dsz; d++) {
            float c = cb[j*Dsz + d];
            s2 += c*c; d0 += c*gw[d*2+0]; d1 += c*gw[d*2+1];
        }
        g_cn2[j] = s2;
        g_gp[j] = 1.f/(1.f+expf(-(d0+gb[0])));
        g_go[j] = 1.f/(1.f+expf(-(d1+gb[1])));
    }
}

// ---------- embedding gather ----------
__global__ void gather_kernel(const int* __restrict__ tokens,
                              const float* __restrict__ embed) {
    int m = blockIdx.x;
    const float4* src = (const float4*)(embed + (size_t)tokens[m]*Dsz);
    ((float4*)(g_zr + (size_t)m*Dsz))[threadIdx.x] = src[threadIdx.x];
}

// ---------- 6-way projection GEMM ----------
__global__ __launch_bounds__(256) void proj_kernel(
        const float* __restrict__ qw, const float* __restrict__ qb,
        const float* __restrict__ kw, const float* __restrict__ kb,
        const float* __restrict__ vw, const float* __restrict__ vb) {
    __shared__ float As[16][128], Bs[16][128];
    const int z = blockIdx.z, pair = z>>1, im = z&1;
    const float* W; const float* bias; float* C;
    if (pair==0){W=qw;bias=qb;C=im?g_qi:g_qr;}
    else if (pair==1){W=kw;bias=kb;C=im?g_ki:g_kr;}
    else {W=vw;bias=vb;C=im?g_vi:g_vr;}
    W += (size_t)im*Dsz*Dsz;
    const float sgn = im?1.f:-1.f;
    const int m0=blockIdx.y*128, n0=blockIdx.x*128;
    const int tid=threadIdx.x, ty=tid>>4, tx=tid&15;
    const int arow=tid>>1, ak=(tid&1)*8;
    const int brow=tid>>4, bcol=(tid&15)*8;
    float acc[8][8];
#pragma unroll
    for(int i=0;i<8;i++)
#pragma unroll
        for(int j=0;j<8;j++) acc[i][j]=0.f;
    float4 aa0=*(const float4*)(g_zr+(size_t)(m0+arow)*Dsz+ak);
    float4 aa1=*(const float4*)(g_zr+(size_t)(m0+arow)*Dsz+ak+4);
    float4 bb0=*(const float4*)(W+(size_t)brow*Dsz+n0+bcol);
    float4 bb1=*(const float4*)(W+(size_t)brow*Dsz+n0+bcol+4);
    for(int k0=0;k0<Dsz;k0+=16){
        __syncthreads();
        As[ak+0][arow]=aa0.x;As[ak+1][arow]=aa0.y;As[ak+2][arow]=aa0.z;As[ak+3][arow]=aa0.w;
        As[ak+4][arow]=aa1.x;As[ak+5][arow]=aa1.y;As[ak+6][arow]=aa1.z;As[ak+7][arow]=aa1.w;
        *(float4*)&Bs[brow][bcol]=bb0; *(float4*)&Bs[brow][bcol+4]=bb1;
        __syncthreads();
        if(k0+16<Dsz){
            aa0=*(const float4*)(g_zr+(size_t)(m0+arow)*Dsz+k0+16+ak);
            aa1=*(const float4*)(g_zr+(size_t)(m0+arow)*Dsz+k0+16+ak+4);
            bb0=*(const float4*)(W+(size_t)(k0+16+brow)*Dsz+n0+bcol);
            bb1=*(const float4*)(W+(size_t)(k0+16+brow)*Dsz+n0+bcol+4);
        }
#pragma unroll
        for(int kk=0;kk<16;kk++){
            float4 a0=*(float4*)&As[kk][ty*8],a1=*(float4*)&As[kk][ty*8+4];
            float4 b0=*(float4*)&Bs[kk][tx*8],b1=*(float4*)&Bs[kk][tx*8+4];
            float a[8]={a0.x,a0.y,a0.z,a0.w,a1.x,a1.y,a1.z,a1.w};
            float b[8]={b0.x,b0.y,b0.z,b0.w,b1.x,b1.y,b1.z,b1.w};
#pragma unroll
            for(int i=0;i<8;i++)
#pragma unroll
                for(int j=0;j<8;j++) acc[i][j]+=a[i]*b[j];
        }
    }
    float bv_[8];
#pragma unroll
    for(int j=0;j<8;j++){int n=n0+tx*8+j; bv_[j]=bias[n]+sgn*bias[Dsz+n];}
#pragma unroll
    for(int i=0;i<8;i++){
        float* cr=C+(size_t)(m0+ty*8+i)*Dsz+n0+tx*8;
        *(float4*)(cr)  =make_float4(acc[i][0]+bv_[0],acc[i][1]+bv_[1],acc[i][2]+bv_[2],acc[i][3]+bv_[3]);
        *(float4*)(cr+4)=make_float4(acc[i][4]+bv_[4],acc[i][5]+bv_[5],acc[i][6]+bv_[6],acc[i][7]+bv_[7]);
    }
}

// ---------- flash attention v3: 128x64 Q-tile, 512 threads, 4x4 micro-tile ----------
#define AP 68
#define ATTN_SMEM ((2*128 + 4*64 + 128) * AP * 4)
__global__ __launch_bounds__(512) void attn_kernel() {
    extern __shared__ float sm[];
    float* sQr=sm;             float* sQi=sQr+128*AP;
    float* sKr=sQi+128*AP;     float* sKi=sKr+64*AP;
    float* sVr=sKi+64*AP;      float* sVi=sVr+64*AP;
    float* sP =sVi+64*AP;
    const int bh=blockIdx.y, b=bh>>3, h=bh&7;
    const int i0=blockIdx.x*128;
    const int tid=threadIdx.x, ty=tid>>4, tx=tid&15;   // ty 0..31, tx 0..15
    const size_t base=(size_t)b*Lsz*Dsz + h*HDsz;
    // load Q 128x64 (2048 float4 per array)
#pragma unroll
    for(int u=0;u<4;u++){
        int li=tid+u*512, r=li>>4, c4=(li&15)*4;
        size_t g=base+(size_t)(i0+r)*Dsz+c4;
        *(float4*)&sQr[r*AP+c4]=*(const float4*)(g_qr+g);
        *(float4*)&sQi[r*AP+c4]=*(const float4*)(g_qi+g);
    }
    float m_run[4],l_run[4],accr[4][4],acci[4][4];
#pragma unroll
    for(int i=0;i<4;i++){m_run[i]=NEG_INF;l_run[i]=0.f;
#pragma unroll
        for(int j=0;j<4;j++){accr[i][j]=0.f;acci[i][j]=0.f;}}
    const int ntile = 2*blockIdx.x + 2;   // causal: tiles 0 .. 2*bx+1
    for(int jt=0;jt<ntile;jt++){
        const int s0=jt*64;
        __syncthreads();
        // load K (transposed) + V, 64x64 each (1024 float4 per array)
#pragma unroll
        for(int u=0;u<2;u++){
            int li=tid+u*512, r=li>>4, c4=(li&15)*4;
            size_t g=base+(size_t)(s0+r)*Dsz+c4;
            float4 a=*(const float4*)(g_kr+g);
            float4 c=*(const float4*)(g_ki+g);
            sKr[(c4+0)*AP+r]=a.x;sKr[(c4+1)*AP+r]=a.y;sKr[(c4+2)*AP+r]=a.z;sKr[(c4+3)*AP+r]=a.w;
            sKi[(c4+0)*AP+r]=c.x;sKi[(c4+1)*AP+r]=c.y;sKi[(c4+2)*AP+r]=c.z;sKi[(c4+3)*AP+r]=c.w;
            *(float4*)&sVr[r*AP+c4]=*(const float4*)(g_vr+g);
            *(float4*)&sVi[r*AP+c4]=*(const float4*)(g_vi+g);
        }
        __syncthreads();
        float s_[4][4];
#pragma unroll
        for(int i=0;i<4;i++)
#pragma unroll
            for(int j=0;j<4;j++) s_[i][j]=0.f;
#pragma unroll
        for(int k4=0;k4<16;k4++){
            float qrv[4][4],qiv[4][4];
#pragma unroll
            for(int i=0;i<4;i++){
                float4 t=*(float4*)&sQr[(4*ty+i)*AP+4*k4];
                qrv[i][0]=t.x;qrv[i][1]=t.y;qrv[i][2]=t.z;qrv[i][3]=t.w;
                float4 u=*(float4*)&sQi[(4*ty+i)*AP+4*k4];
                qiv[i][0]=u.x;qiv[i][1]=u.y;qiv[i][2]=u.z;qiv[i][3]=u.w;
            }
#pragma unroll
            for(int kk=0;kk<4;kk++){
                float4 kr4=*(float4*)&sKr[(4*k4+kk)*AP+4*tx];
                float4 ki4=*(float4*)&sKi[(4*k4+kk)*AP+4*tx];
#pragma unroll
                for(int i=0;i<4;i++){
                    s_[i][0]+=qrv[i][kk]*kr4.x+qiv[i][kk]*ki4.x;
                    s_[i][1]+=qrv[i][kk]*kr4.y+qiv[i][kk]*ki4.y;
                    s_[i][2]+=qrv[i][kk]*kr4.z+qiv[i][kk]*ki4.z;
                    s_[i][3]+=qrv[i][kk]*kr4.w+qiv[i][kk]*ki4.w;
                }
            }
        }
        const bool diag=(jt>=2*(int)blockIdx.x);
#pragma unroll
        for(int i=0;i<4;i++)
#pragma unroll
            for(int j=0;j<4;j++){
                s_[i][j]*=0.125f;
                if(diag && (s0+4*tx+j > i0+4*ty+i)) s_[i][j]=NEG_INF;
            }
        float p_[4][4];
#pragma unroll
        for(int i=0;i<4;i++){
            float mx=fmaxf(fmaxf(s_[i][0],s_[i][1]),fmaxf(s_[i][2],s_[i][3]));
#pragma unroll
            for(int off=8;off;off>>=1) mx=fmaxf(mx,__shfl_xor_sync(0xffffffffu,mx,off));
            float mnew=fmaxf(m_run[i],mx);
            float alpha=__expf(m_run[i]-mnew);
            m_run[i]=mnew;
            float rs=0.f;
#pragma unroll
            for(int j=0;j<4;j++){p_[i][j]=__expf(s_[i][j]-mnew);rs+=p_[i][j];}
#pragma unroll
            for(int off=8;off;off>>=1) rs+=__shfl_xor_sync(0xffffffffu,rs,off);
            l_run[i]=l_run[i]*alpha+rs;
#pragma unroll
            for(int j=0;j<4;j++){accr[i][j]*=alpha;acci[i][j]*=alpha;}
        }
#pragma unroll
        for(int i=0;i<4;i++)
            *(float4*)&sP[(4*ty+i)*AP+4*tx]=make_float4(p_[i][0],p_[i][1],p_[i][2],p_[i][3]);
        __syncthreads();
#pragma unroll
        for(int c4=0;c4<16;c4++){
            float pp[4][4];
#pragma unroll
            for(int i=0;i<4;i++){
                float4 t=*(float4*)&sP[(4*ty+i)*AP+4*c4];
                pp[i][0]=t.x;pp[i][1]=t.y;pp[i][2]=t.z;pp[i][3]=t.w;
            }
#pragma unroll
            for(int cc=0;cc<4;cc++){
                float4 vr4=*(float4*)&sVr[(4*c4+cc)*AP+4*tx];
                float4 vi4=*(float4*)&sVi[(4*c4+cc)*AP+4*tx];
#pragma unroll
                for(int i=0;i<4;i++){
                    accr[i][0]+=pp[i][cc]*vr4.x;accr[i][1]+=pp[i][cc]*vr4.y;
                    accr[i][2]+=pp[i][cc]*vr4.z;accr[i][3]+=pp[i][cc]*vr4.w;
                    acci[i][0]+=pp[i][cc]*vi4.x;acci[i][1]+=pp[i][cc]*vi4.y;
                    acci[i][2]+=pp[i][cc]*vi4.z;acci[i][3]+=pp[i][cc]*vi4.w;
                }
            }
        }
    }
#pragma unroll
    for(int i=0;i<4;i++){
        float inv=1.f/l_run[i];
        size_t g=base+(size_t)(i0+4*ty+i)*Dsz+4*tx;
        *(float4*)(g_ar+g)=make_float4(accr[i][0]*inv,accr[i][1]*inv,accr[i][2]*inv,accr[i][3]*inv);
        *(float4*)(g_ai+g)=make_float4(acci[i][0]*inv,acci[i][1]*inv,acci[i][2]*inv,acci[i][3]*inv);
    }
}

// ---------- complex O-projection ----------
__global__ __launch_bounds__(256) void oproj_kernel(const float* __restrict__ ow,
                                                    const float* __restrict__ ob) {
    __shared__ float Ars[16][128],Ais[16][128],B0s[16][64],B1s[16][64];
    const int m0=blockIdx.y*128, n0=blockIdx.x*64;
    const int tid=threadIdx.x, ty=tid>>4, tx=tid&15;
    const int arow=tid>>1, ak=(tid&1)*8;
    const int bkr=(tid&127)>>3, bn=((tid&127)&7)*8;
    const bool isB1=tid>=128;
    const float* w0=ow; const float* w1=ow+(size_t)Dsz*Dsz;
    const float* ws=isB1?w1:w0;
    float accR[8][4],accI[8][4];
#pragma unroll
    for(int i=0;i<8;i++)
#pragma unroll
        for(int j=0;j<4;j++){accR[i][j]=0.f;accI[i][j]=0.f;}
    float4 ar0=*(const float4*)(g_ar+(size_t)(m0+arow)*Dsz+ak);
    float4 ar1=*(const float4*)(g_ar+(size_t)(m0+arow)*Dsz+ak+4);
    float4 ai0=*(const float4*)(g_ai+(size_t)(m0+arow)*Dsz+ak);
    float4 ai1=*(const float4*)(g_ai+(size_t)(m0+arow)*Dsz+ak+4);
    float4 bb0=*(const float4*)(ws+(size_t)bkr*Dsz+n0+bn);
    float4 bb1=*(const float4*)(ws+(size_t)bkr*Dsz+n0+bn+4);
    for(int k0=0;k0<Dsz;k0+=16){
        __syncthreads();
        Ars[ak+0][arow]=ar0.x;Ars[ak+1][arow]=ar0.y;Ars[ak+2][arow]=ar0.z;Ars[ak+3][arow]=ar0.w;
        Ars[ak+4][arow]=ar1.x;Ars[ak+5][arow]=ar1.y;Ars[ak+6][arow]=ar1.z;Ars[ak+7][arow]=ar1.w;
        Ais[ak+0][arow]=ai0.x;Ais[ak+1][arow]=ai0.y;Ais[ak+2][arow]=ai0.z;Ais[ak+3][arow]=ai0.w;
        Ais[ak+4][arow]=ai1.x;Ais[ak+5][arow]=ai1.y;Ais[ak+6][arow]=ai1.z;Ais[ak+7][arow]=ai1.w;
        if(isB1){*(float4*)&B1s[bkr][bn]=bb0;*(float4*)&B1s[bkr][bn+4]=bb1;}
        else    {*(float4*)&B0s[bkr][bn]=bb0;*(float4*)&B0s[bkr][bn+4]=bb1;}
        __syncthreads();
        if(k0+16<Dsz){
            ar0=*(const float4*)(g_ar+(size_t)(m0+arow)*Dsz+k0+16+ak);
            ar1=*(const float4*)(g_ar+(size_t)(m0+arow)*Dsz+k0+16+ak+4);
            ai0=*(const float4*)(g_ai+(size_t)(m0+arow)*Dsz+k0+16+ak);
            ai1=*(const float4*)(g_ai+(size_t)(m0+arow)*Dsz+k0+16+ak+4);
            bb0=*(const float4*)(ws+(size_t)(k0+16+bkr)*Dsz+n0+bn);
            bb1=*(const float4*)(ws+(size_t)(k0+16+bkr)*Dsz+n0+bn+4);
        }
#pragma unroll
        for(int kk=0;kk<16;kk++){
            float4 a0=*(float4*)&Ars[kk][ty*8],a1=*(float4*)&Ars[kk][ty*8+4];
            float4 c0=*(float4*)&Ais[kk][ty*8],c1=*(float4*)&Ais[kk][ty*8+4];
            float4 b0=*(float4*)&B0s[kk][tx*4],b1=*(float4*)&B1s[kk][tx*4];
            float ar8[8]={a0.x,a0.y,a0.z,a0.w,a1.x,a1.y,a1.z,a1.w};
            float ai8[8]={c0.x,c0.y,c0.z,c0.w,c1.x,c1.y,c1.z,c1.w};
            float bw0[4]={b0.x,b0.y,b0.z,b0.w};
            float bw1[4]={b1.x,b1.y,b1.z,b1.w};
#pragma unroll
            for(int i=0;i<8;i++)
#pragma unroll
                for(int j=0;j<4;j++){
                    accR[i][j]+=ar8[i]*bw0[j]-ai8[i]*bw1[j];
                    accI[i][j]+=ai8[i]*bw0[j]+ar8[i]*bw1[j];
                }
        }
    }
    float bR[4],bI[4];
#pragma unroll
    for(int j=0;j<4;j++){int n=n0+tx*4+j;bR[j]=ob[n]-ob[Dsz+n];bI[j]=ob[n]+ob[Dsz+n];}
#pragma unroll
    for(int i=0;i<8;i++){
        size_t g=(size_t)(m0+ty*8+i)*Dsz+n0+tx*4;
        *(float4*)(g_pr+g)=make_float4(accR[i][0]+bR[0],accR[i][1]+bR[1],accR[i][2]+bR[2],accR[i][3]+bR[3]);
        *(float4*)(g_pi+g)=make_float4(accI[i][0]+bI[0],accI[i][1]+bI[1],accI[i][2]+bI[2],accI[i][3]+bI[3]);
    }
}

// ---------- VQ distance GEMM + first-argmin ----------
__global__ __launch_bounds__(256) void dist_kernel(const float* __restrict__ cb) {
    __shared__ float As[16][128], Bs[16][128];
    __shared__ float2 sRed[128][16];
    const int m0=blockIdx.x*128;
    const int tid=threadIdx.x, ty=tid>>4, tx=tid&15;
    const int arow=tid>>1, ak=(tid&1)*8;
    float acc[8][8];
#pragma unroll
    for(int i=0;i<8;i++)
#pragma unroll
        for(int j=0;j<8;j++) acc[i][j]=0.f;
    float4 aa0=*(const float4*)(g_pr+(size_t)(m0+arow)*Dsz+ak);
    float4 aa1=*(const float4*)(g_pr+(size_t)(m0+arow)*Dsz+ak+4);
    float4 cc0=*(const float4*)(cb+(size_t)arow*Dsz+ak);
    float4 cc1=*(const float4*)(cb+(size_t)arow*Dsz+ak+4);
    for(int k0=0;k0<Dsz;k0+=16){
        __syncthreads();
        As[ak+0][arow]=aa0.x;As[ak+1][arow]=aa0.y;As[ak+2][arow]=aa0.z;As[ak+3][arow]=aa0.w;
        As[ak+4][arow]=aa1.x;As[ak+5][arow]=aa1.y;As[ak+6][arow]=aa1.z;As[ak+7][arow]=aa1.w;
        Bs[ak+0][arow]=cc0.x;Bs[ak+1][arow]=cc0.y;Bs[ak+2][arow]=cc0.z;Bs[ak+3][arow]=cc0.w;
        Bs[ak+4][arow]=cc1.x;Bs[ak+5][arow]=cc1.y;Bs[ak+6][arow]=cc1.z;Bs[ak+7][arow]=cc1.w;
        __syncthreads();
        if(k0+16<Dsz){
            aa0=*(const float4*)(g_pr+(size_t)(m0+arow)*Dsz+k0+16+ak);
            aa1=*(const float4*)(g_pr+(size_t)(m0+arow)*Dsz+k0+16+ak+4);
            cc0=*(const float4*)(cb+(size_t)arow*Dsz+k0+16+ak);
            cc1=*(const float4*)(cb+(size_t)arow*Dsz+k0+16+ak+4);
        }
#pragma unroll
        for(int kk=0;kk<16;kk++){
            float4 a0=*(float4*)&As[kk][ty*8],a1=*(float4*)&As[kk][ty*8+4];
            float4 b0=*(float4*)&Bs[kk][tx*8],b1=*(float4*)&Bs[kk][tx*8+4];
            float a[8]={a0.x,a0.y,a0.z,a0.w,a1.x,a1.y,a1.z,a1.w};
            float b[8]={b0.x,b0.y,b0.z,b0.w,b1.x,b1.y,b1.z,b1.w};
#pragma unroll
            for(int i=0;i<8;i++)
#pragma unroll
                for(int j=0;j<8;j++) acc[i][j]+=a[i]*b[j];
        }
    }
#pragma unroll
    for(int i=0;i<8;i++){
        float bd=1e30f; int bi=0;
#pragma unroll
        for(int j=0;j<8;j++){
            int n=tx*8+j;
            float d=g_cn2[n]-2.f*acc[i][j];
            if(d<bd){bd=d;bi=n;}
        }
        sRed[ty*8+i][tx]=make_float2(bd,__int_as_float(bi));
    }
    __syncthreads();
    if(tid<128){
        float bd=1e30f; int bi=0;
#pragma unroll
        for(int t=0;t<16;t++){
            float2 e=sRed[tid][t];
            if(e.x<bd){bd=e.x;bi=__float_as_int(e.y);}
        }
        g_idx[m0+tid]=bi;
    }
}

// ---------- VQ loss ----------
__global__ void loss_kernel(const float* __restrict__ cb) {
    __shared__ float sw[4];
    int m=blockIdx.x, tid=threadIdx.x;
    const float4 f=((const float4*)(g_pr+(size_t)m*Dsz))[tid];
    const float4 c=((const float4*)(cb+(size_t)g_idx[m]*Dsz))[tid];
    float dx=c.x-f.x,dy=c.y-f.y,dz=c.z-f.z,dw=c.w-f.w;
    float v=dx*dx+dy*dy+dz*dz+dw*dw;
#pragma unroll
    for(int o=16;o;o>>=1) v+=__shfl_xor_sync(0xffffffffu,v,o);
    if((tid&31)==0) sw[tid>>5]=v;
    __syncthreads();
    if(tid==0) atomicAdd(&g_loss,(double)(sw[0]+sw[1]+sw[2]+sw[3]));
}

// ---------- gated stack scan ----------
__global__ __launch_bounds__(256) void scan_kernel(const float* __restrict__ cb) {
    __shared__ int sIdx[256]; __shared__ float sP[256],sO[256];
    const int b=blockIdx.x>>6, dg=blockIdx.x&63;
    const int warp=threadIdx.x>>5, lane=threadIdx.x&31;
    const int d=dg*8+warp;
    float st=0.f;
    for(int t0=0;t0<Lsz;t0+=256){
        __syncthreads();
        int ix=g_idx[b*Lsz+t0+threadIdx.x];
        sIdx[threadIdx.x]=ix; sP[threadIdx.x]=g_gp[ix]; sO[threadIdx.x]=g_go[ix];
        __syncthreads();
        for(int tt=0;tt<256;tt++){
            float val=cb[(size_t)sIdx[tt]*Dsz+d];
            float p=sP[tt],o=sO[tt];
            float sh=__shfl_down_sync(0xffffffffu,st,1);
            if(lane==31) sh=val;
            st=((1.f-p)*st+p*sh)*(1.f-o);
            if(lane==31) g_stk[((size_t)b*Lsz+t0+tt)*Dsz+d]=st;
        }
    }
}

// ---------- final ----------
__device__ __forceinline__ float blkRed(float v, float* s) {
#pragma unroll
    for(int o=16;o;o>>=1) v+=__shfl_xor_sync(0xffffffffu,v,o);
    if((threadIdx.x&31)==0) s[threadIdx.x>>5]=v;
    __syncthreads();
    v=s[0]+s[1]+s[2]+s[3];
    __syncthreads();
    return v;
}

__global__ void final_kernel(const float* __restrict__ cb,
                             const float* __restrict__ lng,
                             const float* __restrict__ lnb,
                             const float* __restrict__ mb,
                             float* __restrict__ out, long out_size) {
    __shared__ float sw[4];
    const int m=blockIdx.x, tid=threadIdx.x;
    const float* pr=g_pr+(size_t)m*Dsz;
    const float4 c4=((const float4*)(cb+(size_t)g_idx[m]*Dsz))[tid];
    const float4 f4=((const float4*)pr)[tid];
    const float4 s4=((const float4*)(g_stk+(size_t)m*Dsz))[tid];
    const float4 i4=((const float4*)(g_pi+(size_t)m*Dsz))[tid];
    float cr[4],ci[4];
    cr[0]=(f4.x+(c4.x-f4.x))+s4.x; cr[1]=(f4.y+(c4.y-f4.y))+s4.y;
    cr[2]=(f4.z+(c4.z-f4.z))+s4.z; cr[3]=(f4.w+(c4.w-f4.w))+s4.w;
    ci[0]=i4.x;ci[1]=i4.y;ci[2]=i4.z;ci[3]=i4.w;
    float sr=cr[0]+cr[1]+cr[2]+cr[3], si=ci[0]+ci[1]+ci[2]+ci[3];
    float mur=blkRed(sr,sw)*(1.f/Dsz);
    float mui=blkRed(si,sw)*(1.f/Dsz);
    float vr=0.f,vi=0.f;
#pragma unroll
    for(int k=0;k<4;k++){float a=cr[k]-mur,b=ci[k]-mui;vr+=a*a;vi+=b*b;}
    float varr=blkRed(vr,sw)*(1.f/Dsz);
    float vari=blkRed(vi,sw)*(1.f/Dsz);
    float rr=rsqrtf(varr+1e-5f), ri=rsqrtf(vari+1e-5f);
#pragma unroll
    for(int k=0;k<4;k++){
        int d=tid*4+k;
        float nr=(cr[k]-mur)*rr*lng[d]+lnb[d];
        float ni=(ci[k]-mui)*ri*lng[Dsz+d]+lnb[Dsz+d];
        float mag=sqrtf(nr*nr+ni*ni);
        float sc=fmaxf(mag+mb[d],0.f)/(mag+1e-6f);
        out[(size_t)m*Dsz+d]=nr*sc;
        out[OUTHALF+(size_t)m*Dsz+d]=ni*sc;
    }
    if(m==0&&tid==0)
        out[out_size-1]=(float)(1.25*g_loss/(double)((size_t)Msz*Dsz));
}

extern "C" void kernel_launch(void* const* d_in, const int* in_sizes, int n_in,
                              void* d_out, int out_size) {
    const int*   tokens=(const int*)  d_in[0];
    const float* embed =(const float*)d_in[2];
    const float* q_w=(const float*)d_in[3],  *q_b=(const float*)d_in[4];
    const float* k_w=(const float*)d_in[5],  *k_b=(const float*)d_in[6];
    const float* v_w=(const float*)d_in[7],  *v_b=(const float*)d_in[8];
    const float* o_w=(const float*)d_in[9],  *o_b=(const float*)d_in[10];
    const float* cb =(const float*)d_in[11];
    const float* gw =(const float*)d_in[12], *gb=(const float*)d_in[13];
    const float* lng=(const float*)d_in[14], *lnb=(const float*)d_in[15];
    const float* mb =(const float*)d_in[16];
    float* out=(float*)d_out;

    static bool attr_set=false;
    if(!attr_set){
        cudaFuncSetAttribute(attn_kernel,cudaFuncAttributeMaxDynamicSharedMemorySize,ATTN_SMEM);
        attr_set=true;
    }
    prep_kernel<<<1,128>>>(cb,gw,gb);
    gather_kernel<<<Msz,128>>>(tokens,embed);
    proj_kernel<<<dim3(4,64,6),256>>>(q_w,q_b,k_w,k_b,v_w,v_b);
    attn_kernel<<<dim3(8,64),512,ATTN_SMEM>>>();
    oproj_kernel<<<dim3(8,64),256>>>(o_w,o_b);
    dist_kernel<<<64,256>>>(cb);
    loss_kernel<<<Msz,128>>>(cb);
    scan_kernel<<<512,256>>>(cb);
    final_kernel<<<Msz,128>>>(cb,lng,lnb,mb,out,(long)out_size);
}

// round 5
// speedup vs baseline: 1.0696x; 1.0012x over previous
#include <cuda_runtime.h>

#define Bsz 8
#define Lsz 1024
#define Dsz 512
#define HDsz 64
#define NCsz 128
#define Msz (Bsz*Lsz)
#define OUTHALF ((size_t)Msz*Dsz)
#define NEG_INF (-__int_as_float(0x7f800000))

__device__ float g_zr[Msz*Dsz];
__device__ float g_qr[Msz*Dsz], g_qi[Msz*Dsz];
__device__ float g_kr[Msz*Dsz], g_ki[Msz*Dsz];
__device__ float g_vr[Msz*Dsz], g_vi[Msz*Dsz];
__device__ float g_ar[Msz*Dsz], g_ai[Msz*Dsz];
__device__ float g_pr[Msz*Dsz], g_pi[Msz*Dsz];
__device__ int   g_idx[Msz];
__device__ float g_stk[Msz*Dsz];
__device__ float g_cn2[NCsz], g_gp[NCsz], g_go[NCsz];
__device__ double g_loss;

// ---------- prep ----------
__global__ void prep_kernel(const float* __restrict__ cb,
                            const float* __restrict__ gw,
                            const float* __restrict__ gb) {
    int j = threadIdx.x;
    if (j == 0) g_loss = 0.0;
    if (j < NCsz) {
        float s2 = 0.f, d0 = 0.f, d1 = 0.f;
        for (int d = 0; d < Dsz; d++) {
            float c = cb[j*Dsz + d];
            s2 += c*c; d0 += c*gw[d*2+0]; d1 += c*gw[d*2+1];
        }
        g_cn2[j] = s2;
        g_gp[j] = 1.f/(1.f+expf(-(d0+gb[0])));
        g_go[j] = 1.f/(1.f+expf(-(d1+gb[1])));
    }
}

// ---------- embedding gather ----------
__global__ void gather_kernel(const int* __restrict__ tokens,
                              const float* __restrict__ embed) {
    int m = blockIdx.x;
    const float4* src = (const float4*)(embed + (size_t)tokens[m]*Dsz);
    ((float4*)(g_zr + (size_t)m*Dsz))[threadIdx.x] = src[threadIdx.x];
}

// ---------- 6-way projection GEMM ----------
__global__ __launch_bounds__(256) void proj_kernel(
        const float* __restrict__ qw, const float* __restrict__ qb,
        const float* __restrict__ kw, const float* __restrict__ kb,
        const float* __restrict__ vw, const float* __restrict__ vb) {
    __shared__ float As[16][128], Bs[16][128];
    const int z = blockIdx.z, pair = z>>1, im = z&1;
    const float* W; const float* bias; float* C;
    if (pair==0){W=qw;bias=qb;C=im?g_qi:g_qr;}
    else if (pair==1){W=kw;bias=kb;C=im?g_ki:g_kr;}
    else {W=vw;bias=vb;C=im?g_vi:g_vr;}
    W += (size_t)im*Dsz*Dsz;
    const float sgn = im?1.f:-1.f;
    const int m0=blockIdx.y*128, n0=blockIdx.x*128;
    const int tid=threadIdx.x, ty=tid>>4, tx=tid&15;
    const int arow=tid>>1, ak=(tid&1)*8;
    const int brow=tid>>4, bcol=(tid&15)*8;
    float acc[8][8];
#pragma unroll
    for(int i=0;i<8;i++)
#pragma unroll
        for(int j=0;j<8;j++) acc[i][j]=0.f;
    float4 aa0=*(const float4*)(g_zr+(size_t)(m0+arow)*Dsz+ak);
    float4 aa1=*(const float4*)(g_zr+(size_t)(m0+arow)*Dsz+ak+4);
    float4 bb0=*(const float4*)(W+(size_t)brow*Dsz+n0+bcol);
    float4 bb1=*(const float4*)(W+(size_t)brow*Dsz+n0+bcol+4);
    for(int k0=0;k0<Dsz;k0+=16){
        __syncthreads();
        As[ak+0][arow]=aa0.x;As[ak+1][arow]=aa0.y;As[ak+2][arow]=aa0.z;As[ak+3][arow]=aa0.w;
        As[ak+4][arow]=aa1.x;As[ak+5][arow]=aa1.y;As[ak+6][arow]=aa1.z;As[ak+7][arow]=aa1.w;
        *(float4*)&Bs[brow][bcol]=bb0; *(float4*)&Bs[brow][bcol+4]=bb1;
        __syncthreads();
        if(k0+16<Dsz){
            aa0=*(const float4*)(g_zr+(size_t)(m0+arow)*Dsz+k0+16+ak);
            aa1=*(const float4*)(g_zr+(size_t)(m0+arow)*Dsz+k0+16+ak+4);
            bb0=*(const float4*)(W+(size_t)(k0+16+brow)*Dsz+n0+bcol);
            bb1=*(const float4*)(W+(size_t)(k0+16+brow)*Dsz+n0+bcol+4);
        }
#pragma unroll
        for(int kk=0;kk<16;kk++){
            float4 a0=*(float4*)&As[kk][ty*8],a1=*(float4*)&As[kk][ty*8+4];
            float4 b0=*(float4*)&Bs[kk][tx*8],b1=*(float4*)&Bs[kk][tx*8+4];
            float a[8]={a0.x,a0.y,a0.z,a0.w,a1.x,a1.y,a1.z,a1.w};
            float b[8]={b0.x,b0.y,b0.z,b0.w,b1.x,b1.y,b1.z,b1.w};
#pragma unroll
            for(int i=0;i<8;i++)
#pragma unroll
                for(int j=0;j<8;j++) acc[i][j]+=a[i]*b[j];
        }
    }
    float bv_[8];
#pragma unroll
    for(int j=0;j<8;j++){int n=n0+tx*8+j; bv_[j]=bias[n]+sgn*bias[Dsz+n];}
#pragma unroll
    for(int i=0;i<8;i++){
        float* cr=C+(size_t)(m0+ty*8+i)*Dsz+n0+tx*8;
        *(float4*)(cr)  =make_float4(acc[i][0]+bv_[0],acc[i][1]+bv_[1],acc[i][2]+bv_[2],acc[i][3]+bv_[3]);
        *(float4*)(cr+4)=make_float4(acc[i][4]+bv_[4],acc[i][5]+bv_[5],acc[i][6]+bv_[6],acc[i][7]+bv_[7]);
    }
}

// ---------- flash attention v3: 128x64 Q-tile, 512 threads, 4x4 micro-tile ----------
#define AP 68
#define ATTN_SMEM ((2*128 + 4*64 + 128) * AP * 4)
__global__ __launch_bounds__(512) void attn_kernel() {
    extern __shared__ float sm[];
    float* sQr=sm;             float* sQi=sQr+128*AP;
    float* sKr=sQi+128*AP;     float* sKi=sKr+64*AP;
    float* sVr=sKi+64*AP;      float* sVi=sVr+64*AP;
    float* sP =sVi+64*AP;
    const int bh=blockIdx.y, b=bh>>3, h=bh&7;
    const int i0=blockIdx.x*128;
    const int tid=threadIdx.x, ty=tid>>4, tx=tid&15;   // ty 0..31, tx 0..15
    const size_t base=(size_t)b*Lsz*Dsz + h*HDsz;
    // load Q 128x64 (2048 float4 per array)
#pragma unroll
    for(int u=0;u<4;u++){
        int li=tid+u*512, r=li>>4, c4=(li&15)*4;
        size_t g=base+(size_t)(i0+r)*Dsz+c4;
        *(float4*)&sQr[r*AP+c4]=*(const float4*)(g_qr+g);
        *(float4*)&sQi[r*AP+c4]=*(const float4*)(g_qi+g);
    }
    float m_run[4],l_run[4],accr[4][4],acci[4][4];
#pragma unroll
    for(int i=0;i<4;i++){m_run[i]=NEG_INF;l_run[i]=0.f;
#pragma unroll
        for(int j=0;j<4;j++){accr[i][j]=0.f;acci[i][j]=0.f;}}
    const int ntile = 2*blockIdx.x + 2;   // causal: tiles 0 .. 2*bx+1
    for(int jt=0;jt<ntile;jt++){
        const int s0=jt*64;
        __syncthreads();
        // load K (transposed) + V, 64x64 each (1024 float4 per array)
#pragma unroll
        for(int u=0;u<2;u++){
            int li=tid+u*512, r=li>>4, c4=(li&15)*4;
            size_t g=base+(size_t)(s0+r)*Dsz+c4;
            float4 a=*(const float4*)(g_kr+g);
            float4 c=*(const float4*)(g_ki+g);
            sKr[(c4+0)*AP+r]=a.x;sKr[(c4+1)*AP+r]=a.y;sKr[(c4+2)*AP+r]=a.z;sKr[(c4+3)*AP+r]=a.w;
            sKi[(c4+0)*AP+r]=c.x;sKi[(c4+1)*AP+r]=c.y;sKi[(c4+2)*AP+r]=c.z;sKi[(c4+3)*AP+r]=c.w;
            *(float4*)&sVr[r*AP+c4]=*(const float4*)(g_vr+g);
            *(float4*)&sVi[r*AP+c4]=*(const float4*)(g_vi+g);
        }
        __syncthreads();
        float s_[4][4];
#pragma unroll
        for(int i=0;i<4;i++)
#pragma unroll
            for(int j=0;j<4;j++) s_[i][j]=0.f;
#pragma unroll
        for(int k4=0;k4<16;k4++){
            float qrv[4][4],qiv[4][4];
#pragma unroll
            for(int i=0;i<4;i++){
                float4 t=*(float4*)&sQr[(4*ty+i)*AP+4*k4];
                qrv[i][0]=t.x;qrv[i][1]=t.y;qrv[i][2]=t.z;qrv[i][3]=t.w;
                float4 u=*(float4*)&sQi[(4*ty+i)*AP+4*k4];
                qiv[i][0]=u.x;qiv[i][1]=u.y;qiv[i][2]=u.z;qiv[i][3]=u.w;
            }
#pragma unroll
            for(int kk=0;kk<4;kk++){
                float4 kr4=*(float4*)&sKr[(4*k4+kk)*AP+4*tx];
                float4 ki4=*(float4*)&sKi[(4*k4+kk)*AP+4*tx];
#pragma unroll
                for(int i=0;i<4;i++){
                    s_[i][0]+=qrv[i][kk]*kr4.x+qiv[i][kk]*ki4.x;
                    s_[i][1]+=qrv[i][kk]*kr4.y+qiv[i][kk]*ki4.y;
                    s_[i][2]+=qrv[i][kk]*kr4.z+qiv[i][kk]*ki4.z;
                    s_[i][3]+=qrv[i][kk]*kr4.w+qiv[i][kk]*ki4.w;
                }
            }
        }
        const bool diag=(jt>=2*(int)blockIdx.x);
#pragma unroll
        for(int i=0;i<4;i++)
#pragma unroll
            for(int j=0;j<4;j++){
                s_[i][j]*=0.125f;
                if(diag && (s0+4*tx+j > i0+4*ty+i)) s_[i][j]=NEG_INF;
            }
        float p_[4][4];
#pragma unroll
        for(int i=0;i<4;i++){
            float mx=fmaxf(fmaxf(s_[i][0],s_[i][1]),fmaxf(s_[i][2],s_[i][3]));
#pragma unroll
            for(int off=8;off;off>>=1) mx=fmaxf(mx,__shfl_xor_sync(0xffffffffu,mx,off));
            float mnew=fmaxf(m_run[i],mx);
            float alpha=__expf(m_run[i]-mnew);
            m_run[i]=mnew;
            float rs=0.f;
#pragma unroll
            for(int j=0;j<4;j++){p_[i][j]=__expf(s_[i][j]-mnew);rs+=p_[i][j];}
#pragma unroll
            for(int off=8;off;off>>=1) rs+=__shfl_xor_sync(0xffffffffu,rs,off);
            l_run[i]=l_run[i]*alpha+rs;
#pragma unroll
            for(int j=0;j<4;j++){accr[i][j]*=alpha;acci[i][j]*=alpha;}
        }
#pragma unroll
        for(int i=0;i<4;i++)
            *(float4*)&sP[(4*ty+i)*AP+4*tx]=make_float4(p_[i][0],p_[i][1],p_[i][2],p_[i][3]);
        __syncthreads();
#pragma unroll
        for(int c4=0;c4<16;c4++){
            float pp[4][4];
#pragma unroll
            for(int i=0;i<4;i++){
                float4 t=*(float4*)&sP[(4*ty+i)*AP+4*c4];
                pp[i][0]=t.x;pp[i][1]=t.y;pp[i][2]=t.z;pp[i][3]=t.w;
            }
#pragma unroll
            for(int cc=0;cc<4;cc++){
                float4 vr4=*(float4*)&sVr[(4*c4+cc)*AP+4*tx];
                float4 vi4=*(float4*)&sVi[(4*c4+cc)*AP+4*tx];
#pragma unroll
                for(int i=0;i<4;i++){
                    accr[i][0]+=pp[i][cc]*vr4.x;accr[i][1]+=pp[i][cc]*vr4.y;
                    accr[i][2]+=pp[i][cc]*vr4.z;accr[i][3]+=pp[i][cc]*vr4.w;
                    acci[i][0]+=pp[i][cc]*vi4.x;acci[i][1]+=pp[i][cc]*vi4.y;
                    acci[i][2]+=pp[i][cc]*vi4.z;acci[i][3]+=pp[i][cc]*vi4.w;
                }
            }
        }
    }
#pragma unroll
    for(int i=0;i<4;i++){
        float inv=1.f/l_run[i];
        size_t g=base+(size_t)(i0+4*ty+i)*Dsz+4*tx;
        *(float4*)(g_ar+g)=make_float4(accr[i][0]*inv,accr[i][1]*inv,accr[i][2]*inv,accr[i][3]*inv);
        *(float4*)(g_ai+g)=make_float4(acci[i][0]*inv,acci[i][1]*inv,acci[i][2]*inv,acci[i][3]*inv);
    }
}

// ---------- complex O-projection ----------
__global__ __launch_bounds__(256) void oproj_kernel(const float* __restrict__ ow,
                                                    const float* __restrict__ ob) {
    __shared__ float Ars[16][128],Ais[16][128],B0s[16][64],B1s[16][64];
    const int m0=blockIdx.y*128, n0=blockIdx.x*64;
    const int tid=threadIdx.x, ty=tid>>4, tx=tid&15;
    const int arow=tid>>1, ak=(tid&1)*8;
    const int bkr=(tid&127)>>3, bn=((tid&127)&7)*8;
    const bool isB1=tid>=128;
    const float* w0=ow; const float* w1=ow+(size_t)Dsz*Dsz;
    const float* ws=isB1?w1:w0;
    float accR[8][4],accI[8][4];
#pragma unroll
    for(int i=0;i<8;i++)
#pragma unroll
        for(int j=0;j<4;j++){accR[i][j]=0.f;accI[i][j]=0.f;}
    float4 ar0=*(const float4*)(g_ar+(size_t)(m0+arow)*Dsz+ak);
    float4 ar1=*(const float4*)(g_ar+(size_t)(m0+arow)*Dsz+ak+4);
    float4 ai0=*(const float4*)(g_ai+(size_t)(m0+arow)*Dsz+ak);
    float4 ai1=*(const float4*)(g_ai+(size_t)(m0+arow)*Dsz+ak+4);
    float4 bb0=*(const float4*)(ws+(size_t)bkr*Dsz+n0+bn);
    float4 bb1=*(const float4*)(ws+(size_t)bkr*Dsz+n0+bn+4);
    for(int k0=0;k0<Dsz;k0+=16){
        __syncthreads();
        Ars[ak+0][arow]=ar0.x;Ars[ak+1][arow]=ar0.y;Ars[ak+2][arow]=ar0.z;Ars[ak+3][arow]=ar0.w;
        Ars[ak+4][arow]=ar1.x;Ars[ak+5][arow]=ar1.y;Ars[ak+6][arow]=ar1.z;Ars[ak+7][arow]=ar1.w;
        Ais[ak+0][arow]=ai0.x;Ais[ak+1][arow]=ai0.y;Ais[ak+2][arow]=ai0.z;Ais[ak+3][arow]=ai0.w;
        Ais[ak+4][arow]=ai1.x;Ais[ak+5][arow]=ai1.y;Ais[ak+6][arow]=ai1.z;Ais[ak+7][arow]=ai1.w;
        if(isB1){*(float4*)&B1s[bkr][bn]=bb0;*(float4*)&B1s[bkr][bn+4]=bb1;}
        else    {*(float4*)&B0s[bkr][bn]=bb0;*(float4*)&B0s[bkr][bn+4]=bb1;}
        __syncthreads();
        if(k0+16<Dsz){
            ar0=*(const float4*)(g_ar+(size_t)(m0+arow)*Dsz+k0+16+ak);
            ar1=*(const float4*)(g_ar+(size_t)(m0+arow)*Dsz+k0+16+ak+4);
            ai0=*(const float4*)(g_ai+(size_t)(m0+arow)*Dsz+k0+16+ak);
            ai1=*(const float4*)(g_ai+(size_t)(m0+arow)*Dsz+k0+16+ak+4);
            bb0=*(const float4*)(ws+(size_t)(k0+16+bkr)*Dsz+n0+bn);
            bb1=*(const float4*)(ws+(size_t)(k0+16+bkr)*Dsz+n0+bn+4);
        }
#pragma unroll
        for(int kk=0;kk<16;kk++){
            float4 a0=*(float4*)&Ars[kk][ty*8],a1=*(float4*)&Ars[kk][ty*8+4];
            float4 c0=*(float4*)&Ais[kk][ty*8],c1=*(float4*)&Ais[kk][ty*8+4];
            float4 b0=*(float4*)&B0s[kk][tx*4],b1=*(float4*)&B1s[kk][tx*4];
            float ar8[8]={a0.x,a0.y,a0.z,a0.w,a1.x,a1.y,a1.z,a1.w};
            float ai8[8]={c0.x,c0.y,c0.z,c0.w,c1.x,c1.y,c1.z,c1.w};
            float bw0[4]={b0.x,b0.y,b0.z,b0.w};
            float bw1[4]={b1.x,b1.y,b1.z,b1.w};
#pragma unroll
            for(int i=0;i<8;i++)
#pragma unroll
                for(int j=0;j<4;j++){
                    accR[i][j]+=ar8[i]*bw0[j]-ai8[i]*bw1[j];
                    accI[i][j]+=ai8[i]*bw0[j]+ar8[i]*bw1[j];
                }
        }
    }
    float bR[4],bI[4];
#pragma unroll
    for(int j=0;j<4;j++){int n=n0+tx*4+j;bR[j]=ob[n]-ob[Dsz+n];bI[j]=ob[n]+ob[Dsz+n];}
#pragma unroll
    for(int i=0;i<8;i++){
        size_t g=(size_t)(m0+ty*8+i)*Dsz+n0+tx*4;
        *(float4*)(g_pr+g)=make_float4(accR[i][0]+bR[0],accR[i][1]+bR[1],accR[i][2]+bR[2],accR[i][3]+bR[3]);
        *(float4*)(g_pi+g)=make_float4(accI[i][0]+bI[0],accI[i][1]+bI[1],accI[i][2]+bI[2],accI[i][3]+bI[3]);
    }
}

// ---------- VQ distance GEMM + first-argmin ----------
__global__ __launch_bounds__(256) void dist_kernel(const float* __restrict__ cb) {
    __shared__ float As[16][128], Bs[16][128];
    __shared__ float2 sRed[128][16];
    const int m0=blockIdx.x*128;
    const int tid=threadIdx.x, ty=tid>>4, tx=tid&15;
    const int arow=tid>>1, ak=(tid&1)*8;
    float acc[8][8];
#pragma unroll
    for(int i=0;i<8;i++)
#pragma unroll
        for(int j=0;j<8;j++) acc[i][j]=0.f;
    float4 aa0=*(const float4*)(g_pr+(size_t)(m0+arow)*Dsz+ak);
    float4 aa1=*(const float4*)(g_pr+(size_t)(m0+arow)*Dsz+ak+4);
    float4 cc0=*(const float4*)(cb+(size_t)arow*Dsz+ak);
    float4 cc1=*(const float4*)(cb+(size_t)arow*Dsz+ak+4);
    for(int k0=0;k0<Dsz;k0+=16){
        __syncthreads();
        As[ak+0][arow]=aa0.x;As[ak+1][arow]=aa0.y;As[ak+2][arow]=aa0.z;As[ak+3][arow]=aa0.w;
        As[ak+4][arow]=aa1.x;As[ak+5][arow]=aa1.y;As[ak+6][arow]=aa1.z;As[ak+7][arow]=aa1.w;
        Bs[ak+0][arow]=cc0.x;Bs[ak+1][arow]=cc0.y;Bs[ak+2][arow]=cc0.z;Bs[ak+3][arow]=cc0.w;
        Bs[ak+4][arow]=cc1.x;Bs[ak+5][arow]=cc1.y;Bs[ak+6][arow]=cc1.z;Bs[ak+7][arow]=cc1.w;
        __syncthreads();
        if(k0+16<Dsz){
            aa0=*(const float4*)(g_pr+(size_t)(m0+arow)*Dsz+k0+16+ak);
            aa1=*(const float4*)(g_pr+(size_t)(m0+arow)*Dsz+k0+16+ak+4);
            cc0=*(const float4*)(cb+(size_t)arow*Dsz+k0+16+ak);
            cc1=*(const float4*)(cb+(size_t)arow*Dsz+k0+16+ak+4);
        }
#pragma unroll
        for(int kk=0;kk<16;kk++){
            float4 a0=*(float4*)&As[kk][ty*8],a1=*(float4*)&As[kk][ty*8+4];
            float4 b0=*(float4*)&Bs[kk][tx*8],b1=*(float4*)&Bs[kk][tx*8+4];
            float a[8]={a0.x,a0.y,a0.z,a0.w,a1.x,a1.y,a1.z,a1.w};
            float b[8]={b0.x,b0.y,b0.z,b0.w,b1.x,b1.y,b1.z,b1.w};
#pragma unroll
            for(int i=0;i<8;i++)
#pragma unroll
                for(int j=0;j<8;j++) acc[i][j]+=a[i]*b[j];
        }
    }
#pragma unroll
    for(int i=0;i<8;i++){
        float bd=1e30f; int bi=0;
#pragma unroll
        for(int j=0;j<8;j++){
            int n=tx*8+j;
            float d=g_cn2[n]-2.f*acc[i][j];
            if(d<bd){bd=d;bi=n;}
        }
        sRed[ty*8+i][tx]=make_float2(bd,__int_as_float(bi));
    }
    __syncthreads();
    if(tid<128){
        float bd=1e30f; int bi=0;
#pragma unroll
        for(int t=0;t<16;t++){
            float2 e=sRed[tid][t];
            if(e.x<bd){bd=e.x;bi=__float_as_int(e.y);}
        }
        g_idx[m0+tid]=bi;
    }
}

// ---------- VQ loss ----------
__global__ void loss_kernel(const float* __restrict__ cb) {
    __shared__ float sw[4];
    int m=blockIdx.x, tid=threadIdx.x;
    const float4 f=((const float4*)(g_pr+(size_t)m*Dsz))[tid];
    const float4 c=((const float4*)(cb+(size_t)g_idx[m]*Dsz))[tid];
    float dx=c.x-f.x,dy=c.y-f.y,dz=c.z-f.z,dw=c.w-f.w;
    float v=dx*dx+dy*dy+dz*dz+dw*dw;
#pragma unroll
    for(int o=16;o;o>>=1) v+=__shfl_xor_sync(0xffffffffu,v,o);
    if((tid&31)==0) sw[tid>>5]=v;
    __syncthreads();
    if(tid==0) atomicAdd(&g_loss,(double)(sw[0]+sw[1]+sw[2]+sw[3]));
}

// ---------- gated stack scan ----------
__global__ __launch_bounds__(256) void scan_kernel(const float* __restrict__ cb) {
    __shared__ int sIdx[256]; __shared__ float sP[256],sO[256];
    const int b=blockIdx.x>>6, dg=blockIdx.x&63;
    const int warp=threadIdx.x>>5, lane=threadIdx.x&31;
    const int d=dg*8+warp;
    float st=0.f;
    for(int t0=0;t0<Lsz;t0+=256){
        __syncthreads();
        int ix=g_idx[b*Lsz+t0+threadIdx.x];
        sIdx[threadIdx.x]=ix; sP[threadIdx.x]=g_gp[ix]; sO[threadIdx.x]=g_go[ix];
        __syncthreads();
        for(int tt=0;tt<256;tt++){
            float val=cb[(size_t)sIdx[tt]*Dsz+d];
            float p=sP[tt],o=sO[tt];
            float sh=__shfl_down_sync(0xffffffffu,st,1);
            if(lane==31) sh=val;
            st=((1.f-p)*st+p*sh)*(1.f-o);
            if(lane==31) g_stk[((size_t)b*Lsz+t0+tt)*Dsz+d]=st;
        }
    }
}

// ---------- final ----------
__device__ __forceinline__ float blkRed(float v, float* s) {
#pragma unroll
    for(int o=16;o;o>>=1) v+=__shfl_xor_sync(0xffffffffu,v,o);
    if((threadIdx.x&31)==0) s[threadIdx.x>>5]=v;
    __syncthreads();
    v=s[0]+s[1]+s[2]+s[3];
    __syncthreads();
    return v;
}

__global__ void final_kernel(const float* __restrict__ cb,
                             const float* __restrict__ lng,
                             const float* __restrict__ lnb,
                             const float* __restrict__ mb,
                             float* __restrict__ out, long out_size) {
    __shared__ float sw[4];
    const int m=blockIdx.x, tid=threadIdx.x;
    const float* pr=g_pr+(size_t)m*Dsz;
    const float4 c4=((const float4*)(cb+(size_t)g_idx[m]*Dsz))[tid];
    const float4 f4=((const float4*)pr)[tid];
    const float4 s4=((const float4*)(g_stk+(size_t)m*Dsz))[tid];
    const float4 i4=((const float4*)(g_pi+(size_t)m*Dsz))[tid];
    float cr[4],ci[4];
    cr[0]=(f4.x+(c4.x-f4.x))+s4.x; cr[1]=(f4.y+(c4.y-f4.y))+s4.y;
    cr[2]=(f4.z+(c4.z-f4.z))+s4.z; cr[3]=(f4.w+(c4.w-f4.w))+s4.w;
    ci[0]=i4.x;ci[1]=i4.y;ci[2]=i4.z;ci[3]=i4.w;
    float sr=cr[0]+cr[1]+cr[2]+cr[3], si=ci[0]+ci[1]+ci[2]+ci[3];
    float mur=blkRed(sr,sw)*(1.f/Dsz);
    float mui=blkRed(si,sw)*(1.f/Dsz);
    float vr=0.f,vi=0.f;
#pragma unroll
    for(int k=0;k<4;k++){float a=cr[k]-mur,b=ci[k]-mui;vr+=a*a;vi+=b*b;}
    float varr=blkRed(vr,sw)*(1.f/Dsz);
    float vari=blkRed(vi,sw)*(1.f/Dsz);
    float rr=rsqrtf(varr+1e-5f), ri=rsqrtf(vari+1e-5f);
#pragma unroll
    for(int k=0;k<4;k++){
        int d=tid*4+k;
        float nr=(cr[k]-mur)*rr*lng[d]+lnb[d];
        float ni=(ci[k]-mui)*ri*lng[Dsz+d]+lnb[Dsz+d];
        float mag=sqrtf(nr*nr+ni*ni);
        float sc=fmaxf(mag+mb[d],0.f)/(mag+1e-6f);
        out[(size_t)m*Dsz+d]=nr*sc;
        out[OUTHALF+(size_t)m*Dsz+d]=ni*sc;
    }
    if(m==0&&tid==0)
        out[out_size-1]=(float)(1.25*g_loss/(double)((size_t)Msz*Dsz));
}

extern "C" void kernel_launch(void* const* d_in, const int* in_sizes, int n_in,
                              void* d_out, int out_size) {
    const int*   tokens=(const int*)  d_in[0];
    const float* embed =(const float*)d_in[2];
    const float* q_w=(const float*)d_in[3],  *q_b=(const float*)d_in[4];
    const float* k_w=(const float*)d_in[5],  *k_b=(const float*)d_in[6];
    const float* v_w=(const float*)d_in[7],  *v_b=(const float*)d_in[8];
    const float* o_w=(const float*)d_in[9],  *o_b=(const float*)d_in[10];
    const float* cb =(const float*)d_in[11];
    const float* gw =(const float*)d_in[12], *gb=(const float*)d_in[13];
    const float* lng=(const float*)d_in[14], *lnb=(const float*)d_in[15];
    const float* mb =(const float*)d_in[16];
    float* out=(float*)d_out;

    static bool attr_set=false;
    if(!attr_set){
        cudaFuncSetAttribute(attn_kernel,cudaFuncAttributeMaxDynamicSharedMemorySize,ATTN_SMEM);
        attr_set=true;
    }
    prep_kernel<<<1,128>>>(cb,gw,gb);
    gather_kernel<<<Msz,128>>>(tokens,embed);
    proj_kernel<<<dim3(4,64,6),256>>>(q_w,q_b,k_w,k_b,v_w,v_b);
    attn_kernel<<<dim3(8,64),512,ATTN_SMEM>>>();
    oproj_kernel<<<dim3(8,64),256>>>(o_w,o_b);
    dist_kernel<<<64,256>>>(cb);
    loss_kernel<<<Msz,128>>>(cb);
    scan_kernel<<<512,256>>>(cb);
    final_kernel<<<Msz,128>>>(cb,lng,lnb,mb,out,(long)out_size);
}

// round 6
// speedup vs baseline: 1.7619x; 1.6473x over previous
#include <cuda_runtime.h>

#define Bsz 8
#define Lsz 1024
#define Dsz 512
#define HDsz 64
#define NCsz 128
#define Msz (Bsz*Lsz)
#define OUTHALF ((size_t)Msz*Dsz)
#define NEG_INF (-__int_as_float(0x7f800000))

__device__ float g_zr[Msz*Dsz];
__device__ float g_qr[Msz*Dsz], g_qi[Msz*Dsz];
__device__ float g_kr[Msz*Dsz], g_ki[Msz*Dsz];
__device__ float g_vr[Msz*Dsz], g_vi[Msz*Dsz];
__device__ float g_ar[Msz*Dsz], g_ai[Msz*Dsz];
__device__ float g_pr[Msz*Dsz], g_pi[Msz*Dsz];
__device__ int   g_idx[Msz];
__device__ float g_stk[Msz*Dsz];
__device__ float g_cn2[NCsz], g_gp[NCsz], g_go[NCsz];
__device__ double g_loss;

// ---------- tf32 mma helpers ----------
__device__ __forceinline__ unsigned f2tf(float v){
    unsigned r; asm("cvt.rna.tf32.f32 %0, %1;" : "=r"(r) : "f"(v)); return r;
}
__device__ __forceinline__ void mma_tf32(float* c, const unsigned* a, const unsigned* b){
    asm volatile("mma.sync.aligned.m16n8k8.row.col.f32.tf32.tf32.f32 "
        "{%0,%1,%2,%3}, {%4,%5,%6,%7}, {%8,%9}, {%0,%1,%2,%3};"
        : "+f"(c[0]),"+f"(c[1]),"+f"(c[2]),"+f"(c[3])
        : "r"(a[0]),"r"(a[1]),"r"(a[2]),"r"(a[3]),"r"(b[0]),"r"(b[1]));
}

// ---------- prep ----------
__global__ void prep_kernel(const float* __restrict__ cb,
                            const float* __restrict__ gw,
                            const float* __restrict__ gb) {
    int j = threadIdx.x;
    if (j == 0) g_loss = 0.0;
    if (j < NCsz) {
        float s2 = 0.f, d0 = 0.f, d1 = 0.f;
        for (int d = 0; d < Dsz; d++) {
            float c = cb[j*Dsz + d];
            s2 += c*c; d0 += c*gw[d*2+0]; d1 += c*gw[d*2+1];
        }
        g_cn2[j] = s2;
        g_gp[j] = 1.f/(1.f+expf(-(d0+gb[0])));
        g_go[j] = 1.f/(1.f+expf(-(d1+gb[1])));
    }
}

// ---------- embedding gather ----------
__global__ void gather_kernel(const int* __restrict__ tokens,
                              const float* __restrict__ embed) {
    int m = blockIdx.x;
    const float4* src = (const float4*)(embed + (size_t)tokens[m]*Dsz);
    ((float4*)(g_zr + (size_t)m*Dsz))[threadIdx.x] = src[threadIdx.x];
}

// ---------- tf32 projection GEMM: 128x128 block, 8 warps (64x32 warp tile) ----------
__global__ __launch_bounds__(256) void proj_kernel(
        const float* __restrict__ qw, const float* __restrict__ qb,
        const float* __restrict__ kw, const float* __restrict__ kb,
        const float* __restrict__ vw, const float* __restrict__ vb) {
    __shared__ unsigned As[128][36];
    __shared__ unsigned Bs[32][132];
    const int z = blockIdx.z, pair = z>>1, im = z&1;
    const float* W; const float* bias; float* C;
    if (pair==0){W=qw;bias=qb;C=im?g_qi:g_qr;}
    else if (pair==1){W=kw;bias=kb;C=im?g_ki:g_kr;}
    else {W=vw;bias=vb;C=im?g_vi:g_vr;}
    W += (size_t)im*Dsz*Dsz;
    const float sgn = im?1.f:-1.f;
    const int m0=blockIdx.y*128, n0=blockIdx.x*128;
    const int tid=threadIdx.x, warp=tid>>5, lane=tid&31;
    const int wm=warp>>2, wn=warp&3, grp=lane>>2, tg=lane&3;
    const int arow=tid>>3, ac4=(tid&7)*4;      // A loader: +32 rows per u
    const int brow=tid>>5, bc4=(tid&31)*4;     // B loader: +8 rows per u
    float acc[4][4][4];
#pragma unroll
    for(int i=0;i<4;i++)
#pragma unroll
        for(int j=0;j<4;j++)
#pragma unroll
            for(int k=0;k<4;k++) acc[i][j][k]=0.f;
    float4 pa[4], pb[4];
#pragma unroll
    for(int u=0;u<4;u++){
        pa[u]=*(const float4*)(g_zr+(size_t)(m0+arow+u*32)*Dsz+ac4);
        pb[u]=*(const float4*)(W+(size_t)(brow+u*8)*Dsz+n0+bc4);
    }
    for(int k0=0;k0<Dsz;k0+=32){
        __syncthreads();
#pragma unroll
        for(int u=0;u<4;u++){
            int r=arow+u*32;
            As[r][ac4+0]=f2tf(pa[u].x);As[r][ac4+1]=f2tf(pa[u].y);
            As[r][ac4+2]=f2tf(pa[u].z);As[r][ac4+3]=f2tf(pa[u].w);
            int rb=brow+u*8;
            Bs[rb][bc4+0]=f2tf(pb[u].x);Bs[rb][bc4+1]=f2tf(pb[u].y);
            Bs[rb][bc4+2]=f2tf(pb[u].z);Bs[rb][bc4+3]=f2tf(pb[u].w);
        }
        __syncthreads();
        if(k0+32<Dsz){
#pragma unroll
            for(int u=0;u<4;u++){
                pa[u]=*(const float4*)(g_zr+(size_t)(m0+arow+u*32)*Dsz+k0+32+ac4);
                pb[u]=*(const float4*)(W+(size_t)(k0+32+brow+u*8)*Dsz+n0+bc4);
            }
        }
#pragma unroll
        for(int k8=0;k8<4;k8++){
            const int kb=k8*8;
            unsigned af[4][4], bf[4][2];
#pragma unroll
            for(int mt=0;mt<4;mt++){
                int r=wm*64+mt*16+grp;
                af[mt][0]=As[r][kb+tg];   af[mt][1]=As[r+8][kb+tg];
                af[mt][2]=As[r][kb+tg+4]; af[mt][3]=As[r+8][kb+tg+4];
            }
#pragma unroll
            for(int nt=0;nt<4;nt++){
                int cix=wn*32+nt*8+grp;
                bf[nt][0]=Bs[kb+tg][cix]; bf[nt][1]=Bs[kb+tg+4][cix];
            }
#pragma unroll
            for(int mt=0;mt<4;mt++)
#pragma unroll
                for(int nt=0;nt<4;nt++) mma_tf32(acc[mt][nt],af[mt],bf[nt]);
        }
    }
#pragma unroll
    for(int mt=0;mt<4;mt++){
#pragma unroll
        for(int nt=0;nt<4;nt++){
            int r=m0+wm*64+mt*16+grp;
            int cix=n0+wn*32+nt*8+2*tg;
            float b0=bias[cix]+sgn*bias[Dsz+cix];
            float b1=bias[cix+1]+sgn*bias[Dsz+cix+1];
            *(float2*)(C+(size_t)r*Dsz+cix)    =make_float2(acc[mt][nt][0]+b0,acc[mt][nt][1]+b1);
            *(float2*)(C+(size_t)(r+8)*Dsz+cix)=make_float2(acc[mt][nt][2]+b0,acc[mt][nt][3]+b1);
        }
    }
}

// ---------- tf32 fused complex O-projection: [ar|ai](8192x1024) @ B'(1024x1024) ----------
__global__ __launch_bounds__(256) void oproj_kernel(const float* __restrict__ ow,
                                                    const float* __restrict__ ob) {
    __shared__ unsigned As[128][36];
    __shared__ unsigned Bs[32][132];
    const float* w0=ow; const float* w1=ow+(size_t)Dsz*Dsz;
    const int m0=blockIdx.y*128, n0=blockIdx.x*128;
    const bool isI = (n0>=Dsz);          // output region (block-uniform)
    const int nloc = isI ? n0-Dsz : n0;  // column offset inside w
    const int tid=threadIdx.x, warp=tid>>5, lane=tid&31;
    const int wm=warp>>2, wn=warp&3, grp=lane>>2, tg=lane&3;
    const int arow=tid>>3, ac4=(tid&7)*4;
    const int brow=tid>>5, bc4=(tid&31)*4;
    float acc[4][4][4];
#pragma unroll
    for(int i=0;i<4;i++)
#pragma unroll
        for(int j=0;j<4;j++)
#pragma unroll
            for(int k=0;k<4;k++) acc[i][j][k]=0.f;
    float4 pa[4], pb[4];
    // k0=0 chunk: A from g_ar, B: isI? w1 : w0, sign +
#pragma unroll
    for(int u=0;u<4;u++){
        pa[u]=*(const float4*)(g_ar+(size_t)(m0+arow+u*32)*Dsz+ac4);
        const float* wsrc = isI ? w1 : w0;
        pb[u]=*(const float4*)(wsrc+(size_t)(brow+u*8)*Dsz+nloc+bc4);
    }
    for(int k0=0;k0<2*Dsz;k0+=32){
        __syncthreads();
        const bool khi_cur = (k0>=Dsz);
        // sign applies to B when (R region && k>=512): B' = -w1
        const float bsgn_cur = (!isI && khi_cur) ? -1.f : 1.f;
#pragma unroll
        for(int u=0;u<4;u++){
            int r=arow+u*32;
            As[r][ac4+0]=f2tf(pa[u].x);As[r][ac4+1]=f2tf(pa[u].y);
            As[r][ac4+2]=f2tf(pa[u].z);As[r][ac4+3]=f2tf(pa[u].w);
            int rb=brow+u*8;
            Bs[rb][bc4+0]=f2tf(bsgn_cur*pb[u].x);Bs[rb][bc4+1]=f2tf(bsgn_cur*pb[u].y);
            Bs[rb][bc4+2]=f2tf(bsgn_cur*pb[u].z);Bs[rb][bc4+3]=f2tf(bsgn_cur*pb[u].w);
        }
        __syncthreads();
        if(k0+32<2*Dsz){
            const int kn=k0+32;
            const bool khi = (kn>=Dsz);
            const float* asrc = khi ? g_ai : g_ar;
            const int akk = khi ? kn-Dsz : kn;
            // B' source: R region: k<512→w0, k>=512→w1(negated later). I region: k<512→w1, k>=512→w0.
            const float* wsrc = isI ? (khi ? w0 : w1) : (khi ? w1 : w0);
            const int bkk = khi ? kn-Dsz : kn;
#pragma unroll
            for(int u=0;u<4;u++){
                pa[u]=*(const float4*)(asrc+(size_t)(m0+arow+u*32)*Dsz+akk+ac4);
                pb[u]=*(const float4*)(wsrc+(size_t)(bkk+brow+u*8)*Dsz+nloc+bc4);
            }
        }
#pragma unroll
        for(int k8=0;k8<4;k8++){
            const int kb=k8*8;
            unsigned af[4][4], bf[4][2];
#pragma unroll
            for(int mt=0;mt<4;mt++){
                int r=wm*64+mt*16+grp;
                af[mt][0]=As[r][kb+tg];   af[mt][1]=As[r+8][kb+tg];
                af[mt][2]=As[r][kb+tg+4]; af[mt][3]=As[r+8][kb+tg+4];
            }
#pragma unroll
            for(int nt=0;nt<4;nt++){
                int cix=wn*32+nt*8+grp;
                bf[nt][0]=Bs[kb+tg][cix]; bf[nt][1]=Bs[kb+tg+4][cix];
            }
#pragma unroll
            for(int mt=0;mt<4;mt++)
#pragma unroll
                for(int nt=0;nt<4;nt++) mma_tf32(acc[mt][nt],af[mt],bf[nt]);
        }
    }
    float* Cdst = isI ? g_pi : g_pr;
    const float s2 = isI ? 1.f : -1.f;
#pragma unroll
    for(int mt=0;mt<4;mt++){
#pragma unroll
        for(int nt=0;nt<4;nt++){
            int r=m0+wm*64+mt*16+grp;
            int cl=wn*32+nt*8+2*tg;          // local col inside 128 block
            int cg=nloc+cl;                  // col inside D
            float b0=ob[cg]+s2*ob[Dsz+cg];
            float b1=ob[cg+1]+s2*ob[Dsz+cg+1];
            *(float2*)(Cdst+(size_t)r*Dsz+cg)    =make_float2(acc[mt][nt][0]+b0,acc[mt][nt][1]+b1);
            *(float2*)(Cdst+(size_t)(r+8)*Dsz+cg)=make_float2(acc[mt][nt][2]+b0,acc[mt][nt][3]+b1);
        }
    }
}

// ---------- flash attention (fp32, 128x64 Q-tile, 512 threads) ----------
#define AP 68
#define ATTN_SMEM ((2*128 + 4*64 + 128) * AP * 4)
__global__ __launch_bounds__(512) void attn_kernel() {
    extern __shared__ float sm[];
    float* sQr=sm;             float* sQi=sQr+128*AP;
    float* sKr=sQi+128*AP;     float* sKi=sKr+64*AP;
    float* sVr=sKi+64*AP;      float* sVi=sVr+64*AP;
    float* sP =sVi+64*AP;
    const int bh=blockIdx.y, b=bh>>3, h=bh&7;
    const int i0=blockIdx.x*128;
    const int tid=threadIdx.x, ty=tid>>4, tx=tid&15;
    const size_t base=(size_t)b*Lsz*Dsz + h*HDsz;
#pragma unroll
    for(int u=0;u<4;u++){
        int li=tid+u*512, r=li>>4, c4=(li&15)*4;
        size_t g=base+(size_t)(i0+r)*Dsz+c4;
        *(float4*)&sQr[r*AP+c4]=*(const float4*)(g_qr+g);
        *(float4*)&sQi[r*AP+c4]=*(const float4*)(g_qi+g);
    }
    float m_run[4],l_run[4],accr[4][4],acci[4][4];
#pragma unroll
    for(int i=0;i<4;i++){m_run[i]=NEG_INF;l_run[i]=0.f;
#pragma unroll
        for(int j=0;j<4;j++){accr[i][j]=0.f;acci[i][j]=0.f;}}
    const int ntile = 2*blockIdx.x + 2;
    for(int jt=0;jt<ntile;jt++){
        const int s0=jt*64;
        __syncthreads();
#pragma unroll
        for(int u=0;u<2;u++){
            int li=tid+u*512, r=li>>4, c4=(li&15)*4;
            size_t g=base+(size_t)(s0+r)*Dsz+c4;
            float4 a=*(const float4*)(g_kr+g);
            float4 c=*(const float4*)(g_ki+g);
            sKr[(c4+0)*AP+r]=a.x;sKr[(c4+1)*AP+r]=a.y;sKr[(c4+2)*AP+r]=a.z;sKr[(c4+3)*AP+r]=a.w;
            sKi[(c4+0)*AP+r]=c.x;sKi[(c4+1)*AP+r]=c.y;sKi[(c4+2)*AP+r]=c.z;sKi[(c4+3)*AP+r]=c.w;
            *(float4*)&sVr[r*AP+c4]=*(const float4*)(g_vr+g);
            *(float4*)&sVi[r*AP+c4]=*(const float4*)(g_vi+g);
        }
        __syncthreads();
        float s_[4][4];
#pragma unroll
        for(int i=0;i<4;i++)
#pragma unroll
            for(int j=0;j<4;j++) s_[i][j]=0.f;
#pragma unroll
        for(int k4=0;k4<16;k4++){
            float qrv[4][4],qiv[4][4];
#pragma unroll
            for(int i=0;i<4;i++){
                float4 t=*(float4*)&sQr[(4*ty+i)*AP+4*k4];
                qrv[i][0]=t.x;qrv[i][1]=t.y;qrv[i][2]=t.z;qrv[i][3]=t.w;
                float4 u=*(float4*)&sQi[(4*ty+i)*AP+4*k4];
                qiv[i][0]=u.x;qiv[i][1]=u.y;qiv[i][2]=u.z;qiv[i][3]=u.w;
            }
#pragma unroll
            for(int kk=0;kk<4;kk++){
                float4 kr4=*(float4*)&sKr[(4*k4+kk)*AP+4*tx];
                float4 ki4=*(float4*)&sKi[(4*k4+kk)*AP+4*tx];
#pragma unroll
                for(int i=0;i<4;i++){
                    s_[i][0]+=qrv[i][kk]*kr4.x+qiv[i][kk]*ki4.x;
                    s_[i][1]+=qrv[i][kk]*kr4.y+qiv[i][kk]*ki4.y;
                    s_[i][2]+=qrv[i][kk]*kr4.z+qiv[i][kk]*ki4.z;
                    s_[i][3]+=qrv[i][kk]*kr4.w+qiv[i][kk]*ki4.w;
                }
            }
        }
        const bool diag=(jt>=2*(int)blockIdx.x);
#pragma unroll
        for(int i=0;i<4;i++)
#pragma unroll
            for(int j=0;j<4;j++){
                s_[i][j]*=0.125f;
                if(diag && (s0+4*tx+j > i0+4*ty+i)) s_[i][j]=NEG_INF;
            }
        float p_[4][4];
#pragma unroll
        for(int i=0;i<4;i++){
            float mx=fmaxf(fmaxf(s_[i][0],s_[i][1]),fmaxf(s_[i][2],s_[i][3]));
#pragma unroll
            for(int off=8;off;off>>=1) mx=fmaxf(mx,__shfl_xor_sync(0xffffffffu,mx,off));
            float mnew=fmaxf(m_run[i],mx);
            float alpha=__expf(m_run[i]-mnew);
            m_run[i]=mnew;
            float rs=0.f;
#pragma unroll
            for(int j=0;j<4;j++){p_[i][j]=__expf(s_[i][j]-mnew);rs+=p_[i][j];}
#pragma unroll
            for(int off=8;off;off>>=1) rs+=__shfl_xor_sync(0xffffffffu,rs,off);
            l_run[i]=l_run[i]*alpha+rs;
#pragma unroll
            for(int j=0;j<4;j++){accr[i][j]*=alpha;acci[i][j]*=alpha;}
        }
#pragma unroll
        for(int i=0;i<4;i++)
            *(float4*)&sP[(4*ty+i)*AP+4*tx]=make_float4(p_[i][0],p_[i][1],p_[i][2],p_[i][3]);
        __syncthreads();
#pragma unroll
        for(int c4=0;c4<16;c4++){
            float pp[4][4];
#pragma unroll
            for(int i=0;i<4;i++){
                float4 t=*(float4*)&sP[(4*ty+i)*AP+4*c4];
                pp[i][0]=t.x;pp[i][1]=t.y;pp[i][2]=t.z;pp[i][3]=t.w;
            }
#pragma unroll
            for(int cc=0;cc<4;cc++){
                float4 vr4=*(float4*)&sVr[(4*c4+cc)*AP+4*tx];
                float4 vi4=*(float4*)&sVi[(4*c4+cc)*AP+4*tx];
#pragma unroll
                for(int i=0;i<4;i++){
                    accr[i][0]+=pp[i][cc]*vr4.x;accr[i][1]+=pp[i][cc]*vr4.y;
                    accr[i][2]+=pp[i][cc]*vr4.z;accr[i][3]+=pp[i][cc]*vr4.w;
                    acci[i][0]+=pp[i][cc]*vi4.x;acci[i][1]+=pp[i][cc]*vi4.y;
                    acci[i][2]+=pp[i][cc]*vi4.z;acci[i][3]+=pp[i][cc]*vi4.w;
                }
            }
        }
    }
#pragma unroll
    for(int i=0;i<4;i++){
        float inv=1.f/l_run[i];
        size_t g=base+(size_t)(i0+4*ty+i)*Dsz+4*tx;
        *(float4*)(g_ar+g)=make_float4(accr[i][0]*inv,accr[i][1]*inv,accr[i][2]*inv,accr[i][3]*inv);
        *(float4*)(g_ai+g)=make_float4(acci[i][0]*inv,acci[i][1]*inv,acci[i][2]*inv,acci[i][3]*inv);
    }
}

// ---------- VQ distance GEMM + first-argmin (fp32) ----------
__global__ __launch_bounds__(256) void dist_kernel(const float* __restrict__ cb) {
    __shared__ float As[16][128], Bs[16][128];
    __shared__ float2 sRed[128][16];
    const int m0=blockIdx.x*128;
    const int tid=threadIdx.x, ty=tid>>4, tx=tid&15;
    const int arow=tid>>1, ak=(tid&1)*8;
    float acc[8][8];
#pragma unroll
    for(int i=0;i<8;i++)
#pragma unroll
        for(int j=0;j<8;j++) acc[i][j]=0.f;
    float4 aa0=*(const float4*)(g_pr+(size_t)(m0+arow)*Dsz+ak);
    float4 aa1=*(const float4*)(g_pr+(size_t)(m0+arow)*Dsz+ak+4);
    float4 cc0=*(const float4*)(cb+(size_t)arow*Dsz+ak);
    float4 cc1=*(const float4*)(cb+(size_t)arow*Dsz+ak+4);
    for(int k0=0;k0<Dsz;k0+=16){
        __syncthreads();
        As[ak+0][arow]=aa0.x;As[ak+1][arow]=aa0.y;As[ak+2][arow]=aa0.z;As[ak+3][arow]=aa0.w;
        As[ak+4][arow]=aa1.x;As[ak+5][arow]=aa1.y;As[ak+6][arow]=aa1.z;As[ak+7][arow]=aa1.w;
        Bs[ak+0][arow]=cc0.x;Bs[ak+1][arow]=cc0.y;Bs[ak+2][arow]=cc0.z;Bs[ak+3][arow]=cc0.w;
        Bs[ak+4][arow]=cc1.x;Bs[ak+5][arow]=cc1.y;Bs[ak+6][arow]=cc1.z;Bs[ak+7][arow]=cc1.w;
        __syncthreads();
        if(k0+16<Dsz){
            aa0=*(const float4*)(g_pr+(size_t)(m0+arow)*Dsz+k0+16+ak);
            aa1=*(const float4*)(g_pr+(size_t)(m0+arow)*Dsz+k0+16+ak+4);
            cc0=*(const float4*)(cb+(size_t)arow*Dsz+k0+16+ak);
            cc1=*(const float4*)(cb+(size_t)arow*Dsz+k0+16+ak+4);
        }
#pragma unroll
        for(int kk=0;kk<16;kk++){
            float4 a0=*(float4*)&As[kk][ty*8],a1=*(float4*)&As[kk][ty*8+4];
            float4 b0=*(float4*)&Bs[kk][tx*8],b1=*(float4*)&Bs[kk][tx*8+4];
            float a[8]={a0.x,a0.y,a0.z,a0.w,a1.x,a1.y,a1.z,a1.w};
            float b[8]={b0.x,b0.y,b0.z,b0.w,b1.x,b1.y,b1.z,b1.w};
#pragma unroll
            for(int i=0;i<8;i++)
#pragma unroll
                for(int j=0;j<8;j++) acc[i][j]+=a[i]*b[j];
        }
    }
#pragma unroll
    for(int i=0;i<8;i++){
        float bd=1e30f; int bi=0;
#pragma unroll
        for(int j=0;j<8;j++){
            int n=tx*8+j;
            float d=g_cn2[n]-2.f*acc[i][j];
            if(d<bd){bd=d;bi=n;}
        }
        sRed[ty*8+i][tx]=make_float2(bd,__int_as_float(bi));
    }
    __syncthreads();
    if(tid<128){
        float bd=1e30f; int bi=0;
#pragma unroll
        for(int t=0;t<16;t++){
            float2 e=sRed[tid][t];
            if(e.x<bd){bd=e.x;bi=__float_as_int(e.y);}
        }
        g_idx[m0+tid]=bi;
    }
}

// ---------- VQ loss ----------
__global__ void loss_kernel(const float* __restrict__ cb) {
    __shared__ float sw[4];
    int m=blockIdx.x, tid=threadIdx.x;
    const float4 f=((const float4*)(g_pr+(size_t)m*Dsz))[tid];
    const float4 c=((const float4*)(cb+(size_t)g_idx[m]*Dsz))[tid];
    float dx=c.x-f.x,dy=c.y-f.y,dz=c.z-f.z,dw=c.w-f.w;
    float v=dx*dx+dy*dy+dz*dz+dw*dw;
#pragma unroll
    for(int o=16;o;o>>=1) v+=__shfl_xor_sync(0xffffffffu,v,o);
    if((tid&31)==0) sw[tid>>5]=v;
    __syncthreads();
    if(tid==0) atomicAdd(&g_loss,(double)(sw[0]+sw[1]+sw[2]+sw[3]));
}

// ---------- gated stack scan ----------
__global__ __launch_bounds__(256) void scan_kernel(const float* __restrict__ cb) {
    __shared__ int sIdx[256]; __shared__ float sP[256],sO[256];
    const int b=blockIdx.x>>6, dg=blockIdx.x&63;
    const int warp=threadIdx.x>>5, lane=threadIdx.x&31;
    const int d=dg*8+warp;
    float st=0.f;
    for(int t0=0;t0<Lsz;t0+=256){
        __syncthreads();
        int ix=g_idx[b*Lsz+t0+threadIdx.x];
        sIdx[threadIdx.x]=ix; sP[threadIdx.x]=g_gp[ix]; sO[threadIdx.x]=g_go[ix];
        __syncthreads();
        for(int tt=0;tt<256;tt++){
            float val=cb[(size_t)sIdx[tt]*Dsz+d];
            float p=sP[tt],o=sO[tt];
            float sh=__shfl_down_sync(0xffffffffu,st,1);
            if(lane==31) sh=val;
            st=((1.f-p)*st+p*sh)*(1.f-o);
            if(lane==31) g_stk[((size_t)b*Lsz+t0+tt)*Dsz+d]=st;
        }
    }
}

// ---------- final ----------
__device__ __forceinline__ float blkRed(float v, float* s) {
#pragma unroll
    for(int o=16;o;o>>=1) v+=__shfl_xor_sync(0xffffffffu,v,o);
    if((threadIdx.x&31)==0) s[threadIdx.x>>5]=v;
    __syncthreads();
    v=s[0]+s[1]+s[2]+s[3];
    __syncthreads();
    return v;
}

__global__ void final_kernel(const float* __restrict__ cb,
                             const float* __restrict__ lng,
                             const float* __restrict__ lnb,
                             const float* __restrict__ mb,
                             float* __restrict__ out, long out_size) {
    __shared__ float sw[4];
    const int m=blockIdx.x, tid=threadIdx.x;
    const float* pr=g_pr+(size_t)m*Dsz;
    const float4 c4=((const float4*)(cb+(size_t)g_idx[m]*Dsz))[tid];
    const float4 f4=((const float4*)pr)[tid];
    const float4 s4=((const float4*)(g_stk+(size_t)m*Dsz))[tid];
    const float4 i4=((const float4*)(g_pi+(size_t)m*Dsz))[tid];
    float cr[4],ci[4];
    cr[0]=(f4.x+(c4.x-f4.x))+s4.x; cr[1]=(f4.y+(c4.y-f4.y))+s4.y;
    cr[2]=(f4.z+(c4.z-f4.z))+s4.z; cr[3]=(f4.w+(c4.w-f4.w))+s4.w;
    ci[0]=i4.x;ci[1]=i4.y;ci[2]=i4.z;ci[3]=i4.w;
    float sr=cr[0]+cr[1]+cr[2]+cr[3], si=ci[0]+ci[1]+ci[2]+ci[3];
    float mur=blkRed(sr,sw)*(1.f/Dsz);
    float mui=blkRed(si,sw)*(1.f/Dsz);
    float vr=0.f,vi=0.f;
#pragma unroll
    for(int k=0;k<4;k++){float a=cr[k]-mur,b=ci[k]-mui;vr+=a*a;vi+=b*b;}
    float varr=blkRed(vr,sw)*(1.f/Dsz);
    float vari=blkRed(vi,sw)*(1.f/Dsz);
    float rr=rsqrtf(varr+1e-5f), ri=rsqrtf(vari+1e-5f);
#pragma unroll
    for(int k=0;k<4;k++){
        int d=tid*4+k;
        float nr=(cr[k]-mur)*rr*lng[d]+lnb[d];
        float ni=(ci[k]-mui)*ri*lng[Dsz+d]+lnb[Dsz+d];
        float mag=sqrtf(nr*nr+ni*ni);
        float sc=fmaxf(mag+mb[d],0.f)/(mag+1e-6f);
        out[(size_t)m*Dsz+d]=nr*sc;
        out[OUTHALF+(size_t)m*Dsz+d]=ni*sc;
    }
    if(m==0&&tid==0)
        out[out_size-1]=(float)(1.25*g_loss/(double)((size_t)Msz*Dsz));
}

extern "C" void kernel_launch(void* const* d_in, const int* in_sizes, int n_in,
                              void* d_out, int out_size) {
    const int*   tokens=(const int*)  d_in[0];
    const float* embed =(const float*)d_in[2];
    const float* q_w=(const float*)d_in[3],  *q_b=(const float*)d_in[4];
    const float* k_w=(const float*)d_in[5],  *k_b=(const float*)d_in[6];
    const float* v_w=(const float*)d_in[7],  *v_b=(const float*)d_in[8];
    const float* o_w=(const float*)d_in[9],  *o_b=(const float*)d_in[10];
    const float* cb =(const float*)d_in[11];
    const float* gw =(const float*)d_in[12], *gb=(const float*)d_in[13];
    const float* lng=(const float*)d_in[14], *lnb=(const float*)d_in[15];
    const float* mb =(const float*)d_in[16];
    float* out=(float*)d_out;

    static bool attr_set=false;
    if(!attr_set){
        cudaFuncSetAttribute(attn_kernel,cudaFuncAttributeMaxDynamicSharedMemorySize,ATTN_SMEM);
        attr_set=true;
    }
    prep_kernel<<<1,128>>>(cb,gw,gb);
    gather_kernel<<<Msz,128>>>(tokens,embed);
    proj_kernel<<<dim3(4,64,6),256>>>(q_w,q_b,k_w,k_b,v_w,v_b);
    attn_kernel<<<dim3(8,64),512,ATTN_SMEM>>>();
    oproj_kernel<<<dim3(8,64),256>>>(o_w,o_b);
    dist_kernel<<<64,256>>>(cb);
    loss_kernel<<<Msz,128>>>(cb);
    scan_kernel<<<512,256>>>(cb);
    final_kernel<<<Msz,128>>>(cb,lng,lnb,mb,out,(long)out_size);
}

// round 7
// speedup vs baseline: 2.4361x; 1.3826x over previous
#include <cuda_runtime.h>

#define Bsz 8
#define Lsz 1024
#define Dsz 512
#define HDsz 64
#define NCsz 128
#define Msz (Bsz*Lsz)
#define OUTHALF ((size_t)Msz*Dsz)
#define NEG_INF (-__int_as_float(0x7f800000))

__device__ float g_zr[Msz*Dsz];
__device__ float g_qr[Msz*Dsz], g_qi[Msz*Dsz];
__device__ float g_kr[Msz*Dsz], g_ki[Msz*Dsz];
__device__ float g_vr[Msz*Dsz], g_vi[Msz*Dsz];
__device__ float g_ar[Msz*Dsz], g_ai[Msz*Dsz];
__device__ float g_pr[Msz*Dsz], g_pi[Msz*Dsz];
__device__ int   g_idx[Msz];
__device__ float g_stk[Msz*Dsz];
__device__ float g_cn2[NCsz], g_gp[NCsz], g_go[NCsz];
__device__ double g_loss;

// ---------- tf32 mma helpers ----------
__device__ __forceinline__ unsigned f2tf(float v){
    unsigned r; asm("cvt.rna.tf32.f32 %0, %1;" : "=r"(r) : "f"(v)); return r;
}
__device__ __forceinline__ void mma_tf32(float* c, const unsigned* a, const unsigned* b){
    asm volatile("mma.sync.aligned.m16n8k8.row.col.f32.tf32.tf32.f32 "
        "{%0,%1,%2,%3}, {%4,%5,%6,%7}, {%8,%9}, {%0,%1,%2,%3};"
        : "+f"(c[0]),"+f"(c[1]),"+f"(c[2]),"+f"(c[3])
        : "r"(a[0]),"r"(a[1]),"r"(a[2]),"r"(a[3]),"r"(b[0]),"r"(b[1]));
}

// ---------- prep ----------
__global__ void prep_kernel(const float* __restrict__ cb,
                            const float* __restrict__ gw,
                            const float* __restrict__ gb) {
    int j = threadIdx.x;
    if (j == 0) g_loss = 0.0;
    if (j < NCsz) {
        float s2 = 0.f, d0 = 0.f, d1 = 0.f;
        for (int d = 0; d < Dsz; d++) {
            float c = cb[j*Dsz + d];
            s2 += c*c; d0 += c*gw[d*2+0]; d1 += c*gw[d*2+1];
        }
        g_cn2[j] = s2;
        g_gp[j] = 1.f/(1.f+expf(-(d0+gb[0])));
        g_go[j] = 1.f/(1.f+expf(-(d1+gb[1])));
    }
}

// ---------- embedding gather ----------
__global__ void gather_kernel(const int* __restrict__ tokens,
                              const float* __restrict__ embed) {
    int m = blockIdx.x;
    const float4* src = (const float4*)(embed + (size_t)tokens[m]*Dsz);
    ((float4*)(g_zr + (size_t)m*Dsz))[threadIdx.x] = src[threadIdx.x];
}

// ---------- tf32 projection GEMM ----------
__global__ __launch_bounds__(256) void proj_kernel(
        const float* __restrict__ qw, const float* __restrict__ qb,
        const float* __restrict__ kw, const float* __restrict__ kb,
        const float* __restrict__ vw, const float* __restrict__ vb) {
    __shared__ unsigned As[128][36];
    __shared__ unsigned Bs[32][132];
    const int z = blockIdx.z, pair = z>>1, im = z&1;
    const float* W; const float* bias; float* C;
    if (pair==0){W=qw;bias=qb;C=im?g_qi:g_qr;}
    else if (pair==1){W=kw;bias=kb;C=im?g_ki:g_kr;}
    else {W=vw;bias=vb;C=im?g_vi:g_vr;}
    W += (size_t)im*Dsz*Dsz;
    const float sgn = im?1.f:-1.f;
    const int m0=blockIdx.y*128, n0=blockIdx.x*128;
    const int tid=threadIdx.x, warp=tid>>5, lane=tid&31;
    const int wm=warp>>2, wn=warp&3, grp=lane>>2, tg=lane&3;
    const int arow=tid>>3, ac4=(tid&7)*4;
    const int brow=tid>>5, bc4=(tid&31)*4;
    float acc[4][4][4];
#pragma unroll
    for(int i=0;i<4;i++)
#pragma unroll
        for(int j=0;j<4;j++)
#pragma unroll
            for(int k=0;k<4;k++) acc[i][j][k]=0.f;
    float4 pa[4], pb[4];
#pragma unroll
    for(int u=0;u<4;u++){
        pa[u]=*(const float4*)(g_zr+(size_t)(m0+arow+u*32)*Dsz+ac4);
        pb[u]=*(const float4*)(W+(size_t)(brow+u*8)*Dsz+n0+bc4);
    }
    for(int k0=0;k0<Dsz;k0+=32){
        __syncthreads();
#pragma unroll
        for(int u=0;u<4;u++){
            int r=arow+u*32;
            As[r][ac4+0]=f2tf(pa[u].x);As[r][ac4+1]=f2tf(pa[u].y);
            As[r][ac4+2]=f2tf(pa[u].z);As[r][ac4+3]=f2tf(pa[u].w);
            int rb=brow+u*8;
            Bs[rb][bc4+0]=f2tf(pb[u].x);Bs[rb][bc4+1]=f2tf(pb[u].y);
            Bs[rb][bc4+2]=f2tf(pb[u].z);Bs[rb][bc4+3]=f2tf(pb[u].w);
        }
        __syncthreads();
        if(k0+32<Dsz){
#pragma unroll
            for(int u=0;u<4;u++){
                pa[u]=*(const float4*)(g_zr+(size_t)(m0+arow+u*32)*Dsz+k0+32+ac4);
                pb[u]=*(const float4*)(W+(size_t)(k0+32+brow+u*8)*Dsz+n0+bc4);
            }
        }
#pragma unroll
        for(int k8=0;k8<4;k8++){
            const int kb=k8*8;
            unsigned af[4][4], bf[4][2];
#pragma unroll
            for(int mt=0;mt<4;mt++){
                int r=wm*64+mt*16+grp;
                af[mt][0]=As[r][kb+tg];   af[mt][1]=As[r+8][kb+tg];
                af[mt][2]=As[r][kb+tg+4]; af[mt][3]=As[r+8][kb+tg+4];
            }
#pragma unroll
            for(int nt=0;nt<4;nt++){
                int cix=wn*32+nt*8+grp;
                bf[nt][0]=Bs[kb+tg][cix]; bf[nt][1]=Bs[kb+tg+4][cix];
            }
#pragma unroll
            for(int mt=0;mt<4;mt++)
#pragma unroll
                for(int nt=0;nt<4;nt++) mma_tf32(acc[mt][nt],af[mt],bf[nt]);
        }
    }
#pragma unroll
    for(int mt=0;mt<4;mt++){
#pragma unroll
        for(int nt=0;nt<4;nt++){
            int r=m0+wm*64+mt*16+grp;
            int cix=n0+wn*32+nt*8+2*tg;
            float b0=bias[cix]+sgn*bias[Dsz+cix];
            float b1=bias[cix+1]+sgn*bias[Dsz+cix+1];
            *(float2*)(C+(size_t)r*Dsz+cix)    =make_float2(acc[mt][nt][0]+b0,acc[mt][nt][1]+b1);
            *(float2*)(C+(size_t)(r+8)*Dsz+cix)=make_float2(acc[mt][nt][2]+b0,acc[mt][nt][3]+b1);
        }
    }
}

// ---------- tf32 fused complex O-projection ----------
__global__ __launch_bounds__(256) void oproj_kernel(const float* __restrict__ ow,
                                                    const float* __restrict__ ob) {
    __shared__ unsigned As[128][36];
    __shared__ unsigned Bs[32][132];
    const float* w0=ow; const float* w1=ow+(size_t)Dsz*Dsz;
    const int m0=blockIdx.y*128, n0=blockIdx.x*128;
    const bool isI = (n0>=Dsz);
    const int nloc = isI ? n0-Dsz : n0;
    const int tid=threadIdx.x, warp=tid>>5, lane=tid&31;
    const int wm=warp>>2, wn=warp&3, grp=lane>>2, tg=lane&3;
    const int arow=tid>>3, ac4=(tid&7)*4;
    const int brow=tid>>5, bc4=(tid&31)*4;
    float acc[4][4][4];
#pragma unroll
    for(int i=0;i<4;i++)
#pragma unroll
        for(int j=0;j<4;j++)
#pragma unroll
            for(int k=0;k<4;k++) acc[i][j][k]=0.f;
    float4 pa[4], pb[4];
#pragma unroll
    for(int u=0;u<4;u++){
        pa[u]=*(const float4*)(g_ar+(size_t)(m0+arow+u*32)*Dsz+ac4);
        const float* wsrc = isI ? w1 : w0;
        pb[u]=*(const float4*)(wsrc+(size_t)(brow+u*8)*Dsz+nloc+bc4);
    }
    for(int k0=0;k0<2*Dsz;k0+=32){
        __syncthreads();
        const bool khi_cur = (k0>=Dsz);
        const float bsgn_cur = (!isI && khi_cur) ? -1.f : 1.f;
#pragma unroll
        for(int u=0;u<4;u++){
            int r=arow+u*32;
            As[r][ac4+0]=f2tf(pa[u].x);As[r][ac4+1]=f2tf(pa[u].y);
            As[r][ac4+2]=f2tf(pa[u].z);As[r][ac4+3]=f2tf(pa[u].w);
            int rb=brow+u*8;
            Bs[rb][bc4+0]=f2tf(bsgn_cur*pb[u].x);Bs[rb][bc4+1]=f2tf(bsgn_cur*pb[u].y);
            Bs[rb][bc4+2]=f2tf(bsgn_cur*pb[u].z);Bs[rb][bc4+3]=f2tf(bsgn_cur*pb[u].w);
        }
        __syncthreads();
        if(k0+32<2*Dsz){
            const int kn=k0+32;
            const bool khi = (kn>=Dsz);
            const float* asrc = khi ? g_ai : g_ar;
            const int akk = khi ? kn-Dsz : kn;
            const float* wsrc = isI ? (khi ? w0 : w1) : (khi ? w1 : w0);
            const int bkk = khi ? kn-Dsz : kn;
#pragma unroll
            for(int u=0;u<4;u++){
                pa[u]=*(const float4*)(asrc+(size_t)(m0+arow+u*32)*Dsz+akk+ac4);
                pb[u]=*(const float4*)(wsrc+(size_t)(bkk+brow+u*8)*Dsz+nloc+bc4);
            }
        }
#pragma unroll
        for(int k8=0;k8<4;k8++){
            const int kb=k8*8;
            unsigned af[4][4], bf[4][2];
#pragma unroll
            for(int mt=0;mt<4;mt++){
                int r=wm*64+mt*16+grp;
                af[mt][0]=As[r][kb+tg];   af[mt][1]=As[r+8][kb+tg];
                af[mt][2]=As[r][kb+tg+4]; af[mt][3]=As[r+8][kb+tg+4];
            }
#pragma unroll
            for(int nt=0;nt<4;nt++){
                int cix=wn*32+nt*8+grp;
                bf[nt][0]=Bs[kb+tg][cix]; bf[nt][1]=Bs[kb+tg+4][cix];
            }
#pragma unroll
            for(int mt=0;mt<4;mt++)
#pragma unroll
                for(int nt=0;nt<4;nt++) mma_tf32(acc[mt][nt],af[mt],bf[nt]);
        }
    }
    float* Cdst = isI ? g_pi : g_pr;
    const float s2 = isI ? 1.f : -1.f;
#pragma unroll
    for(int mt=0;mt<4;mt++){
#pragma unroll
        for(int nt=0;nt<4;nt++){
            int r=m0+wm*64+mt*16+grp;
            int cl=wn*32+nt*8+2*tg;
            int cg=nloc+cl;
            float b0=ob[cg]+s2*ob[Dsz+cg];
            float b1=ob[cg+1]+s2*ob[Dsz+cg+1];
            *(float2*)(Cdst+(size_t)r*Dsz+cg)    =make_float2(acc[mt][nt][0]+b0,acc[mt][nt][1]+b1);
            *(float2*)(Cdst+(size_t)(r+8)*Dsz+cg)=make_float2(acc[mt][nt][2]+b0,acc[mt][nt][3]+b1);
        }
    }
}

// ---------- tf32 flash attention: 128-row Q tile, 8 warps, warp = 16 rows x full 64 cols ----------
#define WAP 68
#define ATTN_SMEM (640*WAP*4)
__global__ __launch_bounds__(256) void attn_kernel() {
    extern __shared__ unsigned smu[];
    unsigned* sQr=smu;              // [128][WAP]  (row, d) tf32
    unsigned* sQi=sQr+128*WAP;
    unsigned* sKr=sQi+128*WAP;      // [64][WAP]   (d, j)  tf32
    unsigned* sKi=sKr+ 64*WAP;
    unsigned* sVr=sKi+ 64*WAP;      // [64][WAP]   (j, d)  tf32
    unsigned* sVi=sVr+ 64*WAP;
    unsigned* sP =sVi+ 64*WAP;      // [128][WAP]  (row, j) tf32
    const int bh=blockIdx.y, b=bh>>3, h=bh&7;
    const int bx=blockIdx.x, i0=bx*128;
    const int tid=threadIdx.x, warp=tid>>5, lane=tid&31;
    const int grp=lane>>2, tg=lane&3;
    const int wrow=warp*16;
    const size_t base=(size_t)b*Lsz*Dsz + h*HDsz;
#pragma unroll
    for(int u=0;u<8;u++){
        int li=tid+u*256, r=li>>4, c4=(li&15)*4;
        size_t g=base+(size_t)(i0+r)*Dsz+c4;
        float4 qr=*(const float4*)(g_qr+g), qi=*(const float4*)(g_qi+g);
        uint4 ua; ua.x=f2tf(qr.x);ua.y=f2tf(qr.y);ua.z=f2tf(qr.z);ua.w=f2tf(qr.w);
        uint4 ub; ub.x=f2tf(qi.x);ub.y=f2tf(qi.y);ub.z=f2tf(qi.z);ub.w=f2tf(qi.w);
        *(uint4*)&sQr[r*WAP+c4]=ua; *(uint4*)&sQi[r*WAP+c4]=ub;
    }
    float m_run[2]={NEG_INF,NEG_INF}, l_run[2]={0.f,0.f};
    float accR[8][4], accI[8][4];
#pragma unroll
    for(int nt=0;nt<8;nt++)
#pragma unroll
        for(int k=0;k<4;k++){accR[nt][k]=0.f;accI[nt][k]=0.f;}
    const int ntile=2*bx+2;
    for(int jt=0;jt<ntile;jt++){
        const int s0=jt*64;
        __syncthreads();
#pragma unroll
        for(int u=0;u<4;u++){
            int li=tid+u*256, r=li>>4, c4=(li&15)*4;
            size_t g=base+(size_t)(s0+r)*Dsz+c4;
            float4 kr=*(const float4*)(g_kr+g), ki=*(const float4*)(g_ki+g);
            float4 vr=*(const float4*)(g_vr+g), vi=*(const float4*)(g_vi+g);
            sKr[(c4+0)*WAP+r]=f2tf(kr.x);sKr[(c4+1)*WAP+r]=f2tf(kr.y);
            sKr[(c4+2)*WAP+r]=f2tf(kr.z);sKr[(c4+3)*WAP+r]=f2tf(kr.w);
            sKi[(c4+0)*WAP+r]=f2tf(ki.x);sKi[(c4+1)*WAP+r]=f2tf(ki.y);
            sKi[(c4+2)*WAP+r]=f2tf(ki.z);sKi[(c4+3)*WAP+r]=f2tf(ki.w);
            uint4 uv; uv.x=f2tf(vr.x);uv.y=f2tf(vr.y);uv.z=f2tf(vr.z);uv.w=f2tf(vr.w);
            uint4 uw; uw.x=f2tf(vi.x);uw.y=f2tf(vi.y);uw.z=f2tf(vi.z);uw.w=f2tf(vi.w);
            *(uint4*)&sVr[r*WAP+c4]=uv; *(uint4*)&sVi[r*WAP+c4]=uw;
        }
        __syncthreads();
        float s_[8][4];
#pragma unroll
        for(int nt=0;nt<8;nt++)
#pragma unroll
            for(int k=0;k<4;k++) s_[nt][k]=0.f;
#pragma unroll
        for(int kc=0;kc<8;kc++){
            const int kb=kc*8;
            unsigned aR[4],aI[4];
            aR[0]=sQr[(wrow+grp  )*WAP+kb+tg];   aR[1]=sQr[(wrow+grp+8)*WAP+kb+tg];
            aR[2]=sQr[(wrow+grp  )*WAP+kb+tg+4]; aR[3]=sQr[(wrow+grp+8)*WAP+kb+tg+4];
            aI[0]=sQi[(wrow+grp  )*WAP+kb+tg];   aI[1]=sQi[(wrow+grp+8)*WAP+kb+tg];
            aI[2]=sQi[(wrow+grp  )*WAP+kb+tg+4]; aI[3]=sQi[(wrow+grp+8)*WAP+kb+tg+4];
#pragma unroll
            for(int nt=0;nt<8;nt++){
                unsigned bR[2],bI[2];
                bR[0]=sKr[(kb+tg  )*WAP+nt*8+grp]; bR[1]=sKr[(kb+tg+4)*WAP+nt*8+grp];
                bI[0]=sKi[(kb+tg  )*WAP+nt*8+grp]; bI[1]=sKi[(kb+tg+4)*WAP+nt*8+grp];
                mma_tf32(s_[nt],aR,bR);
                mma_tf32(s_[nt],aI,bI);
            }
        }
        const bool diag=(jt>=2*bx);
        const int r0=i0+wrow+grp, r1=r0+8;
#pragma unroll
        for(int nt=0;nt<8;nt++){
            const int c0=s0+nt*8+2*tg, c1=c0+1;
            s_[nt][0]*=0.125f; s_[nt][1]*=0.125f; s_[nt][2]*=0.125f; s_[nt][3]*=0.125f;
            if(diag){
                if(c0>r0)s_[nt][0]=NEG_INF; if(c1>r0)s_[nt][1]=NEG_INF;
                if(c0>r1)s_[nt][2]=NEG_INF; if(c1>r1)s_[nt][3]=NEG_INF;
            }
        }
        float mx0=NEG_INF, mx1=NEG_INF;
#pragma unroll
        for(int nt=0;nt<8;nt++){
            mx0=fmaxf(mx0,fmaxf(s_[nt][0],s_[nt][1]));
            mx1=fmaxf(mx1,fmaxf(s_[nt][2],s_[nt][3]));
        }
        mx0=fmaxf(mx0,__shfl_xor_sync(0xffffffffu,mx0,1));
        mx0=fmaxf(mx0,__shfl_xor_sync(0xffffffffu,mx0,2));
        mx1=fmaxf(mx1,__shfl_xor_sync(0xffffffffu,mx1,1));
        mx1=fmaxf(mx1,__shfl_xor_sync(0xffffffffu,mx1,2));
        const float mn0=fmaxf(m_run[0],mx0), mn1=fmaxf(m_run[1],mx1);
        const float al0=__expf(m_run[0]-mn0), al1=__expf(m_run[1]-mn1);
        m_run[0]=mn0; m_run[1]=mn1;
        float rs0=0.f, rs1=0.f;
#pragma unroll
        for(int nt=0;nt<8;nt++){
            float p0=__expf(s_[nt][0]-mn0), p1=__expf(s_[nt][1]-mn0);
            float p2=__expf(s_[nt][2]-mn1), p3=__expf(s_[nt][3]-mn1);
            rs0+=p0+p1; rs1+=p2+p3;
            const int cl=nt*8+2*tg;
            sP[(wrow+grp  )*WAP+cl]=f2tf(p0); sP[(wrow+grp  )*WAP+cl+1]=f2tf(p1);
            sP[(wrow+grp+8)*WAP+cl]=f2tf(p2); sP[(wrow+grp+8)*WAP+cl+1]=f2tf(p3);
        }
        rs0+=__shfl_xor_sync(0xffffffffu,rs0,1); rs0+=__shfl_xor_sync(0xffffffffu,rs0,2);
        rs1+=__shfl_xor_sync(0xffffffffu,rs1,1); rs1+=__shfl_xor_sync(0xffffffffu,rs1,2);
        l_run[0]=l_run[0]*al0+rs0; l_run[1]=l_run[1]*al1+rs1;
#pragma unroll
        for(int nt=0;nt<8;nt++){
            accR[nt][0]*=al0; accR[nt][1]*=al0; accR[nt][2]*=al1; accR[nt][3]*=al1;
            accI[nt][0]*=al0; accI[nt][1]*=al0; accI[nt][2]*=al1; accI[nt][3]*=al1;
        }
        __syncwarp();
#pragma unroll
        for(int kc=0;kc<8;kc++){
            const int kb=kc*8;
            unsigned aP[4];
            aP[0]=sP[(wrow+grp  )*WAP+kb+tg];   aP[1]=sP[(wrow+grp+8)*WAP+kb+tg];
            aP[2]=sP[(wrow+grp  )*WAP+kb+tg+4]; aP[3]=sP[(wrow+grp+8)*WAP+kb+tg+4];
#pragma unroll
            for(int nt=0;nt<8;nt++){
                unsigned bR[2],bI[2];
                bR[0]=sVr[(kb+tg  )*WAP+nt*8+grp]; bR[1]=sVr[(kb+tg+4)*WAP+nt*8+grp];
                bI[0]=sVi[(kb+tg  )*WAP+nt*8+grp]; bI[1]=sVi[(kb+tg+4)*WAP+nt*8+grp];
                mma_tf32(accR[nt],aP,bR);
                mma_tf32(accI[nt],aP,bI);
            }
        }
        __syncwarp();
    }
    const float inv0=1.f/l_run[0], inv1=1.f/l_run[1];
#pragma unroll
    for(int nt=0;nt<8;nt++){
        const int d=nt*8+2*tg;
        size_t g0=base+(size_t)(i0+wrow+grp  )*Dsz+d;
        size_t g1=base+(size_t)(i0+wrow+grp+8)*Dsz+d;
        *(float2*)(g_ar+g0)=make_float2(accR[nt][0]*inv0,accR[nt][1]*inv0);
        *(float2*)(g_ar+g1)=make_float2(accR[nt][2]*inv1,accR[nt][3]*inv1);
        *(float2*)(g_ai+g0)=make_float2(accI[nt][0]*inv0,accI[nt][1]*inv0);
        *(float2*)(g_ai+g1)=make_float2(accI[nt][2]*inv1,accI[nt][3]*inv1);
    }
}

// ---------- VQ distance GEMM + first-argmin (fp32) ----------
__global__ __launch_bounds__(256) void dist_kernel(const float* __restrict__ cb) {
    __shared__ float As[16][128], Bs[16][128];
    __shared__ float2 sRed[128][16];
    const int m0=blockIdx.x*128;
    const int tid=threadIdx.x, ty=tid>>4, tx=tid&15;
    const int arow=tid>>1, ak=(tid&1)*8;
    float acc[8][8];
#pragma unroll
    for(int i=0;i<8;i++)
#pragma unroll
        for(int j=0;j<8;j++) acc[i][j]=0.f;
    float4 aa0=*(const float4*)(g_pr+(size_t)(m0+arow)*Dsz+ak);
    float4 aa1=*(const float4*)(g_pr+(size_t)(m0+arow)*Dsz+ak+4);
    float4 cc0=*(const float4*)(cb+(size_t)arow*Dsz+ak);
    float4 cc1=*(const float4*)(cb+(size_t)arow*Dsz+ak+4);
    for(int k0=0;k0<Dsz;k0+=16){
        __syncthreads();
        As[ak+0][arow]=aa0.x;As[ak+1][arow]=aa0.y;As[ak+2][arow]=aa0.z;As[ak+3][arow]=aa0.w;
        As[ak+4][arow]=aa1.x;As[ak+5][arow]=aa1.y;As[ak+6][arow]=aa1.z;As[ak+7][arow]=aa1.w;
        Bs[ak+0][arow]=cc0.x;Bs[ak+1][arow]=cc0.y;Bs[ak+2][arow]=cc0.z;Bs[ak+3][arow]=cc0.w;
        Bs[ak+4][arow]=cc1.x;Bs[ak+5][arow]=cc1.y;Bs[ak+6][arow]=cc1.z;Bs[ak+7][arow]=cc1.w;
        __syncthreads();
        if(k0+16<Dsz){
            aa0=*(const float4*)(g_pr+(size_t)(m0+arow)*Dsz+k0+16+ak);
            aa1=*(const float4*)(g_pr+(size_t)(m0+arow)*Dsz+k0+16+ak+4);
            cc0=*(const float4*)(cb+(size_t)arow*Dsz+k0+16+ak);
            cc1=*(const float4*)(cb+(size_t)arow*Dsz+k0+16+ak+4);
        }
#pragma unroll
        for(int kk=0;kk<16;kk++){
            float4 a0=*(float4*)&As[kk][ty*8],a1=*(float4*)&As[kk][ty*8+4];
            float4 b0=*(float4*)&Bs[kk][tx*8],b1=*(float4*)&Bs[kk][tx*8+4];
            float a[8]={a0.x,a0.y,a0.z,a0.w,a1.x,a1.y,a1.z,a1.w};
            float b[8]={b0.x,b0.y,b0.z,b0.w,b1.x,b1.y,b1.z,b1.w};
#pragma unroll
            for(int i=0;i<8;i++)
#pragma unroll
                for(int j=0;j<8;j++) acc[i][j]+=a[i]*b[j];
        }
    }
#pragma unroll
    for(int i=0;i<8;i++){
        float bd=1e30f; int bi=0;
#pragma unroll
        for(int j=0;j<8;j++){
            int n=tx*8+j;
            float d=g_cn2[n]-2.f*acc[i][j];
            if(d<bd){bd=d;bi=n;}
        }
        sRed[ty*8+i][tx]=make_float2(bd,__int_as_float(bi));
    }
    __syncthreads();
    if(tid<128){
        float bd=1e30f; int bi=0;
#pragma unroll
        for(int t=0;t<16;t++){
            float2 e=sRed[tid][t];
            if(e.x<bd){bd=e.x;bi=__float_as_int(e.y);}
        }
        g_idx[m0+tid]=bi;
    }
}

// ---------- VQ loss ----------
__global__ void loss_kernel(const float* __restrict__ cb) {
    __shared__ float sw[4];
    int m=blockIdx.x, tid=threadIdx.x;
    const float4 f=((const float4*)(g_pr+(size_t)m*Dsz))[tid];
    const float4 c=((const float4*)(cb+(size_t)g_idx[m]*Dsz))[tid];
    float dx=c.x-f.x,dy=c.y-f.y,dz=c.z-f.z,dw=c.w-f.w;
    float v=dx*dx+dy*dy+dz*dz+dw*dw;
#pragma unroll
    for(int o=16;o;o>>=1) v+=__shfl_xor_sync(0xffffffffu,v,o);
    if((tid&31)==0) sw[tid>>5]=v;
    __syncthreads();
    if(tid==0) atomicAdd(&g_loss,(double)(sw[0]+sw[1]+sw[2]+sw[3]));
}

// ---------- gated stack scan ----------
__global__ __launch_bounds__(256) void scan_kernel(const float* __restrict__ cb) {
    __shared__ int sIdx[256]; __shared__ float sP[256],sO[256];
    const int b=blockIdx.x>>6, dg=blockIdx.x&63;
    const int warp=threadIdx.x>>5, lane=threadIdx.x&31;
    const int d=dg*8+warp;
    float st=0.f;
    for(int t0=0;t0<Lsz;t0+=256){
        __syncthreads();
        int ix=g_idx[b*Lsz+t0+threadIdx.x];
        sIdx[threadIdx.x]=ix; sP[threadIdx.x]=g_gp[ix]; sO[threadIdx.x]=g_go[ix];
        __syncthreads();
        for(int tt=0;tt<256;tt++){
            float val=cb[(size_t)sIdx[tt]*Dsz+d];
            float p=sP[tt],o=sO[tt];
            float sh=__shfl_down_sync(0xffffffffu,st,1);
            if(lane==31) sh=val;
            st=((1.f-p)*st+p*sh)*(1.f-o);
            if(lane==31) g_stk[((size_t)b*Lsz+t0+tt)*Dsz+d]=st;
        }
    }
}

// ---------- final ----------
__device__ __forceinline__ float blkRed(float v, float* s) {
#pragma unroll
    for(int o=16;o;o>>=1) v+=__shfl_xor_sync(0xffffffffu,v,o);
    if((threadIdx.x&31)==0) s[threadIdx.x>>5]=v;
    __syncthreads();
    v=s[0]+s[1]+s[2]+s[3];
    __syncthreads();
    return v;
}

__global__ void final_kernel(const float* __restrict__ cb,
                             const float* __restrict__ lng,
                             const float* __restrict__ lnb,
                             const float* __restrict__ mb,
                             float* __restrict__ out, long out_size) {
    __shared__ float sw[4];
    const int m=blockIdx.x, tid=threadIdx.x;
    const float* pr=g_pr+(size_t)m*Dsz;
    const float4 c4=((const float4*)(cb+(size_t)g_idx[m]*Dsz))[tid];
    const float4 f4=((const float4*)pr)[tid];
    const float4 s4=((const float4*)(g_stk+(size_t)m*Dsz))[tid];
    const float4 i4=((const float4*)(g_pi+(size_t)m*Dsz))[tid];
    float cr[4],ci[4];
    cr[0]=(f4.x+(c4.x-f4.x))+s4.x; cr[1]=(f4.y+(c4.y-f4.y))+s4.y;
    cr[2]=(f4.z+(c4.z-f4.z))+s4.z; cr[3]=(f4.w+(c4.w-f4.w))+s4.w;
    ci[0]=i4.x;ci[1]=i4.y;ci[2]=i4.z;ci[3]=i4.w;
    float sr=cr[0]+cr[1]+cr[2]+cr[3], si=ci[0]+ci[1]+ci[2]+ci[3];
    float mur=blkRed(sr,sw)*(1.f/Dsz);
    float mui=blkRed(si,sw)*(1.f/Dsz);
    float vr=0.f,vi=0.f;
#pragma unroll
    for(int k=0;k<4;k++){float a=cr[k]-mur,b=ci[k]-mui;vr+=a*a;vi+=b*b;}
    float varr=blkRed(vr,sw)*(1.f/Dsz);
    float vari=blkRed(vi,sw)*(1.f/Dsz);
    float rr=rsqrtf(varr+1e-5f), ri=rsqrtf(vari+1e-5f);
#pragma unroll
    for(int k=0;k<4;k++){
        int d=tid*4+k;
        float nr=(cr[k]-mur)*rr*lng[d]+lnb[d];
        float ni=(ci[k]-mui)*ri*lng[Dsz+d]+lnb[Dsz+d];
        float mag=sqrtf(nr*nr+ni*ni);
        float sc=fmaxf(mag+mb[d],0.f)/(mag+1e-6f);
        out[(size_t)m*Dsz+d]=nr*sc;
        out[OUTHALF+(size_t)m*Dsz+d]=ni*sc;
    }
    if(m==0&&tid==0)
        out[out_size-1]=(float)(1.25*g_loss/(double)((size_t)Msz*Dsz));
}

extern "C" void kernel_launch(void* const* d_in, const int* in_sizes, int n_in,
                              void* d_out, int out_size) {
    const int*   tokens=(const int*)  d_in[0];
    const float* embed =(const float*)d_in[2];
    const float* q_w=(const float*)d_in[3],  *q_b=(const float*)d_in[4];
    const float* k_w=(const float*)d_in[5],  *k_b=(const float*)d_in[6];
    const float* v_w=(const float*)d_in[7],  *v_b=(const float*)d_in[8];
    const float* o_w=(const float*)d_in[9],  *o_b=(const float*)d_in[10];
    const float* cb =(const float*)d_in[11];
    const float* gw =(const float*)d_in[12], *gb=(const float*)d_in[13];
    const float* lng=(const float*)d_in[14], *lnb=(const float*)d_in[15];
    const float* mb =(const float*)d_in[16];
    float* out=(float*)d_out;

    static bool attr_set=false;
    if(!attr_set){
        cudaFuncSetAttribute(attn_kernel,cudaFuncAttributeMaxDynamicSharedMemorySize,ATTN_SMEM);
        attr_set=true;
    }
    prep_kernel<<<1,128>>>(cb,gw,gb);
    gather_kernel<<<Msz,128>>>(tokens,embed);
    proj_kernel<<<dim3(4,64,6),256>>>(q_w,q_b,k_w,k_b,v_w,v_b);
    attn_kernel<<<dim3(8,64),256,ATTN_SMEM>>>();
    oproj_kernel<<<dim3(8,64),256>>>(o_w,o_b);
    dist_kernel<<<64,256>>>(cb);
    loss_kernel<<<Msz,128>>>(cb);
    scan_kernel<<<512,256>>>(cb);
    final_kernel<<<Msz,128>>>(cb,lng,lnb,mb,out,(long)out_size);
}

// round 8
// speedup vs baseline: 2.6850x; 1.1022x over previous
#include <cuda_runtime.h>

#define Bsz 8
#define Lsz 1024
#define Dsz 512
#define HDsz 64
#define NCsz 128
#define Msz (Bsz*Lsz)
#define OUTHALF ((size_t)Msz*Dsz)
#define NEG_INF (-__int_as_float(0x7f800000))

__device__ float g_zr[Msz*Dsz];
__device__ float g_qr[Msz*Dsz], g_qi[Msz*Dsz];
__device__ float g_kr[Msz*Dsz], g_ki[Msz*Dsz];
__device__ float g_vr[Msz*Dsz], g_vi[Msz*Dsz];
__device__ float g_ar[Msz*Dsz], g_ai[Msz*Dsz];
__device__ float g_pr[Msz*Dsz], g_pi[Msz*Dsz];
__device__ int   g_idx[Msz];
__device__ float g_stk[Msz*Dsz];
__device__ float g_cn2[NCsz], g_gp[NCsz], g_go[NCsz];
__device__ double g_loss;

__device__ __forceinline__ void mma_tf32(float* c, const unsigned* a, const unsigned* b){
    asm volatile("mma.sync.aligned.m16n8k8.row.col.f32.tf32.tf32.f32 "
        "{%0,%1,%2,%3}, {%4,%5,%6,%7}, {%8,%9}, {%0,%1,%2,%3};"
        : "+f"(c[0]),"+f"(c[1]),"+f"(c[2]),"+f"(c[3])
        : "r"(a[0]),"r"(a[1]),"r"(a[2]),"r"(a[3]),"r"(b[0]),"r"(b[1]));
}
__device__ __forceinline__ unsigned su32(const void* p){
    return (unsigned)__cvta_generic_to_shared(p);
}
#define CPA16(dst,src) asm volatile("cp.async.cg.shared.global [%0], [%1], 16;" :: "r"(su32(dst)), "l"(src))
#define CPA_COMMIT()   asm volatile("cp.async.commit_group;" ::: "memory")
#define CPA_WAIT0()    asm volatile("cp.async.wait_group 0;" ::: "memory")

// ---------- prep ----------
__global__ void prep_kernel(const float* __restrict__ cb,
                            const float* __restrict__ gw,
                            const float* __restrict__ gb) {
    int j = threadIdx.x;
    if (j == 0) g_loss = 0.0;
    if (j < NCsz) {
        float s2 = 0.f, d0 = 0.f, d1 = 0.f;
        for (int d = 0; d < Dsz; d++) {
            float c = cb[j*Dsz + d];
            s2 += c*c; d0 += c*gw[d*2+0]; d1 += c*gw[d*2+1];
        }
        g_cn2[j] = s2;
        g_gp[j] = 1.f/(1.f+expf(-(d0+gb[0])));
        g_go[j] = 1.f/(1.f+expf(-(d1+gb[1])));
    }
}

// ---------- embedding gather ----------
__global__ void gather_kernel(const int* __restrict__ tokens,
                              const float* __restrict__ embed) {
    int m = blockIdx.x;
    const float4* src = (const float4*)(embed + (size_t)tokens[m]*Dsz);
    ((float4*)(g_zr + (size_t)m*Dsz))[threadIdx.x] = src[threadIdx.x];
}

// ---------- tf32 projection GEMM ----------
__global__ __launch_bounds__(256) void proj_kernel(
        const float* __restrict__ qw, const float* __restrict__ qb,
        const float* __restrict__ kw, const float* __restrict__ kb,
        const float* __restrict__ vw, const float* __restrict__ vb) {
    __shared__ unsigned As[128][36];
    __shared__ unsigned Bs[32][132];
    const int z = blockIdx.z, pair = z>>1, im = z&1;
    const float* W; const float* bias; float* C;
    if (pair==0){W=qw;bias=qb;C=im?g_qi:g_qr;}
    else if (pair==1){W=kw;bias=kb;C=im?g_ki:g_kr;}
    else {W=vw;bias=vb;C=im?g_vi:g_vr;}
    W += (size_t)im*Dsz*Dsz;
    const float sgn = im?1.f:-1.f;
    const int m0=blockIdx.y*128, n0=blockIdx.x*128;
    const int tid=threadIdx.x, warp=tid>>5, lane=tid&31;
    const int wm=warp>>2, wn=warp&3, grp=lane>>2, tg=lane&3;
    const int arow=tid>>3, ac4=(tid&7)*4;
    const int brow=tid>>5, bc4=(tid&31)*4;
    float acc[4][4][4];
#pragma unroll
    for(int i=0;i<4;i++)
#pragma unroll
        for(int j=0;j<4;j++)
#pragma unroll
            for(int k=0;k<4;k++) acc[i][j][k]=0.f;
    float4 pa[4], pb[4];
#pragma unroll
    for(int u=0;u<4;u++){
        pa[u]=*(const float4*)(g_zr+(size_t)(m0+arow+u*32)*Dsz+ac4);
        pb[u]=*(const float4*)(W+(size_t)(brow+u*8)*Dsz+n0+bc4);
    }
    for(int k0=0;k0<Dsz;k0+=32){
        __syncthreads();
#pragma unroll
        for(int u=0;u<4;u++){
            *(uint4*)&As[arow+u*32][ac4]=*reinterpret_cast<uint4*>(&pa[u]);
            *(uint4*)&Bs[brow+u*8][bc4]=*reinterpret_cast<uint4*>(&pb[u]);
        }
        __syncthreads();
        if(k0+32<Dsz){
#pragma unroll
            for(int u=0;u<4;u++){
                pa[u]=*(const float4*)(g_zr+(size_t)(m0+arow+u*32)*Dsz+k0+32+ac4);
                pb[u]=*(const float4*)(W+(size_t)(k0+32+brow+u*8)*Dsz+n0+bc4);
            }
        }
#pragma unroll
        for(int k8=0;k8<4;k8++){
            const int kb=k8*8;
            unsigned af[4][4], bf[4][2];
#pragma unroll
            for(int mt=0;mt<4;mt++){
                int r=wm*64+mt*16+grp;
                af[mt][0]=As[r][kb+tg];   af[mt][1]=As[r+8][kb+tg];
                af[mt][2]=As[r][kb+tg+4]; af[mt][3]=As[r+8][kb+tg+4];
            }
#pragma unroll
            for(int nt=0;nt<4;nt++){
                int cix=wn*32+nt*8+grp;
                bf[nt][0]=Bs[kb+tg][cix]; bf[nt][1]=Bs[kb+tg+4][cix];
            }
#pragma unroll
            for(int mt=0;mt<4;mt++)
#pragma unroll
                for(int nt=0;nt<4;nt++) mma_tf32(acc[mt][nt],af[mt],bf[nt]);
        }
    }
#pragma unroll
    for(int mt=0;mt<4;mt++){
#pragma unroll
        for(int nt=0;nt<4;nt++){
            int r=m0+wm*64+mt*16+grp;
            int cix=n0+wn*32+nt*8+2*tg;
            float b0=bias[cix]+sgn*bias[Dsz+cix];
            float b1=bias[cix+1]+sgn*bias[Dsz+cix+1];
            *(float2*)(C+(size_t)r*Dsz+cix)    =make_float2(acc[mt][nt][0]+b0,acc[mt][nt][1]+b1);
            *(float2*)(C+(size_t)(r+8)*Dsz+cix)=make_float2(acc[mt][nt][2]+b0,acc[mt][nt][3]+b1);
        }
    }
}

// ---------- tf32 fused complex O-projection ----------
__global__ __launch_bounds__(256) void oproj_kernel(const float* __restrict__ ow,
                                                    const float* __restrict__ ob) {
    __shared__ unsigned As[128][36];
    __shared__ unsigned Bs[32][132];
    const float* w0=ow; const float* w1=ow+(size_t)Dsz*Dsz;
    const int m0=blockIdx.y*128, n0=blockIdx.x*128;
    const bool isI = (n0>=Dsz);
    const int nloc = isI ? n0-Dsz : n0;
    const int tid=threadIdx.x, warp=tid>>5, lane=tid&31;
    const int wm=warp>>2, wn=warp&3, grp=lane>>2, tg=lane&3;
    const int arow=tid>>3, ac4=(tid&7)*4;
    const int brow=tid>>5, bc4=(tid&31)*4;
    float acc[4][4][4];
#pragma unroll
    for(int i=0;i<4;i++)
#pragma unroll
        for(int j=0;j<4;j++)
#pragma unroll
            for(int k=0;k<4;k++) acc[i][j][k]=0.f;
    float4 pa[4], pb[4];
#pragma unroll
    for(int u=0;u<4;u++){
        pa[u]=*(const float4*)(g_ar+(size_t)(m0+arow+u*32)*Dsz+ac4);
        const float* wsrc = isI ? w1 : w0;
        pb[u]=*(const float4*)(wsrc+(size_t)(brow+u*8)*Dsz+nloc+bc4);
    }
    for(int k0=0;k0<2*Dsz;k0+=32){
        __syncthreads();
        const bool khi_cur = (k0>=Dsz);
        const unsigned smask = (!isI && khi_cur) ? 0x80000000u : 0u;
#pragma unroll
        for(int u=0;u<4;u++){
            *(uint4*)&As[arow+u*32][ac4]=*reinterpret_cast<uint4*>(&pa[u]);
            uint4 ub=*reinterpret_cast<uint4*>(&pb[u]);
            ub.x^=smask; ub.y^=smask; ub.z^=smask; ub.w^=smask;
            *(uint4*)&Bs[brow+u*8][bc4]=ub;
        }
        __syncthreads();
        if(k0+32<2*Dsz){
            const int kn=k0+32;
            const bool khi = (kn>=Dsz);
            const float* asrc = khi ? g_ai : g_ar;
            const int akk = khi ? kn-Dsz : kn;
            const float* wsrc = isI ? (khi ? w0 : w1) : (khi ? w1 : w0);
            const int bkk = khi ? kn-Dsz : kn;
#pragma unroll
            for(int u=0;u<4;u++){
                pa[u]=*(const float4*)(asrc+(size_t)(m0+arow+u*32)*Dsz+akk+ac4);
                pb[u]=*(const float4*)(wsrc+(size_t)(bkk+brow+u*8)*Dsz+nloc+bc4);
            }
        }
#pragma unroll
        for(int k8=0;k8<4;k8++){
            const int kb=k8*8;
            unsigned af[4][4], bf[4][2];
#pragma unroll
            for(int mt=0;mt<4;mt++){
                int r=wm*64+mt*16+grp;
                af[mt][0]=As[r][kb+tg];   af[mt][1]=As[r+8][kb+tg];
                af[mt][2]=As[r][kb+tg+4]; af[mt][3]=As[r+8][kb+tg+4];
            }
#pragma unroll
            for(int nt=0;nt<4;nt++){
                int cix=wn*32+nt*8+grp;
                bf[nt][0]=Bs[kb+tg][cix]; bf[nt][1]=Bs[kb+tg+4][cix];
            }
#pragma unroll
            for(int mt=0;mt<4;mt++)
#pragma unroll
                for(int nt=0;nt<4;nt++) mma_tf32(acc[mt][nt],af[mt],bf[nt]);
        }
    }
    float* Cdst = isI ? g_pi : g_pr;
    const float s2 = isI ? 1.f : -1.f;
#pragma unroll
    for(int mt=0;mt<4;mt++){
#pragma unroll
        for(int nt=0;nt<4;nt++){
            int r=m0+wm*64+mt*16+grp;
            int cl=wn*32+nt*8+2*tg;
            int cg=nloc+cl;
            float b0=ob[cg]+s2*ob[Dsz+cg];
            float b1=ob[cg+1]+s2*ob[Dsz+cg+1];
            *(float2*)(Cdst+(size_t)r*Dsz+cg)    =make_float2(acc[mt][nt][0]+b0,acc[mt][nt][1]+b1);
            *(float2*)(Cdst+(size_t)(r+8)*Dsz+cg)=make_float2(acc[mt][nt][2]+b0,acc[mt][nt][3]+b1);
        }
    }
}

// ---------- tf32 flash attention: cp.async double-buffered K/V, shuffle-P ----------
#define WAP 68
#define KVSTRIDE (4*64*WAP)
#define ATTN_SMEM ((2*128*WAP + 2*KVSTRIDE)*4)
__global__ __launch_bounds__(256) void attn_kernel() {
    extern __shared__ float smf[];
    float* sQr=smf;
    float* sQi=sQr+128*WAP;
    float* sKV=sQi+128*WAP;
    const int bh=blockIdx.y, b=bh>>3, h=bh&7;
    const int bx=blockIdx.x, i0=bx*128;
    const int tid=threadIdx.x, warp=tid>>5, lane=tid&31;
    const int grp=lane>>2, tg=lane&3;
    const int wrow=warp*16;
    const size_t base=(size_t)b*Lsz*Dsz + h*HDsz;
    // Q: cp.async 2x128x64
#pragma unroll
    for(int u=0;u<8;u++){
        int li=tid+u*256, r=li>>4, c4=(li&15)*4;
        size_t g=base+(size_t)(i0+r)*Dsz+c4;
        CPA16(&sQr[r*WAP+c4], g_qr+g);
        CPA16(&sQi[r*WAP+c4], g_qi+g);
    }
    CPA_COMMIT();
    const int ntile=2*bx+2;
    // KV tile 0 -> stage 0
    {
        float* kr=sKV; float* ki=kr+64*WAP; float* vr=ki+64*WAP; float* vi=vr+64*WAP;
#pragma unroll
        for(int u=0;u<4;u++){
            int li=tid+u*256, r=li>>4, c4=(li&15)*4;
            size_t g=base+(size_t)r*Dsz+c4;
            CPA16(&kr[r*WAP+c4], g_kr+g); CPA16(&ki[r*WAP+c4], g_ki+g);
            CPA16(&vr[r*WAP+c4], g_vr+g); CPA16(&vi[r*WAP+c4], g_vi+g);
        }
        CPA_COMMIT();
    }
    float m_run[2]={NEG_INF,NEG_INF}, l_run[2]={0.f,0.f};
    float accR[8][4], accI[8][4];
#pragma unroll
    for(int nt=0;nt<8;nt++)
#pragma unroll
        for(int k=0;k<4;k++){accR[nt][k]=0.f;accI[nt][k]=0.f;}
    const int srcA=(lane&~3)|(tg>>1), srcB=srcA|2;
    const bool odd=tg&1;
    for(int jt=0;jt<ntile;jt++){
        CPA_WAIT0();
        __syncthreads();
        if(jt+1<ntile){
            const int s0n=(jt+1)*64, stn=(jt+1)&1;
            float* kr=sKV+stn*KVSTRIDE; float* ki=kr+64*WAP;
            float* vr=ki+64*WAP;        float* vi=vr+64*WAP;
#pragma unroll
            for(int u=0;u<4;u++){
                int li=tid+u*256, r=li>>4, c4=(li&15)*4;
                size_t g=base+(size_t)(s0n+r)*Dsz+c4;
                CPA16(&kr[r*WAP+c4], g_kr+g); CPA16(&ki[r*WAP+c4], g_ki+g);
                CPA16(&vr[r*WAP+c4], g_vr+g); CPA16(&vi[r*WAP+c4], g_vi+g);
            }
            CPA_COMMIT();
        }
        const int s0=jt*64;
        float* sKr=sKV+(jt&1)*KVSTRIDE; float* sKi=sKr+64*WAP;
        float* sVr=sKi+64*WAP;          float* sVi=sVr+64*WAP;
        float s_[8][4];
#pragma unroll
        for(int nt=0;nt<8;nt++)
#pragma unroll
            for(int k=0;k<4;k++) s_[nt][k]=0.f;
#pragma unroll
        for(int kc=0;kc<8;kc++){
            const int kb=kc*8;
            unsigned aR[4],aI[4];
            aR[0]=__float_as_uint(sQr[(wrow+grp  )*WAP+kb+tg]);
            aR[1]=__float_as_uint(sQr[(wrow+grp+8)*WAP+kb+tg]);
            aR[2]=__float_as_uint(sQr[(wrow+grp  )*WAP+kb+tg+4]);
            aR[3]=__float_as_uint(sQr[(wrow+grp+8)*WAP+kb+tg+4]);
            aI[0]=__float_as_uint(sQi[(wrow+grp  )*WAP+kb+tg]);
            aI[1]=__float_as_uint(sQi[(wrow+grp+8)*WAP+kb+tg]);
            aI[2]=__float_as_uint(sQi[(wrow+grp  )*WAP+kb+tg+4]);
            aI[3]=__float_as_uint(sQi[(wrow+grp+8)*WAP+kb+tg+4]);
#pragma unroll
            for(int nt=0;nt<8;nt++){
                unsigned bR[2],bI[2];
                bR[0]=__float_as_uint(sKr[(8*nt+grp)*WAP+kb+tg]);
                bR[1]=__float_as_uint(sKr[(8*nt+grp)*WAP+kb+tg+4]);
                bI[0]=__float_as_uint(sKi[(8*nt+grp)*WAP+kb+tg]);
                bI[1]=__float_as_uint(sKi[(8*nt+grp)*WAP+kb+tg+4]);
                mma_tf32(s_[nt],aR,bR);
                mma_tf32(s_[nt],aI,bI);
            }
        }
        const bool diag=(jt>=2*bx);
        const int r0=i0+wrow+grp, r1=r0+8;
#pragma unroll
        for(int nt=0;nt<8;nt++){
            const int c0=s0+nt*8+2*tg, c1=c0+1;
            s_[nt][0]*=0.125f; s_[nt][1]*=0.125f; s_[nt][2]*=0.125f; s_[nt][3]*=0.125f;
            if(diag){
                if(c0>r0)s_[nt][0]=NEG_INF; if(c1>r0)s_[nt][1]=NEG_INF;
                if(c0>r1)s_[nt][2]=NEG_INF; if(c1>r1)s_[nt][3]=NEG_INF;
            }
        }
        float mx0=NEG_INF, mx1=NEG_INF;
#pragma unroll
        for(int nt=0;nt<8;nt++){
            mx0=fmaxf(mx0,fmaxf(s_[nt][0],s_[nt][1]));
            mx1=fmaxf(mx1,fmaxf(s_[nt][2],s_[nt][3]));
        }
        mx0=fmaxf(mx0,__shfl_xor_sync(0xffffffffu,mx0,1));
        mx0=fmaxf(mx0,__shfl_xor_sync(0xffffffffu,mx0,2));
        mx1=fmaxf(mx1,__shfl_xor_sync(0xffffffffu,mx1,1));
        mx1=fmaxf(mx1,__shfl_xor_sync(0xffffffffu,mx1,2));
        const float mn0=fmaxf(m_run[0],mx0), mn1=fmaxf(m_run[1],mx1);
        const float al0=__expf(m_run[0]-mn0), al1=__expf(m_run[1]-mn1);
        m_run[0]=mn0; m_run[1]=mn1;
        float rs0=0.f, rs1=0.f;
#pragma unroll
        for(int nt=0;nt<8;nt++){
            s_[nt][0]=__expf(s_[nt][0]-mn0); s_[nt][1]=__expf(s_[nt][1]-mn0);
            s_[nt][2]=__expf(s_[nt][2]-mn1); s_[nt][3]=__expf(s_[nt][3]-mn1);
            rs0+=s_[nt][0]+s_[nt][1]; rs1+=s_[nt][2]+s_[nt][3];
        }
        rs0+=__shfl_xor_sync(0xffffffffu,rs0,1); rs0+=__shfl_xor_sync(0xffffffffu,rs0,2);
        rs1+=__shfl_xor_sync(0xffffffffu,rs1,1); rs1+=__shfl_xor_sync(0xffffffffu,rs1,2);
        l_run[0]=l_run[0]*al0+rs0; l_run[1]=l_run[1]*al1+rs1;
#pragma unroll
        for(int nt=0;nt<8;nt++){
            accR[nt][0]*=al0; accR[nt][1]*=al0; accR[nt][2]*=al1; accR[nt][3]*=al1;
            accI[nt][0]*=al0; accI[nt][1]*=al0; accI[nt][2]*=al1; accI[nt][3]*=al1;
        }
        // PV: A-fragment of P built from softmax registers via quad shuffles
#pragma unroll
        for(int kc=0;kc<8;kc++){
            float x0=__shfl_sync(0xffffffffu,s_[kc][0],srcA);
            float x1=__shfl_sync(0xffffffffu,s_[kc][1],srcA);
            float z0=__shfl_sync(0xffffffffu,s_[kc][2],srcA);
            float z1=__shfl_sync(0xffffffffu,s_[kc][3],srcA);
            float y0=__shfl_sync(0xffffffffu,s_[kc][0],srcB);
            float y1=__shfl_sync(0xffffffffu,s_[kc][1],srcB);
            float w0=__shfl_sync(0xffffffffu,s_[kc][2],srcB);
            float w1=__shfl_sync(0xffffffffu,s_[kc][3],srcB);
            unsigned aP[4];
            aP[0]=__float_as_uint(odd?x1:x0);
            aP[1]=__float_as_uint(odd?z1:z0);
            aP[2]=__float_as_uint(odd?y1:y0);
            aP[3]=__float_as_uint(odd?w1:w0);
#pragma unroll
            for(int nt=0;nt<8;nt++){
                unsigned bR[2],bI[2];
                bR[0]=__float_as_uint(sVr[(8*kc+tg  )*WAP+8*nt+grp]);
                bR[1]=__float_as_uint(sVr[(8*kc+tg+4)*WAP+8*nt+grp]);
                bI[0]=__float_as_uint(sVi[(8*kc+tg  )*WAP+8*nt+grp]);
                bI[1]=__float_as_uint(sVi[(8*kc+tg+4)*WAP+8*nt+grp]);
                mma_tf32(accR[nt],aP,bR);
                mma_tf32(accI[nt],aP,bI);
            }
        }
    }
    const float inv0=1.f/l_run[0], inv1=1.f/l_run[1];
#pragma unroll
    for(int nt=0;nt<8;nt++){
        const int d=nt*8+2*tg;
        size_t g0=base+(size_t)(i0+wrow+grp  )*Dsz+d;
        size_t g1=base+(size_t)(i0+wrow+grp+8)*Dsz+d;
        *(float2*)(g_ar+g0)=make_float2(accR[nt][0]*inv0,accR[nt][1]*inv0);
        *(float2*)(g_ar+g1)=make_float2(accR[nt][2]*inv1,accR[nt][3]*inv1);
        *(float2*)(g_ai+g0)=make_float2(accI[nt][0]*inv0,accI[nt][1]*inv0);
        *(float2*)(g_ai+g1)=make_float2(accI[nt][2]*inv1,accI[nt][3]*inv1);
    }
}

// ---------- VQ distance GEMM + first-argmin (fp32) ----------
__global__ __launch_bounds__(256) void dist_kernel(const float* __restrict__ cb) {
    __shared__ float As[16][128], Bs[16][128];
    __shared__ float2 sRed[128][16];
    const int m0=blockIdx.x*128;
    const int tid=threadIdx.x, ty=tid>>4, tx=tid&15;
    const int arow=tid>>1, ak=(tid&1)*8;
    float acc[8][8];
#pragma unroll
    for(int i=0;i<8;i++)
#pragma unroll
        for(int j=0;j<8;j++) acc[i][j]=0.f;
    float4 aa0=*(const float4*)(g_pr+(size_t)(m0+arow)*Dsz+ak);
    float4 aa1=*(const float4*)(g_pr+(size_t)(m0+arow)*Dsz+ak+4);
    float4 cc0=*(const float4*)(cb+(size_t)arow*Dsz+ak);
    float4 cc1=*(const float4*)(cb+(size_t)arow*Dsz+ak+4);
    for(int k0=0;k0<Dsz;k0+=16){
        __syncthreads();
        As[ak+0][arow]=aa0.x;As[ak+1][arow]=aa0.y;As[ak+2][arow]=aa0.z;As[ak+3][arow]=aa0.w;
        As[ak+4][arow]=aa1.x;As[ak+5][arow]=aa1.y;As[ak+6][arow]=aa1.z;As[ak+7][arow]=aa1.w;
        Bs[ak+0][arow]=cc0.x;Bs[ak+1][arow]=cc0.y;Bs[ak+2][arow]=cc0.z;Bs[ak+3][arow]=cc0.w;
        Bs[ak+4][arow]=cc1.x;Bs[ak+5][arow]=cc1.y;Bs[ak+6][arow]=cc1.z;Bs[ak+7][arow]=cc1.w;
        __syncthreads();
        if(k0+16<Dsz){
            aa0=*(const float4*)(g_pr+(size_t)(m0+arow)*Dsz+k0+16+ak);
            aa1=*(const float4*)(g_pr+(size_t)(m0+arow)*Dsz+k0+16+ak+4);
            cc0=*(const float4*)(cb+(size_t)arow*Dsz+k0+16+ak);
            cc1=*(const float4*)(cb+(size_t)arow*Dsz+k0+16+ak+4);
        }
#pragma unroll
        for(int kk=0;kk<16;kk++){
            float4 a0=*(float4*)&As[kk][ty*8],a1=*(float4*)&As[kk][ty*8+4];
            float4 b0=*(float4*)&Bs[kk][tx*8],b1=*(float4*)&Bs[kk][tx*8+4];
            float a[8]={a0.x,a0.y,a0.z,a0.w,a1.x,a1.y,a1.z,a1.w};
            float b[8]={b0.x,b0.y,b0.z,b0.w,b1.x,b1.y,b1.z,b1.w};
#pragma unroll
            for(int i=0;i<8;i++)
#pragma unroll
                for(int j=0;j<8;j++) acc[i][j]+=a[i]*b[j];
        }
    }
#pragma unroll
    for(int i=0;i<8;i++){
        float bd=1e30f; int bi=0;
#pragma unroll
        for(int j=0;j<8;j++){
            int n=tx*8+j;
            float d=g_cn2[n]-2.f*acc[i][j];
            if(d<bd){bd=d;bi=n;}
        }
        sRed[ty*8+i][tx]=make_float2(bd,__int_as_float(bi));
    }
    __syncthreads();
    if(tid<128){
        float bd=1e30f; int bi=0;
#pragma unroll
        for(int t=0;t<16;t++){
            float2 e=sRed[tid][t];
            if(e.x<bd){bd=e.x;bi=__float_as_int(e.y);}
        }
        g_idx[m0+tid]=bi;
    }
}

// ---------- VQ loss ----------
__global__ void loss_kernel(const float* __restrict__ cb) {
    __shared__ float sw[4];
    int m=blockIdx.x, tid=threadIdx.x;
    const float4 f=((const float4*)(g_pr+(size_t)m*Dsz))[tid];
    const float4 c=((const float4*)(cb+(size_t)g_idx[m]*Dsz))[tid];
    float dx=c.x-f.x,dy=c.y-f.y,dz=c.z-f.z,dw=c.w-f.w;
    float v=dx*dx+dy*dy+dz*dz+dw*dw;
#pragma unroll
    for(int o=16;o;o>>=1) v+=__shfl_xor_sync(0xffffffffu,v,o);
    if((tid&31)==0) sw[tid>>5]=v;
    __syncthreads();
    if(tid==0) atomicAdd(&g_loss,(double)(sw[0]+sw[1]+sw[2]+sw[3]));
}

// ---------- gated stack scan ----------
__global__ __launch_bounds__(256) void scan_kernel(const float* __restrict__ cb) {
    __shared__ int sIdx[256]; __shared__ float sP[256],sO[256];
    const int b=blockIdx.x>>6, dg=blockIdx.x&63;
    const int warp=threadIdx.x>>5, lane=threadIdx.x&31;
    const int d=dg*8+warp;
    float st=0.f;
    for(int t0=0;t0<Lsz;t0+=256){
        __syncthreads();
        int ix=g_idx[b*Lsz+t0+threadIdx.x];
        sIdx[threadIdx.x]=ix; sP[threadIdx.x]=g_gp[ix]; sO[threadIdx.x]=g_go[ix];
        __syncthreads();
        for(int tt=0;tt<256;tt++){
            float val=cb[(size_t)sIdx[tt]*Dsz+d];
            float p=sP[tt],o=sO[tt];
            float sh=__shfl_down_sync(0xffffffffu,st,1);
            if(lane==31) sh=val;
            st=((1.f-p)*st+p*sh)*(1.f-o);
            if(lane==31) g_stk[((size_t)b*Lsz+t0+tt)*Dsz+d]=st;
        }
    }
}

// ---------- final ----------
__device__ __forceinline__ float blkRed(float v, float* s) {
#pragma unroll
    for(int o=16;o;o>>=1) v+=__shfl_xor_sync(0xffffffffu,v,o);
    if((threadIdx.x&31)==0) s[threadIdx.x>>5]=v;
    __syncthreads();
    v=s[0]+s[1]+s[2]+s[3];
    __syncthreads();
    return v;
}

__global__ void final_kernel(const float* __restrict__ cb,
                             const float* __restrict__ lng,
                             const float* __restrict__ lnb,
                             const float* __restrict__ mb,
                             float* __restrict__ out, long out_size) {
    __shared__ float sw[4];
    const int m=blockIdx.x, tid=threadIdx.x;
    const float* pr=g_pr+(size_t)m*Dsz;
    const float4 c4=((const float4*)(cb+(size_t)g_idx[m]*Dsz))[tid];
    const float4 f4=((const float4*)pr)[tid];
    const float4 s4=((const float4*)(g_stk+(size_t)m*Dsz))[tid];
    const float4 i4=((const float4*)(g_pi+(size_t)m*Dsz))[tid];
    float cr[4],ci[4];
    cr[0]=(f4.x+(c4.x-f4.x))+s4.x; cr[1]=(f4.y+(c4.y-f4.y))+s4.y;
    cr[2]=(f4.z+(c4.z-f4.z))+s4.z; cr[3]=(f4.w+(c4.w-f4.w))+s4.w;
    ci[0]=i4.x;ci[1]=i4.y;ci[2]=i4.z;ci[3]=i4.w;
    float sr=cr[0]+cr[1]+cr[2]+cr[3], si=ci[0]+ci[1]+ci[2]+ci[3];
    float mur=blkRed(sr,sw)*(1.f/Dsz);
    float mui=blkRed(si,sw)*(1.f/Dsz);
    float vr=0.f,vi=0.f;
#pragma unroll
    for(int k=0;k<4;k++){float a=cr[k]-mur,b=ci[k]-mui;vr+=a*a;vi+=b*b;}
    float varr=blkRed(vr,sw)*(1.f/Dsz);
    float vari=blkRed(vi,sw)*(1.f/Dsz);
    float rr=rsqrtf(varr+1e-5f), ri=rsqrtf(vari+1e-5f);
#pragma unroll
    for(int k=0;k<4;k++){
        int d=tid*4+k;
        float nr=(cr[k]-mur)*rr*lng[d]+lnb[d];
        float ni=(ci[k]-mui)*ri*lng[Dsz+d]+lnb[Dsz+d];
        float mag=sqrtf(nr*nr+ni*ni);
        float sc=fmaxf(mag+mb[d],0.f)/(mag+1e-6f);
        out[(size_t)m*Dsz+d]=nr*sc;
        out[OUTHALF+(size_t)m*Dsz+d]=ni*sc;
    }
    if(m==0&&tid==0)
        out[out_size-1]=(float)(1.25*g_loss/(double)((size_t)Msz*Dsz));
}

extern "C" void kernel_launch(void* const* d_in, const int* in_sizes, int n_in,
                              void* d_out, int out_size) {
    const int*   tokens=(const int*)  d_in[0];
    const float* embed =(const float*)d_in[2];
    const float* q_w=(const float*)d_in[3],  *q_b=(const float*)d_in[4];
    const float* k_w=(const float*)d_in[5],  *k_b=(const float*)d_in[6];
    const float* v_w=(const float*)d_in[7],  *v_b=(const float*)d_in[8];
    const float* o_w=(const float*)d_in[9],  *o_b=(const float*)d_in[10];
    const float* cb =(const float*)d_in[11];
    const float* gw =(const float*)d_in[12], *gb=(const float*)d_in[13];
    const float* lng=(const float*)d_in[14], *lnb=(const float*)d_in[15];
    const float* mb =(const float*)d_in[16];
    float* out=(float*)d_out;

    static bool attr_set=false;
    if(!attr_set){
        cudaFuncSetAttribute(attn_kernel,cudaFuncAttributeMaxDynamicSharedMemorySize,ATTN_SMEM);
        attr_set=true;
    }
    prep_kernel<<<1,128>>>(cb,gw,gb);
    gather_kernel<<<Msz,128>>>(tokens,embed);
    proj_kernel<<<dim3(4,64,6),256>>>(q_w,q_b,k_w,k_b,v_w,v_b);
    attn_kernel<<<dim3(8,64),256,ATTN_SMEM>>>();
    oproj_kernel<<<dim3(8,64),256>>>(o_w,o_b);
    dist_kernel<<<64,256>>>(cb);
    loss_kernel<<<Msz,128>>>(cb);
    scan_kernel<<<512,256>>>(cb);
    final_kernel<<<Msz,128>>>(cb,lng,lnb,mb,out,(long)out_size);
}

// round 9
// speedup vs baseline: 2.9174x; 1.0865x over previous
#include <cuda_runtime.h>

#define Bsz 8
#define Lsz 1024
#define Dsz 512
#define HDsz 64
#define NCsz 128
#define Msz (Bsz*Lsz)
#define OUTHALF ((size_t)Msz*Dsz)
#define NEG_INF (-__int_as_float(0x7f800000))

__device__ float g_zr[Msz*Dsz];
__device__ float g_qr[Msz*Dsz], g_qi[Msz*Dsz];
__device__ float g_kr[Msz*Dsz], g_ki[Msz*Dsz];
__device__ float g_vr[Msz*Dsz], g_vi[Msz*Dsz];
__device__ float g_ar[Msz*Dsz], g_ai[Msz*Dsz];
__device__ float g_pr[Msz*Dsz], g_pi[Msz*Dsz];
__device__ int   g_idx[Msz];
__device__ float g_stk[Msz*Dsz];
__device__ float g_cn2[NCsz], g_gp[NCsz], g_go[NCsz];
__device__ double g_loss;

__device__ __forceinline__ void mma_tf32(float* c, const unsigned* a, const unsigned* b){
    asm volatile("mma.sync.aligned.m16n8k8.row.col.f32.tf32.tf32.f32 "
        "{%0,%1,%2,%3}, {%4,%5,%6,%7}, {%8,%9}, {%0,%1,%2,%3};"
        : "+f"(c[0]),"+f"(c[1]),"+f"(c[2]),"+f"(c[3])
        : "r"(a[0]),"r"(a[1]),"r"(a[2]),"r"(a[3]),"r"(b[0]),"r"(b[1]));
}
__device__ __forceinline__ unsigned su32(const void* p){
    return (unsigned)__cvta_generic_to_shared(p);
}
#define LDSM4(r,a) asm volatile("ldmatrix.sync.aligned.m8n8.x4.shared.b16 {%0,%1,%2,%3}, [%4];" \
    : "=r"((r)[0]),"=r"((r)[1]),"=r"((r)[2]),"=r"((r)[3]) : "r"(a))
#define LDSM2(r,a) asm volatile("ldmatrix.sync.aligned.m8n8.x2.shared.b16 {%0,%1}, [%2];" \
    : "=r"((r)[0]),"=r"((r)[1]) : "r"(a))
#define CPA16(dst,src) asm volatile("cp.async.cg.shared.global [%0], [%1], 16;" :: "r"(su32(dst)), "l"(src))
#define CPA_COMMIT()   asm volatile("cp.async.commit_group;" ::: "memory")
#define CPA_WAIT0()    asm volatile("cp.async.wait_group 0;" ::: "memory")

// ---------- prep ----------
__global__ void prep_kernel(const float* __restrict__ cb,
                            const float* __restrict__ gw,
                            const float* __restrict__ gb) {
    int j = threadIdx.x;
    if (j == 0) g_loss = 0.0;
    if (j < NCsz) {
        float s2 = 0.f, d0 = 0.f, d1 = 0.f;
        for (int d = 0; d < Dsz; d++) {
            float c = cb[j*Dsz + d];
            s2 += c*c; d0 += c*gw[d*2+0]; d1 += c*gw[d*2+1];
        }
        g_cn2[j] = s2;
        g_gp[j] = 1.f/(1.f+expf(-(d0+gb[0])));
        g_go[j] = 1.f/(1.f+expf(-(d1+gb[1])));
    }
}

// ---------- embedding gather ----------
__global__ void gather_kernel(const int* __restrict__ tokens,
                              const float* __restrict__ embed) {
    int m = blockIdx.x;
    const float4* src = (const float4*)(embed + (size_t)tokens[m]*Dsz);
    ((float4*)(g_zr + (size_t)m*Dsz))[threadIdx.x] = src[threadIdx.x];
}

// ---------- tf32 projection GEMM (ldmatrix A) ----------
__global__ __launch_bounds__(256) void proj_kernel(
        const float* __restrict__ qw, const float* __restrict__ qb,
        const float* __restrict__ kw, const float* __restrict__ kb,
        const float* __restrict__ vw, const float* __restrict__ vb) {
    __shared__ unsigned As[128][36];
    __shared__ unsigned Bs[32][132];
    const int z = blockIdx.z, pair = z>>1, im = z&1;
    const float* W; const float* bias; float* C;
    if (pair==0){W=qw;bias=qb;C=im?g_qi:g_qr;}
    else if (pair==1){W=kw;bias=kb;C=im?g_ki:g_kr;}
    else {W=vw;bias=vb;C=im?g_vi:g_vr;}
    W += (size_t)im*Dsz*Dsz;
    const float sgn = im?1.f:-1.f;
    const int m0=blockIdx.y*128, n0=blockIdx.x*128;
    const int tid=threadIdx.x, warp=tid>>5, lane=tid&31;
    const int wm=warp>>2, wn=warp&3, grp=lane>>2, tg=lane&3;
    const int lrow=lane&15, lcol=(lane&16)?4:0;
    const int arow=tid>>3, ac4=(tid&7)*4;
    const int brow=tid>>5, bc4=(tid&31)*4;
    float acc[4][4][4];
#pragma unroll
    for(int i=0;i<4;i++)
#pragma unroll
        for(int j=0;j<4;j++)
#pragma unroll
            for(int k=0;k<4;k++) acc[i][j][k]=0.f;
    float4 pa[4], pb[4];
#pragma unroll
    for(int u=0;u<4;u++){
        pa[u]=*(const float4*)(g_zr+(size_t)(m0+arow+u*32)*Dsz+ac4);
        pb[u]=*(const float4*)(W+(size_t)(brow+u*8)*Dsz+n0+bc4);
    }
    for(int k0=0;k0<Dsz;k0+=32){
        __syncthreads();
#pragma unroll
        for(int u=0;u<4;u++){
            *(uint4*)&As[arow+u*32][ac4]=*reinterpret_cast<uint4*>(&pa[u]);
            *(uint4*)&Bs[brow+u*8][bc4]=*reinterpret_cast<uint4*>(&pb[u]);
        }
        __syncthreads();
        if(k0+32<Dsz){
#pragma unroll
            for(int u=0;u<4;u++){
                pa[u]=*(const float4*)(g_zr+(size_t)(m0+arow+u*32)*Dsz+k0+32+ac4);
                pb[u]=*(const float4*)(W+(size_t)(k0+32+brow+u*8)*Dsz+n0+bc4);
            }
        }
#pragma unroll
        for(int k8=0;k8<4;k8++){
            const int kb8=k8*8;
            unsigned af[4][4], bf[4][2];
#pragma unroll
            for(int mt=0;mt<4;mt++){
                LDSM4(af[mt], su32(&As[wm*64+mt*16+lrow][kb8+lcol]));
            }
#pragma unroll
            for(int nt=0;nt<4;nt++){
                int cix=wn*32+nt*8+grp;
                bf[nt][0]=Bs[kb8+tg][cix]; bf[nt][1]=Bs[kb8+tg+4][cix];
            }
#pragma unroll
            for(int mt=0;mt<4;mt++)
#pragma unroll
                for(int nt=0;nt<4;nt++) mma_tf32(acc[mt][nt],af[mt],bf[nt]);
        }
    }
#pragma unroll
    for(int mt=0;mt<4;mt++){
#pragma unroll
        for(int nt=0;nt<4;nt++){
            int r=m0+wm*64+mt*16+grp;
            int cix=n0+wn*32+nt*8+2*tg;
            float b0=bias[cix]+sgn*bias[Dsz+cix];
            float b1=bias[cix+1]+sgn*bias[Dsz+cix+1];
            *(float2*)(C+(size_t)r*Dsz+cix)    =make_float2(acc[mt][nt][0]+b0,acc[mt][nt][1]+b1);
            *(float2*)(C+(size_t)(r+8)*Dsz+cix)=make_float2(acc[mt][nt][2]+b0,acc[mt][nt][3]+b1);
        }
    }
}

// ---------- tf32 fused complex O-projection (ldmatrix A) ----------
__global__ __launch_bounds__(256) void oproj_kernel(const float* __restrict__ ow,
                                                    const float* __restrict__ ob) {
    __shared__ unsigned As[128][36];
    __shared__ unsigned Bs[32][132];
    const float* w0=ow; const float* w1=ow+(size_t)Dsz*Dsz;
    const int m0=blockIdx.y*128, n0=blockIdx.x*128;
    const bool isI = (n0>=Dsz);
    const int nloc = isI ? n0-Dsz : n0;
    const int tid=threadIdx.x, warp=tid>>5, lane=tid&31;
    const int wm=warp>>2, wn=warp&3, grp=lane>>2, tg=lane&3;
    const int lrow=lane&15, lcol=(lane&16)?4:0;
    const int arow=tid>>3, ac4=(tid&7)*4;
    const int brow=tid>>5, bc4=(tid&31)*4;
    float acc[4][4][4];
#pragma unroll
    for(int i=0;i<4;i++)
#pragma unroll
        for(int j=0;j<4;j++)
#pragma unroll
            for(int k=0;k<4;k++) acc[i][j][k]=0.f;
    float4 pa[4], pb[4];
#pragma unroll
    for(int u=0;u<4;u++){
        pa[u]=*(const float4*)(g_ar+(size_t)(m0+arow+u*32)*Dsz+ac4);
        const float* wsrc = isI ? w1 : w0;
        pb[u]=*(const float4*)(wsrc+(size_t)(brow+u*8)*Dsz+nloc+bc4);
    }
    for(int k0=0;k0<2*Dsz;k0+=32){
        __syncthreads();
        const bool khi_cur = (k0>=Dsz);
        const unsigned smask = (!isI && khi_cur) ? 0x80000000u : 0u;
#pragma unroll
        for(int u=0;u<4;u++){
            *(uint4*)&As[arow+u*32][ac4]=*reinterpret_cast<uint4*>(&pa[u]);
            uint4 ub=*reinterpret_cast<uint4*>(&pb[u]);
            ub.x^=smask; ub.y^=smask; ub.z^=smask; ub.w^=smask;
            *(uint4*)&Bs[brow+u*8][bc4]=ub;
        }
        __syncthreads();
        if(k0+32<2*Dsz){
            const int kn=k0+32;
            const bool khi = (kn>=Dsz);
            const float* asrc = khi ? g_ai : g_ar;
            const int akk = khi ? kn-Dsz : kn;
            const float* wsrc = isI ? (khi ? w0 : w1) : (khi ? w1 : w0);
            const int bkk = khi ? kn-Dsz : kn;
#pragma unroll
            for(int u=0;u<4;u++){
                pa[u]=*(const float4*)(asrc+(size_t)(m0+arow+u*32)*Dsz+akk+ac4);
                pb[u]=*(const float4*)(wsrc+(size_t)(bkk+brow+u*8)*Dsz+nloc+bc4);
            }
        }
#pragma unroll
        for(int k8=0;k8<4;k8++){
            const int kb8=k8*8;
            unsigned af[4][4], bf[4][2];
#pragma unroll
            for(int mt=0;mt<4;mt++){
                LDSM4(af[mt], su32(&As[wm*64+mt*16+lrow][kb8+lcol]));
            }
#pragma unroll
            for(int nt=0;nt<4;nt++){
                int cix=wn*32+nt*8+grp;
                bf[nt][0]=Bs[kb8+tg][cix]; bf[nt][1]=Bs[kb8+tg+4][cix];
            }
#pragma unroll
            for(int mt=0;mt<4;mt++)
#pragma unroll
                for(int nt=0;nt<4;nt++) mma_tf32(acc[mt][nt],af[mt],bf[nt]);
        }
    }
    float* Cdst = isI ? g_pi : g_pr;
    const float s2 = isI ? 1.f : -1.f;
#pragma unroll
    for(int mt=0;mt<4;mt++){
#pragma unroll
        for(int nt=0;nt<4;nt++){
            int r=m0+wm*64+mt*16+grp;
            int cl=wn*32+nt*8+2*tg;
            int cg=nloc+cl;
            float b0=ob[cg]+s2*ob[Dsz+cg];
            float b1=ob[cg+1]+s2*ob[Dsz+cg+1];
            *(float2*)(Cdst+(size_t)r*Dsz+cg)    =make_float2(acc[mt][nt][0]+b0,acc[mt][nt][1]+b1);
            *(float2*)(Cdst+(size_t)(r+8)*Dsz+cg)=make_float2(acc[mt][nt][2]+b0,acc[mt][nt][3]+b1);
        }
    }
}

// ---------- tf32 flash attention: cp.async double-buffered K/V, ldmatrix Q/K, shuffle-P ----------
#define WAP 68
#define KVSTRIDE (4*64*WAP)
#define ATTN_SMEM ((2*128*WAP + 2*KVSTRIDE)*4)
__global__ __launch_bounds__(256) void attn_kernel() {
    extern __shared__ float smf[];
    float* sQr=smf;
    float* sQi=sQr+128*WAP;
    float* sKV=sQi+128*WAP;
    const int bh=blockIdx.y, b=bh>>3, h=bh&7;
    const int bx=blockIdx.x, i0=bx*128;
    const int tid=threadIdx.x, warp=tid>>5, lane=tid&31;
    const int grp=lane>>2, tg=lane&3;
    const int lrow=lane&15, lcol=(lane&16)?4:0;
    const int lrow2=lane&7, lcol2=(lane&8)?4:0;
    const int wrow=warp*16;
    const size_t base=(size_t)b*Lsz*Dsz + h*HDsz;
#pragma unroll
    for(int u=0;u<8;u++){
        int li=tid+u*256, r=li>>4, c4=(li&15)*4;
        size_t g=base+(size_t)(i0+r)*Dsz+c4;
        CPA16(&sQr[r*WAP+c4], g_qr+g);
        CPA16(&sQi[r*WAP+c4], g_qi+g);
    }
    CPA_COMMIT();
    const int ntile=2*bx+2;
    {
        float* kr=sKV; float* ki=kr+64*WAP; float* vr=ki+64*WAP; float* vi=vr+64*WAP;
#pragma unroll
        for(int u=0;u<4;u++){
            int li=tid+u*256, r=li>>4, c4=(li&15)*4;
            size_t g=base+(size_t)r*Dsz+c4;
            CPA16(&kr[r*WAP+c4], g_kr+g); CPA16(&ki[r*WAP+c4], g_ki+g);
            CPA16(&vr[r*WAP+c4], g_vr+g); CPA16(&vi[r*WAP+c4], g_vi+g);
        }
        CPA_COMMIT();
    }
    float m_run[2]={NEG_INF,NEG_INF}, l_run[2]={0.f,0.f};
    float accR[8][4], accI[8][4];
#pragma unroll
    for(int nt=0;nt<8;nt++)
#pragma unroll
        for(int k=0;k<4;k++){accR[nt][k]=0.f;accI[nt][k]=0.f;}
    const int srcA=(lane&~3)|(tg>>1), srcB=srcA|2;
    const bool odd=tg&1;
    for(int jt=0;jt<ntile;jt++){
        CPA_WAIT0();
        __syncthreads();
        if(jt+1<ntile){
            const int s0n=(jt+1)*64, stn=(jt+1)&1;
            float* kr=sKV+stn*KVSTRIDE; float* ki=kr+64*WAP;
            float* vr=ki+64*WAP;        float* vi=vr+64*WAP;
#pragma unroll
            for(int u=0;u<4;u++){
                int li=tid+u*256, r=li>>4, c4=(li&15)*4;
                size_t g=base+(size_t)(s0n+r)*Dsz+c4;
                CPA16(&kr[r*WAP+c4], g_kr+g); CPA16(&ki[r*WAP+c4], g_ki+g);
                CPA16(&vr[r*WAP+c4], g_vr+g); CPA16(&vi[r*WAP+c4], g_vi+g);
            }
            CPA_COMMIT();
        }
        const int s0=jt*64;
        float* sKr=sKV+(jt&1)*KVSTRIDE; float* sKi=sKr+64*WAP;
        float* sVr=sKi+64*WAP;          float* sVi=sVr+64*WAP;
        float s_[8][4];
#pragma unroll
        for(int nt=0;nt<8;nt++)
#pragma unroll
            for(int k=0;k<4;k++) s_[nt][k]=0.f;
#pragma unroll
        for(int kc=0;kc<8;kc++){
            const int kb=kc*8;
            unsigned aR[4],aI[4];
            LDSM4(aR, su32(&sQr[(wrow+lrow)*WAP+kb+lcol]));
            LDSM4(aI, su32(&sQi[(wrow+lrow)*WAP+kb+lcol]));
#pragma unroll
            for(int nt=0;nt<8;nt++){
                unsigned bR[2],bI[2];
                LDSM2(bR, su32(&sKr[(8*nt+lrow2)*WAP+kb+lcol2]));
                LDSM2(bI, su32(&sKi[(8*nt+lrow2)*WAP+kb+lcol2]));
                mma_tf32(s_[nt],aR,bR);
                mma_tf32(s_[nt],aI,bI);
            }
        }
        const bool diag=(jt>=2*bx);
        const int r0=i0+wrow+grp, r1=r0+8;
#pragma unroll
        for(int nt=0;nt<8;nt++){
            const int c0=s0+nt*8+2*tg, c1=c0+1;
            s_[nt][0]*=0.125f; s_[nt][1]*=0.125f; s_[nt][2]*=0.125f; s_[nt][3]*=0.125f;
            if(diag){
                if(c0>r0)s_[nt][0]=NEG_INF; if(c1>r0)s_[nt][1]=NEG_INF;
                if(c0>r1)s_[nt][2]=NEG_INF; if(c1>r1)s_[nt][3]=NEG_INF;
            }
        }
        float mx0=NEG_INF, mx1=NEG_INF;
#pragma unroll
        for(int nt=0;nt<8;nt++){
            mx0=fmaxf(mx0,fmaxf(s_[nt][0],s_[nt][1]));
            mx1=fmaxf(mx1,fmaxf(s_[nt][2],s_[nt][3]));
        }
        mx0=fmaxf(mx0,__shfl_xor_sync(0xffffffffu,mx0,1));
        mx0=fmaxf(mx0,__shfl_xor_sync(0xffffffffu,mx0,2));
        mx1=fmaxf(mx1,__shfl_xor_sync(0xffffffffu,mx1,1));
        mx1=fmaxf(mx1,__shfl_xor_sync(0xffffffffu,mx1,2));
        const float mn0=fmaxf(m_run[0],mx0), mn1=fmaxf(m_run[1],mx1);
        const float al0=__expf(m_run[0]-mn0), al1=__expf(m_run[1]-mn1);
        m_run[0]=mn0; m_run[1]=mn1;
        float rs0=0.f, rs1=0.f;
#pragma unroll
        for(int nt=0;nt<8;nt++){
            s_[nt][0]=__expf(s_[nt][0]-mn0); s_[nt][1]=__expf(s_[nt][1]-mn0);
            s_[nt][2]=__expf(s_[nt][2]-mn1); s_[nt][3]=__expf(s_[nt][3]-mn1);
            rs0+=s_[nt][0]+s_[nt][1]; rs1+=s_[nt][2]+s_[nt][3];
        }
        rs0+=__shfl_xor_sync(0xffffffffu,rs0,1); rs0+=__shfl_xor_sync(0xffffffffu,rs0,2);
        rs1+=__shfl_xor_sync(0xffffffffu,rs1,1); rs1+=__shfl_xor_sync(0xffffffffu,rs1,2);
        l_run[0]=l_run[0]*al0+rs0; l_run[1]=l_run[1]*al1+rs1;
#pragma unroll
        for(int nt=0;nt<8;nt++){
            accR[nt][0]*=al0; accR[nt][1]*=al0; accR[nt][2]*=al1; accR[nt][3]*=al1;
            accI[nt][0]*=al0; accI[nt][1]*=al0; accI[nt][2]*=al1; accI[nt][3]*=al1;
        }
#pragma unroll
        for(int kc=0;kc<8;kc++){
            float x0=__shfl_sync(0xffffffffu,s_[kc][0],srcA);
            float x1=__shfl_sync(0xffffffffu,s_[kc][1],srcA);
            float z0=__shfl_sync(0xffffffffu,s_[kc][2],srcA);
            float z1=__shfl_sync(0xffffffffu,s_[kc][3],srcA);
            float y0=__shfl_sync(0xffffffffu,s_[kc][0],srcB);
            float y1=__shfl_sync(0xffffffffu,s_[kc][1],srcB);
            float w0=__shfl_sync(0xffffffffu,s_[kc][2],srcB);
            float w1=__shfl_sync(0xffffffffu,s_[kc][3],srcB);
            unsigned aP[4];
            aP[0]=__float_as_uint(odd?x1:x0);
            aP[1]=__float_as_uint(odd?z1:z0);
            aP[2]=__float_as_uint(odd?y1:y0);
            aP[3]=__float_as_uint(odd?w1:w0);
#pragma unroll
            for(int nt=0;nt<8;nt++){
                unsigned bR[2],bI[2];
                bR[0]=__float_as_uint(sVr[(8*kc+tg  )*WAP+8*nt+grp]);
                bR[1]=__float_as_uint(sVr[(8*kc+tg+4)*WAP+8*nt+grp]);
                bI[0]=__float_as_uint(sVi[(8*kc+tg  )*WAP+8*nt+grp]);
                bI[1]=__float_as_uint(sVi[(8*kc+tg+4)*WAP+8*nt+grp]);
                mma_tf32(accR[nt],aP,bR);
                mma_tf32(accI[nt],aP,bI);
            }
        }
    }
    const float inv0=1.f/l_run[0], inv1=1.f/l_run[1];
#pragma unroll
    for(int nt=0;nt<8;nt++){
        const int d=nt*8+2*tg;
        size_t g0=base+(size_t)(i0+wrow+grp  )*Dsz+d;
        size_t g1=base+(size_t)(i0+wrow+grp+8)*Dsz+d;
        *(float2*)(g_ar+g0)=make_float2(accR[nt][0]*inv0,accR[nt][1]*inv0);
        *(float2*)(g_ar+g1)=make_float2(accR[nt][2]*inv1,accR[nt][3]*inv1);
        *(float2*)(g_ai+g0)=make_float2(accI[nt][0]*inv0,accI[nt][1]*inv0);
        *(float2*)(g_ai+g1)=make_float2(accI[nt][2]*inv1,accI[nt][3]*inv1);
    }
}

// ---------- VQ distance v2: 32-row tiles, 256 blocks ----------
__global__ __launch_bounds__(256) void dist_kernel(const float* __restrict__ cb) {
    __shared__ float As[16][36];
    __shared__ float Bs[16][132];
    __shared__ float2 sRed[32][32];
    const int m0=blockIdx.x*32;
    const int tid=threadIdx.x, ty=tid>>5, tx=tid&31;
    const int arow=tid>>2, ak=(tid&3)*4;
    float acc[4][4];
#pragma unroll
    for(int i=0;i<4;i++)
#pragma unroll
        for(int j=0;j<4;j++) acc[i][j]=0.f;
    float4 pa=make_float4(0,0,0,0), pb0, pb1;
    if(tid<128) pa=*(const float4*)(g_pr+(size_t)(m0+arow)*Dsz+ak);
    pb0=*(const float4*)(cb+(size_t)(tid>>2)*Dsz+ak);
    pb1=*(const float4*)(cb+(size_t)(64+(tid>>2))*Dsz+ak);
    for(int k0=0;k0<Dsz;k0+=16){
        __syncthreads();
        if(tid<128){
            As[ak+0][arow]=pa.x;As[ak+1][arow]=pa.y;As[ak+2][arow]=pa.z;As[ak+3][arow]=pa.w;
        }
        {
            int c=tid>>2;
            Bs[ak+0][c]=pb0.x;Bs[ak+1][c]=pb0.y;Bs[ak+2][c]=pb0.z;Bs[ak+3][c]=pb0.w;
            Bs[ak+0][64+c]=pb1.x;Bs[ak+1][64+c]=pb1.y;Bs[ak+2][64+c]=pb1.z;Bs[ak+3][64+c]=pb1.w;
        }
        __syncthreads();
        if(k0+16<Dsz){
            if(tid<128) pa=*(const float4*)(g_pr+(size_t)(m0+arow)*Dsz+k0+16+ak);
            pb0=*(const float4*)(cb+(size_t)(tid>>2)*Dsz+k0+16+ak);
            pb1=*(const float4*)(cb+(size_t)(64+(tid>>2))*Dsz+k0+16+ak);
        }
#pragma unroll
        for(int kk=0;kk<16;kk++){
            float4 a4=*(float4*)&As[kk][ty*4];
            float4 b4=*(float4*)&Bs[kk][tx*4];
            float a[4]={a4.x,a4.y,a4.z,a4.w};
            float b[4]={b4.x,b4.y,b4.z,b4.w};
#pragma unroll
            for(int i=0;i<4;i++)
#pragma unroll
                for(int j=0;j<4;j++) acc[i][j]+=a[i]*b[j];
        }
    }
#pragma unroll
    for(int i=0;i<4;i++){
        float bd=1e30f; int bi=0;
#pragma unroll
        for(int j=0;j<4;j++){
            int n=tx*4+j;
            float d=g_cn2[n]-2.f*acc[i][j];
            if(d<bd){bd=d;bi=n;}
        }
        sRed[ty*4+i][tx]=make_float2(bd,__int_as_float(bi));
    }
    __syncthreads();
    if(tid<32){
        float bd=1e30f; int bi=0;
#pragma unroll
        for(int t=0;t<32;t++){
            float2 e=sRed[tid][t];
            if(e.x<bd){bd=e.x;bi=__float_as_int(e.y);}
        }
        g_idx[m0+tid]=bi;
    }
}

// ---------- gated stack scan ----------
__global__ __launch_bounds__(256) void scan_kernel(const float* __restrict__ cb) {
    __shared__ int sIdx[256]; __shared__ float sP[256],sO[256];
    const int b=blockIdx.x>>6, dg=blockIdx.x&63;
    const int warp=threadIdx.x>>5, lane=threadIdx.x&31;
    const int d=dg*8+warp;
    float st=0.f;
    for(int t0=0;t0<Lsz;t0+=256){
        __syncthreads();
        int ix=g_idx[b*Lsz+t0+threadIdx.x];
        sIdx[threadIdx.x]=ix; sP[threadIdx.x]=g_gp[ix]; sO[threadIdx.x]=g_go[ix];
        __syncthreads();
        for(int tt=0;tt<256;tt++){
            float val=cb[(size_t)sIdx[tt]*Dsz+d];
            float p=sP[tt],o=sO[tt];
            float sh=__shfl_down_sync(0xffffffffu,st,1);
            if(lane==31) sh=val;
            st=((1.f-p)*st+p*sh)*(1.f-o);
            if(lane==31) g_stk[((size_t)b*Lsz+t0+tt)*Dsz+d]=st;
        }
    }
}

// ---------- final (with fused loss partial) ----------
__device__ __forceinline__ float blkRed(float v, float* s) {
#pragma unroll
    for(int o=16;o;o>>=1) v+=__shfl_xor_sync(0xffffffffu,v,o);
    if((threadIdx.x&31)==0) s[threadIdx.x>>5]=v;
    __syncthreads();
    v=s[0]+s[1]+s[2]+s[3];
    __syncthreads();
    return v;
}

__global__ void final_kernel(const float* __restrict__ cb,
                             const float* __restrict__ lng,
                             const float* __restrict__ lnb,
                             const float* __restrict__ mb,
                             float* __restrict__ out) {
    __shared__ float sw[4];
    const int m=blockIdx.x, tid=threadIdx.x;
    const float* pr=g_pr+(size_t)m*Dsz;
    const float4 c4=((const float4*)(cb+(size_t)g_idx[m]*Dsz))[tid];
    const float4 f4=((const float4*)pr)[tid];
    const float4 s4=((const float4*)(g_stk+(size_t)m*Dsz))[tid];
    const float4 i4=((const float4*)(g_pi+(size_t)m*Dsz))[tid];
    // fused VQ loss partial
    {
        float dx=c4.x-f4.x,dy=c4.y-f4.y,dz=c4.z-f4.z,dw=c4.w-f4.w;
        float lv=dx*dx+dy*dy+dz*dz+dw*dw;
        float lt=blkRed(lv,sw);
        if(tid==0) atomicAdd(&g_loss,(double)lt);
    }
    float cr[4],ci[4];
    cr[0]=(f4.x+(c4.x-f4.x))+s4.x; cr[1]=(f4.y+(c4.y-f4.y))+s4.y;
    cr[2]=(f4.z+(c4.z-f4.z))+s4.z; cr[3]=(f4.w+(c4.w-f4.w))+s4.w;
    ci[0]=i4.x;ci[1]=i4.y;ci[2]=i4.z;ci[3]=i4.w;
    float sr=cr[0]+cr[1]+cr[2]+cr[3], si=ci[0]+ci[1]+ci[2]+ci[3];
    float mur=blkRed(sr,sw)*(1.f/Dsz);
    float mui=blkRed(si,sw)*(1.f/Dsz);
    float vr=0.f,vi=0.f;
#pragma unroll
    for(int k=0;k<4;k++){float a=cr[k]-mur,b=ci[k]-mui;vr+=a*a;vi+=b*b;}
    float varr=blkRed(vr,sw)*(1.f/Dsz);
    float vari=blkRed(vi,sw)*(1.f/Dsz);
    float rr=rsqrtf(varr+1e-5f), ri=rsqrtf(vari+1e-5f);
#pragma unroll
    for(int k=0;k<4;k++){
        int d=tid*4+k;
        float nr=(cr[k]-mur)*rr*lng[d]+lnb[d];
        float ni=(ci[k]-mui)*ri*lng[Dsz+d]+lnb[Dsz+d];
        float mag=sqrtf(nr*nr+ni*ni);
        float sc=fmaxf(mag+mb[d],0.f)/(mag+1e-6f);
        out[(size_t)m*Dsz+d]=nr*sc;
        out[OUTHALF+(size_t)m*Dsz+d]=ni*sc;
    }
}

__global__ void loss_write(float* __restrict__ out, long out_size){
    out[out_size-1]=(float)(1.25*g_loss/(double)((size_t)Msz*Dsz));
}

extern "C" void kernel_launch(void* const* d_in, const int* in_sizes, int n_in,
                              void* d_out, int out_size) {
    const int*   tokens=(const int*)  d_in[0];
    const float* embed =(const float*)d_in[2];
    const float* q_w=(const float*)d_in[3],  *q_b=(const float*)d_in[4];
    const float* k_w=(const float*)d_in[5],  *k_b=(const float*)d_in[6];
    const float* v_w=(const float*)d_in[7],  *v_b=(const float*)d_in[8];
    const float* o_w=(const float*)d_in[9],  *o_b=(const float*)d_in[10];
    const float* cb =(const float*)d_in[11];
    const float* gw =(const float*)d_in[12], *gb=(const float*)d_in[13];
    const float* lng=(const float*)d_in[14], *lnb=(const float*)d_in[15];
    const float* mb =(const float*)d_in[16];
    float* out=(float*)d_out;

    static bool attr_set=false;
    if(!attr_set){
        cudaFuncSetAttribute(attn_kernel,cudaFuncAttributeMaxDynamicSharedMemorySize,ATTN_SMEM);
        attr_set=true;
    }
    prep_kernel<<<1,128>>>(cb,gw,gb);
    gather_kernel<<<Msz,128>>>(tokens,embed);
    proj_kernel<<<dim3(4,64,6),256>>>(q_w,q_b,k_w,k_b,v_w,v_b);
    attn_kernel<<<dim3(8,64),256,ATTN_SMEM>>>();
    oproj_kernel<<<dim3(8,64),256>>>(o_w,o_b);
    dist_kernel<<<256,256>>>(cb);
    scan_kernel<<<512,256>>>(cb);
    final_kernel<<<Msz,128>>>(cb,lng,lnb,mb,out);
    loss_write<<<1,1>>>(out,(long)out_size);
}

// round 10
// speedup vs baseline: 3.3107x; 1.1348x over previous
#include <cuda_runtime.h>

#define Bsz 8
#define Lsz 1024
#define Dsz 512
#define HDsz 64
#define NCsz 128
#define Msz (Bsz*Lsz)
#define OUTHALF ((size_t)Msz*Dsz)
#define NEG_INF (-__int_as_float(0x7f800000))

__device__ float g_qr[Msz*Dsz], g_qi[Msz*Dsz];
__device__ float g_kr[Msz*Dsz], g_ki[Msz*Dsz];
__device__ float g_vr[Msz*Dsz], g_vi[Msz*Dsz];
__device__ float g_ar[Msz*Dsz], g_ai[Msz*Dsz];
__device__ float g_pr[Msz*Dsz], g_pi[Msz*Dsz];
__device__ int   g_idx[Msz];
__device__ float g_stk[Msz*Dsz];
__device__ float g_cn2[NCsz], g_gp[NCsz], g_go[NCsz];
__device__ double g_loss;

__device__ __forceinline__ void mma_tf32(float* c, const unsigned* a, const unsigned* b){
    asm volatile("mma.sync.aligned.m16n8k8.row.col.f32.tf32.tf32.f32 "
        "{%0,%1,%2,%3}, {%4,%5,%6,%7}, {%8,%9}, {%0,%1,%2,%3};"
        : "+f"(c[0]),"+f"(c[1]),"+f"(c[2]),"+f"(c[3])
        : "r"(a[0]),"r"(a[1]),"r"(a[2]),"r"(a[3]),"r"(b[0]),"r"(b[1]));
}
__device__ __forceinline__ unsigned su32(const void* p){
    return (unsigned)__cvta_generic_to_shared(p);
}
#define LDSM4(r,a) asm volatile("ldmatrix.sync.aligned.m8n8.x4.shared.b16 {%0,%1,%2,%3}, [%4];" \
    : "=r"((r)[0]),"=r"((r)[1]),"=r"((r)[2]),"=r"((r)[3]) : "r"(a))
#define CPA16(dst,src) asm volatile("cp.async.cg.shared.global [%0], [%1], 16;" :: "r"(su32(dst)), "l"(src))
#define CPA_COMMIT()   asm volatile("cp.async.commit_group;" ::: "memory")
#define CPA_WAIT0()    asm volatile("cp.async.wait_group 0;" ::: "memory")

// ---------- prep: parallel over codes ----------
__global__ void prep_kernel(const float* __restrict__ cb,
                            const float* __restrict__ gw,
                            const float* __restrict__ gb) {
    __shared__ float sh[3][4];
    const int j=blockIdx.x, t=threadIdx.x;
    if(j==0&&t==0) g_loss=0.0;
    float s2=0.f,d0=0.f,d1=0.f;
    for(int d=t; d<Dsz; d+=128){
        float c=cb[j*Dsz+d];
        s2+=c*c; d0+=c*gw[2*d]; d1+=c*gw[2*d+1];
    }
#pragma unroll
    for(int o=16;o;o>>=1){
        s2+=__shfl_xor_sync(0xffffffffu,s2,o);
        d0+=__shfl_xor_sync(0xffffffffu,d0,o);
        d1+=__shfl_xor_sync(0xffffffffu,d1,o);
    }
    if((t&31)==0){ sh[0][t>>5]=s2; sh[1][t>>5]=d0; sh[2][t>>5]=d1; }
    __syncthreads();
    if(t==0){
        float a=sh[0][0]+sh[0][1]+sh[0][2]+sh[0][3];
        float b=sh[1][0]+sh[1][1]+sh[1][2]+sh[1][3];
        float c=sh[2][0]+sh[2][1]+sh[2][2]+sh[2][3];
        g_cn2[j]=a;
        g_gp[j]=1.f/(1.f+expf(-(b+gb[0])));
        g_go[j]=1.f/(1.f+expf(-(c+gb[1])));
    }
}

// ---------- tf32 projection GEMM (fused embed gather, ldmatrix A) ----------
__global__ __launch_bounds__(256) void proj_kernel(
        const int* __restrict__ tokens, const float* __restrict__ embed,
        const float* __restrict__ qw, const float* __restrict__ qb,
        const float* __restrict__ kw, const float* __restrict__ kb,
        const float* __restrict__ vw, const float* __restrict__ vb) {
    __shared__ unsigned As[128][36];
    __shared__ unsigned Bs[32][132];
    const int z = blockIdx.z, pair = z>>1, im = z&1;
    const float* W; const float* bias; float* C;
    if (pair==0){W=qw;bias=qb;C=im?g_qi:g_qr;}
    else if (pair==1){W=kw;bias=kb;C=im?g_ki:g_kr;}
    else {W=vw;bias=vb;C=im?g_vi:g_vr;}
    W += (size_t)im*Dsz*Dsz;
    const float sgn = im?1.f:-1.f;
    const int m0=blockIdx.y*128, n0=blockIdx.x*128;
    const int tid=threadIdx.x, warp=tid>>5, lane=tid&31;
    const int wm=warp>>2, wn=warp&3, grp=lane>>2, tg=lane&3;
    const int lrow=lane&15, lcol=(lane&16)?4:0;
    const int arow=tid>>3, ac4=(tid&7)*4;
    const int brow=tid>>5, bc4=(tid&31)*4;
    size_t aoff[4];
#pragma unroll
    for(int u=0;u<4;u++)
        aoff[u]=(size_t)tokens[m0+arow+u*32]*Dsz;
    float acc[4][4][4];
#pragma unroll
    for(int i=0;i<4;i++)
#pragma unroll
        for(int j=0;j<4;j++)
#pragma unroll
            for(int k=0;k<4;k++) acc[i][j][k]=0.f;
    float4 pa[4], pb[4];
#pragma unroll
    for(int u=0;u<4;u++){
        pa[u]=*(const float4*)(embed+aoff[u]+ac4);
        pb[u]=*(const float4*)(W+(size_t)(brow+u*8)*Dsz+n0+bc4);
    }
    for(int k0=0;k0<Dsz;k0+=32){
        __syncthreads();
#pragma unroll
        for(int u=0;u<4;u++){
            *(uint4*)&As[arow+u*32][ac4]=*reinterpret_cast<uint4*>(&pa[u]);
            *(uint4*)&Bs[brow+u*8][bc4]=*reinterpret_cast<uint4*>(&pb[u]);
        }
        __syncthreads();
        if(k0+32<Dsz){
#pragma unroll
            for(int u=0;u<4;u++){
                pa[u]=*(const float4*)(embed+aoff[u]+k0+32+ac4);
                pb[u]=*(const float4*)(W+(size_t)(k0+32+brow+u*8)*Dsz+n0+bc4);
            }
        }
#pragma unroll
        for(int k8=0;k8<4;k8++){
            const int kb8=k8*8;
            unsigned af[4][4], bf[4][2];
#pragma unroll
            for(int mt=0;mt<4;mt++){
                LDSM4(af[mt], su32(&As[wm*64+mt*16+lrow][kb8+lcol]));
            }
#pragma unroll
            for(int nt=0;nt<4;nt++){
                int cix=wn*32+nt*8+grp;
                bf[nt][0]=Bs[kb8+tg][cix]; bf[nt][1]=Bs[kb8+tg+4][cix];
            }
#pragma unroll
            for(int mt=0;mt<4;mt++)
#pragma unroll
                for(int nt=0;nt<4;nt++) mma_tf32(acc[mt][nt],af[mt],bf[nt]);
        }
    }
#pragma unroll
    for(int mt=0;mt<4;mt++){
#pragma unroll
        for(int nt=0;nt<4;nt++){
            int r=m0+wm*64+mt*16+grp;
            int cix=n0+wn*32+nt*8+2*tg;
            float b0=bias[cix]+sgn*bias[Dsz+cix];
            float b1=bias[cix+1]+sgn*bias[Dsz+cix+1];
            *(float2*)(C+(size_t)r*Dsz+cix)    =make_float2(acc[mt][nt][0]+b0,acc[mt][nt][1]+b1);
            *(float2*)(C+(size_t)(r+8)*Dsz+cix)=make_float2(acc[mt][nt][2]+b0,acc[mt][nt][3]+b1);
        }
    }
}

// ---------- tf32 fused complex O-projection (ldmatrix A) ----------
__global__ __launch_bounds__(256) void oproj_kernel(const float* __restrict__ ow,
                                                    const float* __restrict__ ob) {
    __shared__ unsigned As[128][36];
    __shared__ unsigned Bs[32][132];
    const float* w0=ow; const float* w1=ow+(size_t)Dsz*Dsz;
    const int m0=blockIdx.y*128, n0=blockIdx.x*128;
    const bool isI = (n0>=Dsz);
    const int nloc = isI ? n0-Dsz : n0;
    const int tid=threadIdx.x, warp=tid>>5, lane=tid&31;
    const int wm=warp>>2, wn=warp&3, grp=lane>>2, tg=lane&3;
    const int lrow=lane&15, lcol=(lane&16)?4:0;
    const int arow=tid>>3, ac4=(tid&7)*4;
    const int brow=tid>>5, bc4=(tid&31)*4;
    float acc[4][4][4];
#pragma unroll
    for(int i=0;i<4;i++)
#pragma unroll
        for(int j=0;j<4;j++)
#pragma unroll
            for(int k=0;k<4;k++) acc[i][j][k]=0.f;
    float4 pa[4], pb[4];
#pragma unroll
    for(int u=0;u<4;u++){
        pa[u]=*(const float4*)(g_ar+(size_t)(m0+arow+u*32)*Dsz+ac4);
        const float* wsrc = isI ? w1 : w0;
        pb[u]=*(const float4*)(wsrc+(size_t)(brow+u*8)*Dsz+nloc+bc4);
    }
    for(int k0=0;k0<2*Dsz;k0+=32){
        __syncthreads();
        const bool khi_cur = (k0>=Dsz);
        const unsigned smask = (!isI && khi_cur) ? 0x80000000u : 0u;
#pragma unroll
        for(int u=0;u<4;u++){
            *(uint4*)&As[arow+u*32][ac4]=*reinterpret_cast<uint4*>(&pa[u]);
            uint4 ub=*reinterpret_cast<uint4*>(&pb[u]);
            ub.x^=smask; ub.y^=smask; ub.z^=smask; ub.w^=smask;
            *(uint4*)&Bs[brow+u*8][bc4]=ub;
        }
        __syncthreads();
        if(k0+32<2*Dsz){
            const int kn=k0+32;
            const bool khi = (kn>=Dsz);
            const float* asrc = khi ? g_ai : g_ar;
            const int akk = khi ? kn-Dsz : kn;
            const float* wsrc = isI ? (khi ? w0 : w1) : (khi ? w1 : w0);
            const int bkk = khi ? kn-Dsz : kn;
#pragma unroll
            for(int u=0;u<4;u++){
                pa[u]=*(const float4*)(asrc+(size_t)(m0+arow+u*32)*Dsz+akk+ac4);
                pb[u]=*(const float4*)(wsrc+(size_t)(bkk+brow+u*8)*Dsz+nloc+bc4);
            }
        }
#pragma unroll
        for(int k8=0;k8<4;k8++){
            const int kb8=k8*8;
            unsigned af[4][4], bf[4][2];
#pragma unroll
            for(int mt=0;mt<4;mt++){
                LDSM4(af[mt], su32(&As[wm*64+mt*16+lrow][kb8+lcol]));
            }
#pragma unroll
            for(int nt=0;nt<4;nt++){
                int cix=wn*32+nt*8+grp;
                bf[nt][0]=Bs[kb8+tg][cix]; bf[nt][1]=Bs[kb8+tg+4][cix];
            }
#pragma unroll
            for(int mt=0;mt<4;mt++)
#pragma unroll
                for(int nt=0;nt<4;nt++) mma_tf32(acc[mt][nt],af[mt],bf[nt]);
        }
    }
    float* Cdst = isI ? g_pi : g_pr;
    const float s2 = isI ? 1.f : -1.f;
#pragma unroll
    for(int mt=0;mt<4;mt++){
#pragma unroll
        for(int nt=0;nt<4;nt++){
            int r=m0+wm*64+mt*16+grp;
            int cl=wn*32+nt*8+2*tg;
            int cg=nloc+cl;
            float b0=ob[cg]+s2*ob[Dsz+cg];
            float b1=ob[cg+1]+s2*ob[Dsz+cg+1];
            *(float2*)(Cdst+(size_t)r*Dsz+cg)    =make_float2(acc[mt][nt][0]+b0,acc[mt][nt][1]+b1);
            *(float2*)(Cdst+(size_t)(r+8)*Dsz+cg)=make_float2(acc[mt][nt][2]+b0,acc[mt][nt][3]+b1);
        }
    }
}

// ---------- tf32 flash attention v4: 64-row Q tile, 4 warps, 2 CTAs/SM ----------
#define WAP 68
#define ATTN_SMEM (6*64*WAP*4)
__global__ __launch_bounds__(128) void attn_kernel() {
    extern __shared__ float smf[];
    float* sQr=smf;             float* sQi=sQr+64*WAP;
    float* sKr=sQi+64*WAP;      float* sKi=sKr+64*WAP;
    float* sVr=sKi+64*WAP;      float* sVi=sVr+64*WAP;
    const int bh=blockIdx.y, b=bh>>3, h=bh&7;
    const int bx=blockIdx.x, i0=bx*64;
    const int tid=threadIdx.x, warp=tid>>5, lane=tid&31;
    const int grp=lane>>2, tg=lane&3;
    const int lrow=lane&15, lcol=(lane&16)?4:0;
    const int krow=((lane>>4)<<3)|(lane&7), kcol=((lane>>3)&1)*4;
    const int wrow=warp*16;
    const size_t base=(size_t)b*Lsz*Dsz + h*HDsz;
    // Q load (64 rows)
#pragma unroll
    for(int u=0;u<8;u++){
        int li=tid+u*128, r=li>>4, c4=(li&15)*4;
        size_t g=base+(size_t)(i0+r)*Dsz+c4;
        CPA16(&sQr[r*WAP+c4], g_qr+g);
        CPA16(&sQi[r*WAP+c4], g_qi+g);
    }
    CPA_COMMIT();
    const int ntile=bx+1;
    // KV tile 0
#pragma unroll
    for(int u=0;u<8;u++){
        int li=tid+u*128, r=li>>4, c4=(li&15)*4;
        size_t g=base+(size_t)r*Dsz+c4;
        CPA16(&sKr[r*WAP+c4], g_kr+g); CPA16(&sKi[r*WAP+c4], g_ki+g);
        CPA16(&sVr[r*WAP+c4], g_vr+g); CPA16(&sVi[r*WAP+c4], g_vi+g);
    }
    CPA_COMMIT();
    float m_run[2]={NEG_INF,NEG_INF}, l_run[2]={0.f,0.f};
    float accR[8][4], accI[8][4];
#pragma unroll
    for(int nt=0;nt<8;nt++)
#pragma unroll
        for(int k=0;k<4;k++){accR[nt][k]=0.f;accI[nt][k]=0.f;}
    const int srcA=(lane&~3)|(tg>>1), srcB=srcA|2;
    const bool odd=tg&1;
    for(int jt=0;jt<ntile;jt++){
        CPA_WAIT0();
        __syncthreads();
        const int s0=jt*64;
        float s_[8][4];
#pragma unroll
        for(int nt=0;nt<8;nt++)
#pragma unroll
            for(int k=0;k<4;k++) s_[nt][k]=0.f;
#pragma unroll
        for(int kc=0;kc<8;kc++){
            const int kb=kc*8;
            unsigned aR[4],aI[4];
            LDSM4(aR, su32(&sQr[(wrow+lrow)*WAP+kb+lcol]));
            LDSM4(aI, su32(&sQi[(wrow+lrow)*WAP+kb+lcol]));
#pragma unroll
            for(int ntp=0;ntp<4;ntp++){
                unsigned kR[4],kI[4];
                LDSM4(kR, su32(&sKr[(16*ntp+krow)*WAP+kb+kcol]));
                LDSM4(kI, su32(&sKi[(16*ntp+krow)*WAP+kb+kcol]));
                mma_tf32(s_[2*ntp],  aR,&kR[0]); mma_tf32(s_[2*ntp],  aI,&kI[0]);
                mma_tf32(s_[2*ntp+1],aR,&kR[2]); mma_tf32(s_[2*ntp+1],aI,&kI[2]);
            }
        }
        const bool diag=(jt==bx);
        const int r0=i0+wrow+grp, r1=r0+8;
#pragma unroll
        for(int nt=0;nt<8;nt++){
            const int c0=s0+nt*8+2*tg, c1=c0+1;
            s_[nt][0]*=0.125f; s_[nt][1]*=0.125f; s_[nt][2]*=0.125f; s_[nt][3]*=0.125f;
            if(diag){
                if(c0>r0)s_[nt][0]=NEG_INF; if(c1>r0)s_[nt][1]=NEG_INF;
                if(c0>r1)s_[nt][2]=NEG_INF; if(c1>r1)s_[nt][3]=NEG_INF;
            }
        }
        float mx0=NEG_INF, mx1=NEG_INF;
#pragma unroll
        for(int nt=0;nt<8;nt++){
            mx0=fmaxf(mx0,fmaxf(s_[nt][0],s_[nt][1]));
            mx1=fmaxf(mx1,fmaxf(s_[nt][2],s_[nt][3]));
        }
        mx0=fmaxf(mx0,__shfl_xor_sync(0xffffffffu,mx0,1));
        mx0=fmaxf(mx0,__shfl_xor_sync(0xffffffffu,mx0,2));
        mx1=fmaxf(mx1,__shfl_xor_sync(0xffffffffu,mx1,1));
        mx1=fmaxf(mx1,__shfl_xor_sync(0xffffffffu,mx1,2));
        const float mn0=fmaxf(m_run[0],mx0), mn1=fmaxf(m_run[1],mx1);
        const float al0=__expf(m_run[0]-mn0), al1=__expf(m_run[1]-mn1);
        m_run[0]=mn0; m_run[1]=mn1;
        float rs0=0.f, rs1=0.f;
#pragma unroll
        for(int nt=0;nt<8;nt++){
            s_[nt][0]=__expf(s_[nt][0]-mn0); s_[nt][1]=__expf(s_[nt][1]-mn0);
            s_[nt][2]=__expf(s_[nt][2]-mn1); s_[nt][3]=__expf(s_[nt][3]-mn1);
            rs0+=s_[nt][0]+s_[nt][1]; rs1+=s_[nt][2]+s_[nt][3];
        }
        rs0+=__shfl_xor_sync(0xffffffffu,rs0,1); rs0+=__shfl_xor_sync(0xffffffffu,rs0,2);
        rs1+=__shfl_xor_sync(0xffffffffu,rs1,1); rs1+=__shfl_xor_sync(0xffffffffu,rs1,2);
        l_run[0]=l_run[0]*al0+rs0; l_run[1]=l_run[1]*al1+rs1;
#pragma unroll
        for(int nt=0;nt<8;nt++){
            accR[nt][0]*=al0; accR[nt][1]*=al0; accR[nt][2]*=al1; accR[nt][3]*=al1;
            accI[nt][0]*=al0; accI[nt][1]*=al0; accI[nt][2]*=al1; accI[nt][3]*=al1;
        }
#pragma unroll
        for(int kc=0;kc<8;kc++){
            float x0=__shfl_sync(0xffffffffu,s_[kc][0],srcA);
            float x1=__shfl_sync(0xffffffffu,s_[kc][1],srcA);
            float z0=__shfl_sync(0xffffffffu,s_[kc][2],srcA);
            float z1=__shfl_sync(0xffffffffu,s_[kc][3],srcA);
            float y0=__shfl_sync(0xffffffffu,s_[kc][0],srcB);
            float y1=__shfl_sync(0xffffffffu,s_[kc][1],srcB);
            float w0=__shfl_sync(0xffffffffu,s_[kc][2],srcB);
            float w1=__shfl_sync(0xffffffffu,s_[kc][3],srcB);
            unsigned aP[4];
            aP[0]=__float_as_uint(odd?x1:x0);
            aP[1]=__float_as_uint(odd?z1:z0);
            aP[2]=__float_as_uint(odd?y1:y0);
            aP[3]=__float_as_uint(odd?w1:w0);
#pragma unroll
            for(int nt=0;nt<8;nt++){
                unsigned bR[2],bI[2];
                bR[0]=__float_as_uint(sVr[(8*kc+tg  )*WAP+8*nt+grp]);
                bR[1]=__float_as_uint(sVr[(8*kc+tg+4)*WAP+8*nt+grp]);
                bI[0]=__float_as_uint(sVi[(8*kc+tg  )*WAP+8*nt+grp]);
                bI[1]=__float_as_uint(sVi[(8*kc+tg+4)*WAP+8*nt+grp]);
                mma_tf32(accR[nt],aP,bR);
                mma_tf32(accI[nt],aP,bI);
            }
        }
        __syncthreads();
        if(jt+1<ntile){
            const int s0n=(jt+1)*64;
#pragma unroll
            for(int u=0;u<8;u++){
                int li=tid+u*128, r=li>>4, c4=(li&15)*4;
                size_t g=base+(size_t)(s0n+r)*Dsz+c4;
                CPA16(&sKr[r*WAP+c4], g_kr+g); CPA16(&sKi[r*WAP+c4], g_ki+g);
                CPA16(&sVr[r*WAP+c4], g_vr+g); CPA16(&sVi[r*WAP+c4], g_vi+g);
            }
            CPA_COMMIT();
        }
    }
    const float inv0=1.f/l_run[0], inv1=1.f/l_run[1];
#pragma unroll
    for(int nt=0;nt<8;nt++){
        const int d=nt*8+2*tg;
        size_t g0=base+(size_t)(i0+wrow+grp  )*Dsz+d;
        size_t g1=base+(size_t)(i0+wrow+grp+8)*Dsz+d;
        *(float2*)(g_ar+g0)=make_float2(accR[nt][0]*inv0,accR[nt][1]*inv0);
        *(float2*)(g_ar+g1)=make_float2(accR[nt][2]*inv1,accR[nt][3]*inv1);
        *(float2*)(g_ai+g0)=make_float2(accI[nt][0]*inv0,accI[nt][1]*inv0);
        *(float2*)(g_ai+g1)=make_float2(accI[nt][2]*inv1,accI[nt][3]*inv1);
    }
}

// ---------- VQ distance: 32-row tiles, 256 blocks ----------
__global__ __launch_bounds__(256) void dist_kernel(const float* __restrict__ cb) {
    __shared__ float As[16][36];
    __shared__ float Bs[16][132];
    __shared__ float2 sRed[32][32];
    const int m0=blockIdx.x*32;
    const int tid=threadIdx.x, ty=tid>>5, tx=tid&31;
    const int arow=tid>>2, ak=(tid&3)*4;
    float acc[4][4];
#pragma unroll
    for(int i=0;i<4;i++)
#pragma unroll
        for(int j=0;j<4;j++) acc[i][j]=0.f;
    float4 pa=make_float4(0,0,0,0), pb0, pb1;
    if(tid<128) pa=*(const float4*)(g_pr+(size_t)(m0+arow)*Dsz+ak);
    pb0=*(const float4*)(cb+(size_t)(tid>>2)*Dsz+ak);
    pb1=*(const float4*)(cb+(size_t)(64+(tid>>2))*Dsz+ak);
    for(int k0=0;k0<Dsz;k0+=16){
        __syncthreads();
        if(tid<128){
            As[ak+0][arow]=pa.x;As[ak+1][arow]=pa.y;As[ak+2][arow]=pa.z;As[ak+3][arow]=pa.w;
        }
        {
            int c=tid>>2;
            Bs[ak+0][c]=pb0.x;Bs[ak+1][c]=pb0.y;Bs[ak+2][c]=pb0.z;Bs[ak+3][c]=pb0.w;
            Bs[ak+0][64+c]=pb1.x;Bs[ak+1][64+c]=pb1.y;Bs[ak+2][64+c]=pb1.z;Bs[ak+3][64+c]=pb1.w;
        }
        __syncthreads();
        if(k0+16<Dsz){
            if(tid<128) pa=*(const float4*)(g_pr+(size_t)(m0+arow)*Dsz+k0+16+ak);
            pb0=*(const float4*)(cb+(size_t)(tid>>2)*Dsz+k0+16+ak);
            pb1=*(const float4*)(cb+(size_t)(64+(tid>>2))*Dsz+k0+16+ak);
        }
#pragma unroll
        for(int kk=0;kk<16;kk++){
            float4 a4=*(float4*)&As[kk][ty*4];
            float4 b4=*(float4*)&Bs[kk][tx*4];
            float a[4]={a4.x,a4.y,a4.z,a4.w};
            float b[4]={b4.x,b4.y,b4.z,b4.w};
#pragma unroll
            for(int i=0;i<4;i++)
#pragma unroll
                for(int j=0;j<4;j++) acc[i][j]+=a[i]*b[j];
        }
    }
#pragma unroll
    for(int i=0;i<4;i++){
        float bd=1e30f; int bi=0;
#pragma unroll
        for(int j=0;j<4;j++){
            int n=tx*4+j;
            float d=g_cn2[n]-2.f*acc[i][j];
            if(d<bd){bd=d;bi=n;}
        }
        sRed[ty*4+i][tx]=make_float2(bd,__int_as_float(bi));
    }
    __syncthreads();
    if(tid<32){
        float bd=1e30f; int bi=0;
#pragma unroll
        for(int t=0;t<32;t++){
            float2 e=sRed[tid][t];
            if(e.x<bd){bd=e.x;bi=__float_as_int(e.y);}
        }
        g_idx[m0+tid]=bi;
    }
}

// ---------- gated stack scan ----------
__global__ __launch_bounds__(256) void scan_kernel(const float* __restrict__ cb) {
    __shared__ int sIdx[256]; __shared__ float sP[256],sO[256];
    const int b=blockIdx.x>>6, dg=blockIdx.x&63;
    const int warp=threadIdx.x>>5, lane=threadIdx.x&31;
    const int d=dg*8+warp;
    float st=0.f;
    for(int t0=0;t0<Lsz;t0+=256){
        __syncthreads();
        int ix=g_idx[b*Lsz+t0+threadIdx.x];
        sIdx[threadIdx.x]=ix; sP[threadIdx.x]=g_gp[ix]; sO[threadIdx.x]=g_go[ix];
        __syncthreads();
        for(int tt=0;tt<256;tt++){
            float val=cb[(size_t)sIdx[tt]*Dsz+d];
            float p=sP[tt],o=sO[tt];
            float sh=__shfl_down_sync(0xffffffffu,st,1);
            if(lane==31) sh=val;
            st=((1.f-p)*st+p*sh)*(1.f-o);
            if(lane==31) g_stk[((size_t)b*Lsz+t0+tt)*Dsz+d]=st;
        }
    }
}

// ---------- final (with fused loss partial) ----------
__device__ __forceinline__ float blkRed(float v, float* s) {
#pragma unroll
    for(int o=16;o;o>>=1) v+=__shfl_xor_sync(0xffffffffu,v,o);
    if((threadIdx.x&31)==0) s[threadIdx.x>>5]=v;
    __syncthreads();
    v=s[0]+s[1]+s[2]+s[3];
    __syncthreads();
    return v;
}

__global__ void final_kernel(const float* __restrict__ cb,
                             const float* __restrict__ lng,
                             const float* __restrict__ lnb,
                             const float* __restrict__ mb,
                             float* __restrict__ out) {
    __shared__ float sw[4];
    const int m=blockIdx.x, tid=threadIdx.x;
    const float* pr=g_pr+(size_t)m*Dsz;
    const float4 c4=((const float4*)(cb+(size_t)g_idx[m]*Dsz))[tid];
    const float4 f4=((const float4*)pr)[tid];
    const float4 s4=((const float4*)(g_stk+(size_t)m*Dsz))[tid];
    const float4 i4=((const float4*)(g_pi+(size_t)m*Dsz))[tid];
    {
        float dx=c4.x-f4.x,dy=c4.y-f4.y,dz=c4.z-f4.z,dw=c4.w-f4.w;
        float lv=dx*dx+dy*dy+dz*dz+dw*dw;
        float lt=blkRed(lv,sw);
        if(tid==0) atomicAdd(&g_loss,(double)lt);
    }
    float cr[4],ci[4];
    cr[0]=(f4.x+(c4.x-f4.x))+s4.x; cr[1]=(f4.y+(c4.y-f4.y))+s4.y;
    cr[2]=(f4.z+(c4.z-f4.z))+s4.z; cr[3]=(f4.w+(c4.w-f4.w))+s4.w;
    ci[0]=i4.x;ci[1]=i4.y;ci[2]=i4.z;ci[3]=i4.w;
    float sr=cr[0]+cr[1]+cr[2]+cr[3], si=ci[0]+ci[1]+ci[2]+ci[3];
    float mur=blkRed(sr,sw)*(1.f/Dsz);
    float mui=blkRed(si,sw)*(1.f/Dsz);
    float vr=0.f,vi=0.f;
#pragma unroll
    for(int k=0;k<4;k++){float a=cr[k]-mur,b=ci[k]-mui;vr+=a*a;vi+=b*b;}
    float varr=blkRed(vr,sw)*(1.f/Dsz);
    float vari=blkRed(vi,sw)*(1.f/Dsz);
    float rr=rsqrtf(varr+1e-5f), ri=rsqrtf(vari+1e-5f);
#pragma unroll
    for(int k=0;k<4;k++){
        int d=tid*4+k;
        float nr=(cr[k]-mur)*rr*lng[d]+lnb[d];
        float ni=(ci[k]-mui)*ri*lng[Dsz+d]+lnb[Dsz+d];
        float mag=sqrtf(nr*nr+ni*ni);
        float sc=fmaxf(mag+mb[d],0.f)/(mag+1e-6f);
        out[(size_t)m*Dsz+d]=nr*sc;
        out[OUTHALF+(size_t)m*Dsz+d]=ni*sc;
    }
}

__global__ void loss_write(float* __restrict__ out, long out_size){
    out[out_size-1]=(float)(1.25*g_loss/(double)((size_t)Msz*Dsz));
}

extern "C" void kernel_launch(void* const* d_in, const int* in_sizes, int n_in,
                              void* d_out, int out_size) {
    const int*   tokens=(const int*)  d_in[0];
    const float* embed =(const float*)d_in[2];
    const float* q_w=(const float*)d_in[3],  *q_b=(const float*)d_in[4];
    const float* k_w=(const float*)d_in[5],  *k_b=(const float*)d_in[6];
    const float* v_w=(const float*)d_in[7],  *v_b=(const float*)d_in[8];
    const float* o_w=(const float*)d_in[9],  *o_b=(const float*)d_in[10];
    const float* cb =(const float*)d_in[11];
    const float* gw =(const float*)d_in[12], *gb=(const float*)d_in[13];
    const float* lng=(const float*)d_in[14], *lnb=(const float*)d_in[15];
    const float* mb =(const float*)d_in[16];
    float* out=(float*)d_out;

    static bool attr_set=false;
    if(!attr_set){
        cudaFuncSetAttribute(attn_kernel,cudaFuncAttributeMaxDynamicSharedMemorySize,ATTN_SMEM);
        attr_set=true;
    }
    prep_kernel<<<NCsz,128>>>(cb,gw,gb);
    proj_kernel<<<dim3(4,64,6),256>>>(tokens,embed,q_w,q_b,k_w,k_b,v_w,v_b);
    attn_kernel<<<dim3(16,64),128,ATTN_SMEM>>>();
    oproj_kernel<<<dim3(8,64),256>>>(o_w,o_b);
    dist_kernel<<<256,256>>>(cb);
    scan_kernel<<<512,256>>>(cb);
    final_kernel<<<Msz,128>>>(cb,lng,lnb,mb,out);
    loss_write<<<1,1>>>(out,(long)out_size);
}